// round 13
// baseline (speedup 1.0000x reference)
#include <cuda_runtime.h>
#include <math.h>
#include <stdint.h>

#define NV 4096
#define NG 2048
#define KK 128
#define NBLK 4
#define EE 32768

// ---------------- scratch ----------------
__device__ float g_rbf [NV * NG];
__device__ float g_rbfT[NG * NV];
__device__ float g_xd  [NV * 64];        // x_diff
__device__ float g_xout[NV * 64];        // x' (MLP output)
__device__ float g_y   [2 * NV * 64];    // double-buffered diff_x
__device__ float g_cat [NV * 128];       // [gX | gY]
__device__ float g_b2  [2 * NV * 64];    // [b_re ; b_im]
__device__ float g_sg  [KK * 64 + NG * 64];  // [xs | gx] split-K targets (one memset)
__device__ float g_W   [NBLK * 2 * KK * 64]; // per-block [Wre ; Wim]
__device__ float g_GE  [2 * NV * 128];   // [gradX@evecs ; gradY@evecs]
__device__ float g_eT  [KK * NV];        // evecs^T
__device__ float g_hw  [NG * 64];
__device__ float g_agg2[NG * 64];
__device__ float g_deg [NG];
__device__ float g_dinv[NG];
__device__ int   g_rowptr[NG + 1];
__device__ int   g_cursor[NG];
__device__ int   g_srcs[EE];

// ---------------- tf32 helpers ----------------
__device__ __forceinline__ float tf32r(float x) {
    uint32_t r;
    asm("cvt.rna.tf32.f32 %0, %1;" : "=r"(r) : "f"(x));
    return __uint_as_float(r);
}
__device__ __forceinline__ void mma_tf32(float* c, const uint32_t* a, const uint32_t* b) {
    asm volatile(
        "mma.sync.aligned.m16n8k8.row.col.f32.tf32.tf32.f32 "
        "{%0,%1,%2,%3}, {%4,%5,%6,%7}, {%8,%9}, {%0,%1,%2,%3};"
        : "+f"(c[0]), "+f"(c[1]), "+f"(c[2]), "+f"(c[3])
        : "r"(a[0]), "r"(a[1]), "r"(a[2]), "r"(a[3]), "r"(b[0]), "r"(b[1]));
}

// per-z slice descriptors
struct Sl {
    const float* A[4];
    float*       C[4];
    int          ldc[4];
};

// ---------------- generic N=64 GEMM (tf32 MMA), BM=128, 128 threads -----------
// abias:  A-load  a = relu(a + abias[k])
// bbias:  B-load  b = b + bbias[n]
// bscale: B-load  b = b * bscale[k]            (mass fusion for xs GEMM)
// bexp_*: B-load  b = b * exp(-ev[k] * max(t[n],eps))
// gridDim.y > 1 => split-K atomicAdd (caller zero-inits C).
__global__ __launch_bounds__(128) void gemm64(
    Sl sl, int lda,
    const float* __restrict__ B0, const float* __restrict__ B1, int ldb,
    int KB, int kchunk,
    const float* __restrict__ bias,
    const float* __restrict__ resid, int ldr, int act,
    const float* __restrict__ abias, const float* __restrict__ bbias,
    const float* __restrict__ bscale,
    const float* __restrict__ bexp_ev, const float* __restrict__ bexp_t)
{
    __shared__ float As[2][128][36];
    __shared__ float Bs[2][32][72];

    const int z = blockIdx.z;
    const float* A = sl.A[z];
    const float* B = (z & 1) ? B1 : B0;
    float* C = sl.C[z];
    const int ldc = sl.ldc[z];

    const int tid    = threadIdx.x;
    const int warp   = tid >> 5;
    const int lane   = tid & 31;
    const int g      = lane >> 2;
    const int tg     = lane & 3;
    const int m0     = blockIdx.x * 128;
    const int warp_m = warp * 32;
    const int kbeg   = blockIdx.y * kchunk;
    const int ntile  = kchunk >> 5;

    const int am = tid >> 3;
    const int ak = (tid & 7) * 4;
    const int bk = tid >> 4;
    const int bn = (tid & 15) * 4;

    float4 bb = make_float4(0.f, 0.f, 0.f, 0.f);
    if (bbias) bb = *(const float4*)(bbias + bn);
    float4 tc = make_float4(0.f, 0.f, 0.f, 0.f);
    if (bexp_t) {
        tc = *(const float4*)(bexp_t + bn);
        tc.x = fmaxf(tc.x, 1e-8f); tc.y = fmaxf(tc.y, 1e-8f);
        tc.z = fmaxf(tc.z, 1e-8f); tc.w = fmaxf(tc.w, 1e-8f);
    }

    float4 rA[8], rB[4];
    float c[2][8][4];
#pragma unroll
    for (int mi = 0; mi < 2; mi++)
#pragma unroll
        for (int ni = 0; ni < 8; ni++)
#pragma unroll
            for (int r = 0; r < 4; r++) c[mi][ni][r] = 0.0f;

    {   // prologue tile 0
        const float* ap = A + (size_t)(m0 + am) * lda + kbeg + ak;
        const float* bp = B + (size_t)(kbeg + bk) * ldb + bn;
#pragma unroll
        for (int i = 0; i < 8; i++) rA[i] = *(const float4*)(ap + (size_t)(i * 16) * lda);
#pragma unroll
        for (int i = 0; i < 4; i++) rB[i] = *(const float4*)(bp + (size_t)(i * 8) * ldb);
    }

    int buf = 0;
    for (int it = 0; it < ntile; it++) {
        const int kst = kbeg + it * 32;
#pragma unroll
        for (int i = 0; i < 8; i++) {
            float4 v = rA[i];
            if (abias) {
                float4 ab = *(const float4*)(abias + kst + ak);
                v.x = fmaxf(v.x + ab.x, 0.f); v.y = fmaxf(v.y + ab.y, 0.f);
                v.z = fmaxf(v.z + ab.z, 0.f); v.w = fmaxf(v.w + ab.w, 0.f);
            }
            v.x = tf32r(v.x); v.y = tf32r(v.y); v.z = tf32r(v.z); v.w = tf32r(v.w);
            *(float4*)&As[buf][am + i * 16][ak] = v;
        }
#pragma unroll
        for (int i = 0; i < 4; i++) {
            float4 v = rB[i];
            if (bscale) {
                float s = bscale[kst + bk + i * 8];
                v.x *= s; v.y *= s; v.z *= s; v.w *= s;
            }
            if (bexp_ev) {
                float ev = bexp_ev[kst + bk + i * 8];
                v.x *= __expf(-ev * tc.x); v.y *= __expf(-ev * tc.y);
                v.z *= __expf(-ev * tc.z); v.w *= __expf(-ev * tc.w);
            }
            v.x += bb.x; v.y += bb.y; v.z += bb.z; v.w += bb.w;
            v.x = tf32r(v.x); v.y = tf32r(v.y); v.z = tf32r(v.z); v.w = tf32r(v.w);
            *(float4*)&Bs[buf][bk + i * 8][bn] = v;
        }
        __syncthreads();

        if (it + 1 < ntile) {
            int kb = kbeg + (it + 1) * 32;
            const float* ap = A + (size_t)(m0 + am) * lda + kb + ak;
            const float* bp = B + (size_t)(kb + bk) * ldb + bn;
#pragma unroll
            for (int i = 0; i < 8; i++) rA[i] = *(const float4*)(ap + (size_t)(i * 16) * lda);
#pragma unroll
            for (int i = 0; i < 4; i++) rB[i] = *(const float4*)(bp + (size_t)(i * 8) * ldb);
        }

#pragma unroll
        for (int k8 = 0; k8 < 32; k8 += 8) {
            uint32_t a[2][4];
#pragma unroll
            for (int mi = 0; mi < 2; mi++) {
                int r0 = warp_m + mi * 16 + g;
                a[mi][0] = __float_as_uint(As[buf][r0][k8 + tg]);
                a[mi][1] = __float_as_uint(As[buf][r0 + 8][k8 + tg]);
                a[mi][2] = __float_as_uint(As[buf][r0][k8 + tg + 4]);
                a[mi][3] = __float_as_uint(As[buf][r0 + 8][k8 + tg + 4]);
            }
            uint32_t b[8][2];
#pragma unroll
            for (int ni = 0; ni < 8; ni++) {
                b[ni][0] = __float_as_uint(Bs[buf][k8 + tg][ni * 8 + g]);
                b[ni][1] = __float_as_uint(Bs[buf][k8 + tg + 4][ni * 8 + g]);
            }
#pragma unroll
            for (int mi = 0; mi < 2; mi++)
#pragma unroll
                for (int ni = 0; ni < 8; ni++)
                    mma_tf32(c[mi][ni], a[mi], b[ni]);
        }
        buf ^= 1;
    }

    const bool split = (gridDim.y > 1);
#pragma unroll
    for (int mi = 0; mi < 2; mi++) {
#pragma unroll
        for (int rr = 0; rr < 2; rr++) {
            int m = m0 + warp_m + mi * 16 + g + rr * 8;
#pragma unroll
            for (int ni = 0; ni < 8; ni++) {
                int n = ni * 8 + tg * 2;
                float v0 = c[mi][ni][rr * 2 + 0];
                float v1 = c[mi][ni][rr * 2 + 1];
                if (split) {
                    atomicAdd(&C[(size_t)m * ldc + n],     v0);
                    atomicAdd(&C[(size_t)m * ldc + n + 1], v1);
                } else {
                    if (bias)  { v0 += bias[n]; v1 += bias[n + 1]; }
                    if (resid) { v0 += resid[(size_t)m * ldr + n];
                                 v1 += resid[(size_t)m * ldr + n + 1]; }
                    if (act)   { v0 = fmaxf(v0, 0.0f); v1 = fmaxf(v1, 0.0f); }
                    *(float2*)&C[(size_t)m * ldc + n] = make_float2(v0, v1);
                }
            }
        }
    }
}

// ---------------- fused 3-layer MLP (one launch) -------------------------------
// A-loader: k<64 -> x (yA), k<128 -> x_diff, k>=128 -> gfeat from cat/b2.
__device__ __forceinline__ float4 load_f_ext(
    const float* __restrict__ x, const float* __restrict__ xd,
    const float* __restrict__ cat, const float* __restrict__ b2, int m, int k)
{
    if (k < 64)  return *(const float4*)(x  + (size_t)m * 64 + k);
    if (k < 128) return *(const float4*)(xd + (size_t)m * 64 + k - 64);
    int kk = k - 128;
    float4 gx = *(const float4*)(cat + (size_t)m * 128 + kk);
    float4 gy = *(const float4*)(cat + (size_t)m * 128 + 64 + kk);
    float4 br = *(const float4*)(b2 + (size_t)m * 64 + kk);
    float4 bi = *(const float4*)(b2 + (size_t)(NV * 64) + (size_t)m * 64 + kk);
    float4 r;
    r.x = tanhf(gx.x * br.x + gy.x * bi.x);
    r.y = tanhf(gx.y * br.y + gy.y * bi.y);
    r.z = tanhf(gx.z * br.z + gy.z * bi.z);
    r.w = tanhf(gx.w * br.w + gy.w * bi.w);
    return r;
}

__global__ __launch_bounds__(128) void mlp_kernel(
    const float* __restrict__ x, const float* __restrict__ xd,
    float* __restrict__ xout,
    const float* __restrict__ cat, const float* __restrict__ b2v,
    const float* __restrict__ w0, const float* __restrict__ b0,
    const float* __restrict__ w1, const float* __restrict__ b1,
    const float* __restrict__ w2, const float* __restrict__ b2)
{
    __shared__ float As[2][128][36];
    __shared__ float Bs[2][32][72];

    const int tid = threadIdx.x, warp = tid >> 5, lane = tid & 31;
    const int g = lane >> 2, tg = lane & 3;
    const int m0 = blockIdx.x * 128, warp_m = warp * 32;
    const int am = tid >> 3, ak = (tid & 7) * 4;
    const int bk = tid >> 4, bn = (tid & 15) * 4;

    float c[2][8][4];
#pragma unroll
    for (int mi = 0; mi < 2; mi++)
#pragma unroll
        for (int ni = 0; ni < 8; ni++)
#pragma unroll
            for (int r = 0; r < 4; r++) c[mi][ni][r] = 0.0f;

    // ---- phase 1: h1 = relu(fext @ w0 + b0), K=192 streamed (6 tiles) ----
    float4 rA[8], rB[4];
    {
#pragma unroll
        for (int i = 0; i < 8; i++)
            rA[i] = load_f_ext(x, xd, cat, b2v, m0 + am + i * 16, ak);
        const float* bp = w0 + (size_t)bk * 64 + bn;
#pragma unroll
        for (int i = 0; i < 4; i++) rB[i] = *(const float4*)(bp + (size_t)(i * 8) * 64);
    }
    int buf = 0;
    for (int it = 0; it < 6; it++) {
#pragma unroll
        for (int i = 0; i < 8; i++) {
            float4 v = rA[i];
            v.x = tf32r(v.x); v.y = tf32r(v.y); v.z = tf32r(v.z); v.w = tf32r(v.w);
            *(float4*)&As[buf][am + i * 16][ak] = v;
        }
#pragma unroll
        for (int i = 0; i < 4; i++) {
            float4 v = rB[i];
            v.x = tf32r(v.x); v.y = tf32r(v.y); v.z = tf32r(v.z); v.w = tf32r(v.w);
            *(float4*)&Bs[buf][bk + i * 8][bn] = v;
        }
        __syncthreads();
        if (it + 1 < 6) {
            int kb = (it + 1) * 32;
#pragma unroll
            for (int i = 0; i < 8; i++)
                rA[i] = load_f_ext(x, xd, cat, b2v, m0 + am + i * 16, kb + ak);
            const float* bp = w0 + (size_t)(kb + bk) * 64 + bn;
#pragma unroll
            for (int i = 0; i < 4; i++) rB[i] = *(const float4*)(bp + (size_t)(i * 8) * 64);
        }
#pragma unroll
        for (int k8 = 0; k8 < 32; k8 += 8) {
            uint32_t a[2][4];
#pragma unroll
            for (int mi = 0; mi < 2; mi++) {
                int r0 = warp_m + mi * 16 + g;
                a[mi][0] = __float_as_uint(As[buf][r0][k8 + tg]);
                a[mi][1] = __float_as_uint(As[buf][r0 + 8][k8 + tg]);
                a[mi][2] = __float_as_uint(As[buf][r0][k8 + tg + 4]);
                a[mi][3] = __float_as_uint(As[buf][r0 + 8][k8 + tg + 4]);
            }
            uint32_t b[8][2];
#pragma unroll
            for (int ni = 0; ni < 8; ni++) {
                b[ni][0] = __float_as_uint(Bs[buf][k8 + tg][ni * 8 + g]);
                b[ni][1] = __float_as_uint(Bs[buf][k8 + tg + 4][ni * 8 + g]);
            }
#pragma unroll
            for (int mi = 0; mi < 2; mi++)
#pragma unroll
                for (int ni = 0; ni < 8; ni++)
                    mma_tf32(c[mi][ni], a[mi], b[ni]);
        }
        buf ^= 1;
    }
    // h1 -> As (own-warp rows)
#pragma unroll
    for (int mi = 0; mi < 2; mi++)
#pragma unroll
        for (int rr = 0; rr < 2; rr++) {
            int ml = warp_m + mi * 16 + g + rr * 8;
#pragma unroll
            for (int ni = 0; ni < 8; ni++) {
                int n = ni * 8 + tg * 2;
                float v0 = fmaxf(c[mi][ni][rr * 2 + 0] + b0[n], 0.f);
                float v1 = fmaxf(c[mi][ni][rr * 2 + 1] + b0[n + 1], 0.f);
                *(float2*)&As[n >> 5][ml][n & 31] = make_float2(tf32r(v0), tf32r(v1));
            }
        }
    __syncthreads();

    // ---- phase 2: h2 = relu(h1 @ w1 + b1) ----
#pragma unroll
    for (int t = 0; t < 2; t++)
#pragma unroll
        for (int i = 0; i < 4; i++) {
            float4 v = *(const float4*)(w1 + (size_t)(t * 32 + bk + i * 8) * 64 + bn);
            v.x = tf32r(v.x); v.y = tf32r(v.y); v.z = tf32r(v.z); v.w = tf32r(v.w);
            *(float4*)&Bs[t][bk + i * 8][bn] = v;
        }
    __syncthreads();
#pragma unroll
    for (int mi = 0; mi < 2; mi++)
#pragma unroll
        for (int ni = 0; ni < 8; ni++)
#pragma unroll
            for (int r = 0; r < 4; r++) c[mi][ni][r] = 0.0f;
#pragma unroll
    for (int kt = 0; kt < 2; kt++)
#pragma unroll
        for (int k8 = 0; k8 < 32; k8 += 8) {
            uint32_t a[2][4];
#pragma unroll
            for (int mi = 0; mi < 2; mi++) {
                int r0 = warp_m + mi * 16 + g;
                a[mi][0] = __float_as_uint(As[kt][r0][k8 + tg]);
                a[mi][1] = __float_as_uint(As[kt][r0 + 8][k8 + tg]);
                a[mi][2] = __float_as_uint(As[kt][r0][k8 + tg + 4]);
                a[mi][3] = __float_as_uint(As[kt][r0 + 8][k8 + tg + 4]);
            }
            uint32_t b[8][2];
#pragma unroll
            for (int ni = 0; ni < 8; ni++) {
                b[ni][0] = __float_as_uint(Bs[kt][k8 + tg][ni * 8 + g]);
                b[ni][1] = __float_as_uint(Bs[kt][k8 + tg + 4][ni * 8 + g]);
            }
#pragma unroll
            for (int mi = 0; mi < 2; mi++)
#pragma unroll
                for (int ni = 0; ni < 8; ni++)
                    mma_tf32(c[mi][ni], a[mi], b[ni]);
        }
#pragma unroll
    for (int mi = 0; mi < 2; mi++)
#pragma unroll
        for (int rr = 0; rr < 2; rr++) {
            int ml = warp_m + mi * 16 + g + rr * 8;
#pragma unroll
            for (int ni = 0; ni < 8; ni++) {
                int n = ni * 8 + tg * 2;
                float v0 = fmaxf(c[mi][ni][rr * 2 + 0] + b1[n], 0.f);
                float v1 = fmaxf(c[mi][ni][rr * 2 + 1] + b1[n + 1], 0.f);
                *(float2*)&As[n >> 5][ml][n & 31] = make_float2(tf32r(v0), tf32r(v1));
            }
        }
    __syncthreads();

    // ---- phase 3: x' = h2 @ w2 + b2 + x -> xout ----
#pragma unroll
    for (int t = 0; t < 2; t++)
#pragma unroll
        for (int i = 0; i < 4; i++) {
            float4 v = *(const float4*)(w2 + (size_t)(t * 32 + bk + i * 8) * 64 + bn);
            v.x = tf32r(v.x); v.y = tf32r(v.y); v.z = tf32r(v.z); v.w = tf32r(v.w);
            *(float4*)&Bs[t][bk + i * 8][bn] = v;
        }
    __syncthreads();
#pragma unroll
    for (int mi = 0; mi < 2; mi++)
#pragma unroll
        for (int ni = 0; ni < 8; ni++)
#pragma unroll
            for (int r = 0; r < 4; r++) c[mi][ni][r] = 0.0f;
#pragma unroll
    for (int kt = 0; kt < 2; kt++)
#pragma unroll
        for (int k8 = 0; k8 < 32; k8 += 8) {
            uint32_t a[2][4];
#pragma unroll
            for (int mi = 0; mi < 2; mi++) {
                int r0 = warp_m + mi * 16 + g;
                a[mi][0] = __float_as_uint(As[kt][r0][k8 + tg]);
                a[mi][1] = __float_as_uint(As[kt][r0 + 8][k8 + tg]);
                a[mi][2] = __float_as_uint(As[kt][r0][k8 + tg + 4]);
                a[mi][3] = __float_as_uint(As[kt][r0 + 8][k8 + tg + 4]);
            }
            uint32_t b[8][2];
#pragma unroll
            for (int ni = 0; ni < 8; ni++) {
                b[ni][0] = __float_as_uint(Bs[kt][k8 + tg][ni * 8 + g]);
                b[ni][1] = __float_as_uint(Bs[kt][k8 + tg + 4][ni * 8 + g]);
            }
#pragma unroll
            for (int mi = 0; mi < 2; mi++)
#pragma unroll
                for (int ni = 0; ni < 8; ni++)
                    mma_tf32(c[mi][ni], a[mi], b[ni]);
        }
#pragma unroll
    for (int mi = 0; mi < 2; mi++)
#pragma unroll
        for (int rr = 0; rr < 2; rr++) {
            int m = m0 + warp_m + mi * 16 + g + rr * 8;
#pragma unroll
            for (int ni = 0; ni < 8; ni++) {
                int n = ni * 8 + tg * 2;
                float v0 = c[mi][ni][rr * 2 + 0] + b2[n]     + x[(size_t)m * 64 + n];
                float v1 = c[mi][ni][rr * 2 + 1] + b2[n + 1] + x[(size_t)m * 64 + n + 1];
                *(float2*)&xout[(size_t)m * 64 + n] = make_float2(v0, v1);
            }
        }
}

// ---------------- fused GCN: t2 = relu((A_hat@gx)@W1+b1)@W2 -------------------
// A-loader performs the CSR aggregation gather directly from gx.
__global__ __launch_bounds__(128) void gcn_kernel(
    const float* __restrict__ gx, const float* __restrict__ dinv,
    const int* __restrict__ rowptr, const int* __restrict__ srcs,
    float* __restrict__ t2,
    const float* __restrict__ W1, const float* __restrict__ bb1,
    const float* __restrict__ W2)
{
    __shared__ float As[2][128][36];
    __shared__ float Bs[2][32][72];
    float* Asf = &As[0][0][0];

    const int tid = threadIdx.x, warp = tid >> 5, lane = tid & 31;
    const int g = lane >> 2, tg = lane & 3;
    const int m0 = blockIdx.x * 128, warp_m = warp * 32;
    const int am = tid >> 3, ak = (tid & 7) * 4;
    const int bk = tid >> 4, bn = (tid & 15) * 4;

    // stage A = A_hat @ gx (CSR gather per row), B = W1
    for (int b = 0; b < 2; b++)
        for (int i = 0; i < 8; i++) {
            int m = m0 + am + i * 16;
            int c0 = b * 32 + ak;
            float di = dinv[m];
            float4 acc = *(const float4*)(gx + (size_t)m * 64 + c0);
            acc.x *= di; acc.y *= di; acc.z *= di; acc.w *= di;
            int r1 = rowptr[m + 1];
            for (int r = rowptr[m]; r < r1; r++) {
                int s = srcs[r];
                float ds = dinv[s];
                float4 v = *(const float4*)(gx + (size_t)s * 64 + c0);
                acc.x = fmaf(ds, v.x, acc.x); acc.y = fmaf(ds, v.y, acc.y);
                acc.z = fmaf(ds, v.z, acc.z); acc.w = fmaf(ds, v.w, acc.w);
            }
            acc.x = tf32r(acc.x * di); acc.y = tf32r(acc.y * di);
            acc.z = tf32r(acc.z * di); acc.w = tf32r(acc.w * di);
            *(float4*)&As[b][am + i * 16][ak] = acc;
        }
#pragma unroll
    for (int i = 0; i < 8; i++) {
        int k = bk + i * 8;
        float4 v = *(const float4*)(W1 + (size_t)k * 64 + bn);
        v.x = tf32r(v.x); v.y = tf32r(v.y); v.z = tf32r(v.z); v.w = tf32r(v.w);
        *(float4*)&Bs[k >> 5][k & 31][bn] = v;
    }
    __syncthreads();

    float c[2][8][4];
#pragma unroll
    for (int mi = 0; mi < 2; mi++)
#pragma unroll
        for (int ni = 0; ni < 8; ni++)
#pragma unroll
            for (int r = 0; r < 4; r++) c[mi][ni][r] = 0.0f;
#pragma unroll
    for (int kt = 0; kt < 2; kt++)
#pragma unroll
        for (int k8 = 0; k8 < 32; k8 += 8) {
            uint32_t a[2][4];
#pragma unroll
            for (int mi = 0; mi < 2; mi++) {
                int r0 = warp_m + mi * 16 + g;
                a[mi][0] = __float_as_uint(As[kt][r0][k8 + tg]);
                a[mi][1] = __float_as_uint(As[kt][r0 + 8][k8 + tg]);
                a[mi][2] = __float_as_uint(As[kt][r0][k8 + tg + 4]);
                a[mi][3] = __float_as_uint(As[kt][r0 + 8][k8 + tg + 4]);
            }
            uint32_t b[8][2];
#pragma unroll
            for (int ni = 0; ni < 8; ni++) {
                b[ni][0] = __float_as_uint(Bs[kt][k8 + tg][ni * 8 + g]);
                b[ni][1] = __float_as_uint(Bs[kt][k8 + tg + 4][ni * 8 + g]);
            }
#pragma unroll
            for (int mi = 0; mi < 2; mi++)
#pragma unroll
                for (int ni = 0; ni < 8; ni++)
                    mma_tf32(c[mi][ni], a[mi], b[ni]);
        }
    // h = relu(c + b1) -> As (own-warp rows)
#pragma unroll
    for (int mi = 0; mi < 2; mi++)
#pragma unroll
        for (int rr = 0; rr < 2; rr++) {
            int ml = warp_m + mi * 16 + g + rr * 8;
#pragma unroll
            for (int ni = 0; ni < 8; ni++) {
                int n = ni * 8 + tg * 2;
                float v0 = fmaxf(c[mi][ni][rr * 2 + 0] + bb1[n], 0.f);
                float v1 = fmaxf(c[mi][ni][rr * 2 + 1] + bb1[n + 1], 0.f);
                int idx = (n >> 5) * 4608 + ml * 36 + (n & 31);
                Asf[idx]     = tf32r(v0);
                Asf[idx + 1] = tf32r(v1);
            }
        }
    __syncthreads();

    // stage B = W2
#pragma unroll
    for (int i = 0; i < 8; i++) {
        int k = bk + i * 8;
        float4 v = *(const float4*)(W2 + (size_t)k * 64 + bn);
        v.x = tf32r(v.x); v.y = tf32r(v.y); v.z = tf32r(v.z); v.w = tf32r(v.w);
        *(float4*)&Bs[k >> 5][k & 31][bn] = v;
    }
    __syncthreads();
#pragma unroll
    for (int mi = 0; mi < 2; mi++)
#pragma unroll
        for (int ni = 0; ni < 8; ni++)
#pragma unroll
            for (int r = 0; r < 4; r++) c[mi][ni][r] = 0.0f;
#pragma unroll
    for (int kt = 0; kt < 2; kt++)
#pragma unroll
        for (int k8 = 0; k8 < 32; k8 += 8) {
            uint32_t a[2][4];
#pragma unroll
            for (int mi = 0; mi < 2; mi++) {
                int r0 = warp_m + mi * 16 + g;
                a[mi][0] = __float_as_uint(As[kt][r0][k8 + tg]);
                a[mi][1] = __float_as_uint(As[kt][r0 + 8][k8 + tg]);
                a[mi][2] = __float_as_uint(As[kt][r0][k8 + tg + 4]);
                a[mi][3] = __float_as_uint(As[kt][r0 + 8][k8 + tg + 4]);
            }
            uint32_t b[8][2];
#pragma unroll
            for (int ni = 0; ni < 8; ni++) {
                b[ni][0] = __float_as_uint(Bs[kt][k8 + tg][ni * 8 + g]);
                b[ni][1] = __float_as_uint(Bs[kt][k8 + tg + 4][ni * 8 + g]);
            }
#pragma unroll
            for (int mi = 0; mi < 2; mi++)
#pragma unroll
                for (int ni = 0; ni < 8; ni++)
                    mma_tf32(c[mi][ni], a[mi], b[ni]);
        }
#pragma unroll
    for (int mi = 0; mi < 2; mi++)
#pragma unroll
        for (int rr = 0; rr < 2; rr++) {
            int m = m0 + warp_m + mi * 16 + g + rr * 8;
#pragma unroll
            for (int ni = 0; ni < 8; ni++) {
                int n = ni * 8 + tg * 2;
                *(float2*)&t2[(size_t)m * 64 + n] =
                    make_float2(c[mi][ni][rr * 2 + 0], c[mi][ni][rr * 2 + 1]);
            }
        }
}

// ---------------- rbf coupling + transpose (fast math) ----------------
__device__ __forceinline__ float exp_neg_04(float dist) {
    float t  = dist * -0.5770780163555852f;
    float fn = floorf(t);
    float fr = t - fn;
    float p  = 1.5403530e-4f;
    p = fmaf(p, fr, 1.33335581e-3f);
    p = fmaf(p, fr, 9.61812911e-3f);
    p = fmaf(p, fr, 5.55041087e-2f);
    p = fmaf(p, fr, 2.40226507e-1f);
    p = fmaf(p, fr, 6.93147181e-1f);
    p = fmaf(p, fr, 1.0f);
    int n = (int)fn;
    n = n < -126 ? -126 : n;
    return p * __int_as_float((n + 127) << 23);
}

__global__ void rbf_kernel(const float* __restrict__ vert, const float* __restrict__ gp,
                           float* __restrict__ rbf, float* __restrict__ rbfT)
{
    __shared__ float tile[32][33];
    int tx = threadIdx.x, ty = threadIdx.y;
    int g = blockIdx.x * 32 + tx;
    int v = blockIdx.y * 32 + ty;
    float vx = vert[v * 3], vy = vert[v * 3 + 1], vz = vert[v * 3 + 2];
    float gx = gp[g * 3],  gy = gp[g * 3 + 1],  gz = gp[g * 3 + 2];
    float dx = vx - gx, dy = vy - gy, dz = vz - gz;
    float d2 = fmaf(dx, dx, fmaf(dy, dy, dz * dz));
    d2 = fmaxf(d2, 1e-24f);
    float rs;
    asm("rsqrt.approx.f32 %0, %1;" : "=f"(rs) : "f"(d2));
    float r = exp_neg_04(d2 * rs);
    rbf[(size_t)v * NG + g] = r;
    tile[ty][tx] = r;
    __syncthreads();
    int g2 = blockIdx.x * 32 + ty;
    int v2 = blockIdx.y * 32 + tx;
    rbfT[(size_t)g2 * NV + v2] = tile[tx][ty];
}

__global__ void transpose_kernel(const float* __restrict__ in, float* __restrict__ out)
{
    __shared__ float t[32][33];
    int x = blockIdx.x * 32 + threadIdx.x;
    int y = blockIdx.y * 32 + threadIdx.y;
    t[threadIdx.y][threadIdx.x] = in[(size_t)y * 128 + x];
    __syncthreads();
    int ox = blockIdx.y * 32 + threadIdx.x;
    int oy = blockIdx.x * 32 + threadIdx.y;
    out[(size_t)oy * NV + ox] = t[threadIdx.x][threadIdx.y];
}

__global__ void wcat_kernel(const float* __restrict__ are, const float* __restrict__ aim,
                            float* __restrict__ W)
{
    int gid = blockIdx.x * 256 + threadIdx.x;   // NBLK*KK*64
    int blk = gid >> 13;
    int r = gid & 8191;
    int k = r >> 6, d = r & 63;
    const float* a_re = are + blk * 64 * 64;
    const float* a_im = aim + blk * 64 * 64;
    float wre, wim;
    if (k < 64) { wre = a_re[k * 64 + d];         wim = a_im[k * 64 + d]; }
    else        { wre = -a_im[(k - 64) * 64 + d]; wim = a_re[(k - 64) * 64 + d]; }
    float* Wb = W + blk * 2 * KK * 64;
    Wb[r]           = wre;
    Wb[KK * 64 + r] = wim;
}

// ---------------- GCN CSR build ----------------
__global__ void deg_kernel(const int* __restrict__ dst, float* __restrict__ deg)
{
    int e = blockIdx.x * 256 + threadIdx.x;
    atomicAdd(&deg[dst[e]], 1.0f);
}
__global__ void dinv_kernel(const float* __restrict__ deg, float* __restrict__ dinv)
{
    int i = blockIdx.x * 256 + threadIdx.x;
    dinv[i] = rsqrtf(deg[i] + 1.0f);
}
__global__ __launch_bounds__(1024) void scan_kernel(const float* __restrict__ deg,
                                                    int* __restrict__ rowptr,
                                                    int* __restrict__ cursor)
{
    __shared__ int p[1024];
    int t = threadIdx.x;
    int d0 = (int)deg[2 * t], d1 = (int)deg[2 * t + 1];
    p[t] = d0 + d1;
    __syncthreads();
    for (int off = 1; off < 1024; off <<= 1) {
        int v = p[t];
        if (t >= off) v += p[t - off];
        __syncthreads();
        p[t] = v;
        __syncthreads();
    }
    int excl = (t == 0) ? 0 : p[t - 1];
    rowptr[2 * t]     = excl;
    rowptr[2 * t + 1] = excl + d0;
    if (t == 1023) rowptr[2048] = p[1023];
    cursor[2 * t] = 0;
    cursor[2 * t + 1] = 0;
}
__global__ void scatter_kernel(const int* __restrict__ src, const int* __restrict__ dst,
                               const int* __restrict__ rowptr, int* __restrict__ cursor,
                               int* __restrict__ srcs)
{
    int e = blockIdx.x * 256 + threadIdx.x;
    int s = src[e], t = dst[e];
    int pos = rowptr[t] + atomicAdd(&cursor[t], 1);
    srcs[pos] = s;
}
__global__ void csr_agg_kernel(const float* __restrict__ hw, const float* __restrict__ dinv,
                               const int* __restrict__ rowptr, const int* __restrict__ srcs,
                               float* __restrict__ agg)
{
    int gid = blockIdx.x * 256 + threadIdx.x;   // NG*64
    int i = gid >> 6, d = gid & 63;
    float di = dinv[i];
    float acc = hw[i * 64 + d] * di;
    int r1 = rowptr[i + 1];
    for (int r = rowptr[i]; r < r1; r++) {
        int s = srcs[r];
        acc += hw[s * 64 + d] * dinv[s];
    }
    agg[gid] = acc * di;
}

// ---------------- head / tail ----------------
__global__ void lin1_kernel(const float* __restrict__ sx, const float* __restrict__ w,
                            const float* __restrict__ b, float* __restrict__ y)
{
    int gid = blockIdx.x * 256 + threadIdx.x;   // NV*64
    int v = gid >> 6, d = gid & 63;
    float acc = b[d];
#pragma unroll
    for (int j = 0; j < 5; j++) acc += sx[v * 5 + j] * w[j * 64 + d];
    y[gid] = acc;
}

__global__ void out_kernel(const float* __restrict__ y, const float* __restrict__ w,
                           const float* __restrict__ b, float* __restrict__ out)
{
    int gid = blockIdx.x * 256 + threadIdx.x;   // NV*8
    int v = gid >> 3, c = gid & 7;
    float acc = b[c];
#pragma unroll 8
    for (int d = 0; d < 64; d++) acc += y[v * 64 + d] * w[d * 8 + c];
    out[gid] = acc;
}

// ---------------- host ----------------
static inline Sl sl1(const float* A, float* C, int ldc) {
    Sl s; for (int i = 0; i < 4; i++) { s.A[i] = A; s.C[i] = C; s.ldc[i] = ldc; }
    return s;
}

extern "C" void kernel_launch(void* const* d_in, const int* in_sizes, int n_in,
                              void* d_out, int out_size)
{
    static bool inited = false;
    static float *p_rbf, *p_rbfT, *p_xd, *p_xout, *p_y, *p_cat, *p_b2,
                 *p_sg, *p_W, *p_GE, *p_eT, *p_hw, *p_agg2, *p_deg, *p_dinv;
    static int *p_rowptr, *p_cursor, *p_srcs;
    if (!inited) {
        cudaGetSymbolAddress((void**)&p_rbf,  g_rbf);
        cudaGetSymbolAddress((void**)&p_rbfT, g_rbfT);
        cudaGetSymbolAddress((void**)&p_xd,   g_xd);
        cudaGetSymbolAddress((void**)&p_xout, g_xout);
        cudaGetSymbolAddress((void**)&p_y,    g_y);
        cudaGetSymbolAddress((void**)&p_cat,  g_cat);
        cudaGetSymbolAddress((void**)&p_b2,   g_b2);
        cudaGetSymbolAddress((void**)&p_sg,   g_sg);
        cudaGetSymbolAddress((void**)&p_W,    g_W);
        cudaGetSymbolAddress((void**)&p_GE,   g_GE);
        cudaGetSymbolAddress((void**)&p_eT,   g_eT);
        cudaGetSymbolAddress((void**)&p_hw,   g_hw);
        cudaGetSymbolAddress((void**)&p_agg2, g_agg2);
        cudaGetSymbolAddress((void**)&p_deg,  g_deg);
        cudaGetSymbolAddress((void**)&p_dinv, g_dinv);
        cudaGetSymbolAddress((void**)&p_rowptr, g_rowptr);
        cudaGetSymbolAddress((void**)&p_cursor, g_cursor);
        cudaGetSymbolAddress((void**)&p_srcs,   g_srcs);
        inited = true;
    }
    float* p_xs = p_sg;
    float* p_gx = p_sg + KK * 64;

    const float* surf_x    = (const float*)d_in[0];
    const float* mass      = (const float*)d_in[1];
    const float* evals     = (const float*)d_in[2];
    const float* evecs     = (const float*)d_in[3];
    const float* gradX     = (const float*)d_in[4];
    const float* gradY     = (const float*)d_in[5];
    const float* vertices  = (const float*)d_in[6];
    const float* graph_pos = (const float*)d_in[8];
    const float* lin1_w    = (const float*)d_in[9];
    const float* lin1_b    = (const float*)d_in[10];
    const float* last_w    = (const float*)d_in[13];
    const float* last_b    = (const float*)d_in[14];
    const float* diff_time = (const float*)d_in[15];
    const float* A_re      = (const float*)d_in[16];
    const float* A_im      = (const float*)d_in[17];
    const float* mlp_w0    = (const float*)d_in[18];
    const float* mlp_b0    = (const float*)d_in[19];
    const float* mlp_w1    = (const float*)d_in[20];
    const float* mlp_b1    = (const float*)d_in[21];
    const float* mlp_w2    = (const float*)d_in[22];
    const float* mlp_b2    = (const float*)d_in[23];
    const float* gcn_w1    = (const float*)d_in[24];
    const float* gcn_b1    = (const float*)d_in[25];
    const float* gcn_w2    = (const float*)d_in[26];
    const float* gcn_b2    = (const float*)d_in[27];
    const int*   eidx      = (const int*)d_in[28];
    const int*   e_src     = eidx;
    const int*   e_dst     = eidx + EE;
    float* out = (float*)d_out;

    // ---- setup (serial) ----
    rbf_kernel<<<dim3(NG / 32, NV / 32), dim3(32, 32)>>>(vertices, graph_pos, p_rbf, p_rbfT);

    cudaMemsetAsync(p_deg, 0, NG * sizeof(float));
    deg_kernel<<<EE / 256, 256>>>(e_dst, p_deg);
    dinv_kernel<<<NG / 256, 256>>>(p_deg, p_dinv);
    scan_kernel<<<1, 1024>>>(p_deg, p_rowptr, p_cursor);
    scatter_kernel<<<EE / 256, 256>>>(e_src, e_dst, p_rowptr, p_cursor, p_srcs);

    transpose_kernel<<<dim3(KK / 32, NV / 32), dim3(32, 32)>>>(evecs, p_eT);
    lin1_kernel<<<NV * 64 / 256, 256>>>(surf_x, lin1_w, lin1_b, p_y);       // -> y[0]
    wcat_kernel<<<NBLK * KK * 64 / 256, 256>>>(A_re, A_im, p_W);            // all blocks

    // GE = [gradX@evecs(lo) ; gradX@evecs(hi) ; gradY@evecs(lo) ; gradY@evecs(hi)]
    {
        Sl s;
        s.A[0] = gradX; s.A[1] = gradX; s.A[2] = gradY; s.A[3] = gradY;
        s.C[0] = p_GE;            s.C[1] = p_GE + 64;
        s.C[2] = p_GE + NV * 128; s.C[3] = p_GE + NV * 128 + 64;
        s.ldc[0] = s.ldc[1] = s.ldc[2] = s.ldc[3] = 128;
        gemm64<<<dim3(NV / 128, 1, 4), 128>>>(
            s, NV, evecs, evecs + 64, 128, NV, NV,
            nullptr, nullptr, 0, 0, nullptr, nullptr, nullptr, nullptr, nullptr);
    }

    for (int blk = 0; blk < NBLK; blk++) {
        const float* t   = diff_time + blk * 64;
        const float* w0  = mlp_w0 + blk * 192 * 64;
        const float* b0  = mlp_b0 + blk * 64;
        const float* w1  = mlp_w1 + blk * 64 * 64;
        const float* b1  = mlp_b1 + blk * 64;
        const float* w2  = mlp_w2 + blk * 64 * 64;
        const float* b2m = mlp_b2 + blk * 64;
        const float* gw1 = gcn_w1 + blk * 64 * 64;
        const float* gb1 = gcn_b1 + blk * 64;
        const float* gw2 = gcn_w2 + blk * 64 * 64;
        const float* gb2 = gcn_b2 + blk * 64;
        const float* Wb  = p_W + blk * 2 * KK * 64;
        float* yA = p_y + (blk & 1) * NV * 64;
        float* yB = p_y + (1 - (blk & 1)) * NV * 64;

        // zero split-K targets
        cudaMemsetAsync(yB, 0, NV * 64 * sizeof(float));
        cudaMemsetAsync(p_sg, 0, (KK * 64 + NG * 64) * sizeof(float));

        // xs = evecsT @ (mass .* x)  (mass fused via bscale; split-K 32)
        gemm64<<<dim3(1, 32, 1), 128>>>(
            sl1(p_eT, p_xs, 64), NV, yA, yA, 64, NV, NV / 32,
            nullptr, nullptr, 0, 0, nullptr, nullptr, mass, nullptr, nullptr);

        // [x_diff ; gX ; gY] = [evecs ; GE_X ; GE_Y] @ (coef * xs)  (exp fused)
        {
            Sl s;
            s.A[0] = evecs;          s.C[0] = p_xd;       s.ldc[0] = 64;
            s.A[1] = p_GE;           s.C[1] = p_cat;      s.ldc[1] = 128;
            s.A[2] = p_GE + NV*128;  s.C[2] = p_cat + 64; s.ldc[2] = 128;
            s.A[3] = evecs;          s.C[3] = p_xd;       s.ldc[3] = 64;
            gemm64<<<dim3(NV / 128, 1, 3), 128>>>(
                s, 128, p_xs, p_xs, 64, KK, KK,
                nullptr, nullptr, 0, 0, nullptr, nullptr, nullptr, evals, t);
        }

        // b_re|b_im = cat @ [Wre|Wim]
        {
            Sl s;
            s.A[0] = p_cat; s.C[0] = p_b2;           s.ldc[0] = 64;
            s.A[1] = p_cat; s.C[1] = p_b2 + NV * 64; s.ldc[1] = 64;
            s.A[2] = p_cat; s.C[2] = p_b2;           s.ldc[2] = 64;
            s.A[3] = p_cat; s.C[3] = p_b2;           s.ldc[3] = 64;
            gemm64<<<dim3(NV / 128, 1, 2), 128>>>(
                s, 128, Wb, Wb + KK * 64, 64, KK, KK,
                nullptr, nullptr, 0, 0, nullptr, nullptr, nullptr, nullptr, nullptr);
        }

        // fused MLP (gfeat computed in-loader) + residual -> xout
        mlp_kernel<<<NV / 128, 128>>>(yA, p_xd, p_xout, p_cat, p_b2,
                                      w0, b0, w1, b1, w2, b2m);

        // gx = rbf^T @ x' (split-K 8)
        gemm64<<<dim3(NG / 128, 8, 1), 128>>>(
            sl1(p_rbfT, p_gx, 64), NV, p_xout, p_xout, 64, NV, NV / 8,
            nullptr, nullptr, 0, 0, nullptr, nullptr, nullptr, nullptr, nullptr);

        // GCN: hw = relu((A_hat@gx)@W1 + b1)@W2   (gather fused in A-loader)
        gcn_kernel<<<NG / 128, 128>>>(p_gx, p_dinv, p_rowptr, p_srcs,
                                      p_hw, gw1, gb1, gw2);
        // agg2 = A_hat @ hw
        csr_agg_kernel<<<NG * 64 / 256, 256>>>(p_hw, p_dinv, p_rowptr, p_srcs, p_agg2);

        // diff_x = rbf @ (agg2 + gb2)  (B-loader bias fused; split-K 4) -> yB
        gemm64<<<dim3(NV / 128, 4, 1), 128>>>(
            sl1(p_rbf, yB, 64), NG, p_agg2, p_agg2, 64, NG, NG / 4,
            nullptr, nullptr, 0, 0, nullptr, gb2, nullptr, nullptr, nullptr);
    }

    // final: out = y[0] @ last_w + last_b
    out_kernel<<<(NV * 8) / 256, 256>>>(p_y, last_w, last_b, out);
}

// round 14
// speedup vs baseline: 1.1643x; 1.1643x over previous
#include <cuda_runtime.h>
#include <math.h>
#include <stdint.h>

#define NV 4096
#define NG 2048
#define KK 128
#define NBLK 4
#define EE 32768

// ---------------- scratch ----------------
__device__ float g_rbf [NV * NG];
__device__ float g_rbfT[NG * NV];
__device__ float g_xd  [NV * 64];        // x_diff
__device__ float g_xout[NV * 64];        // x' (MLP output)
__device__ float g_y   [2 * NV * 64];    // double-buffered diff_x
__device__ float g_cat [NV * 128];       // [gX | gY]
__device__ float g_b2  [2 * NV * 64];    // [b_re ; b_im]
__device__ float g_sg  [KK * 64 + NG * 64];  // [xs | gx] split-K targets (one memset)
__device__ float g_W   [NBLK * 2 * KK * 64]; // per-block [Wre ; Wim]
__device__ float g_GE  [2 * NV * 128];   // [gradX@evecs ; gradY@evecs]
__device__ float g_eT  [KK * NV];        // evecs^T
__device__ float g_hw  [NG * 64];
__device__ float g_agg [NG * 64];
__device__ float g_agg2[NG * 64];
__device__ float g_deg [NG];
__device__ float g_dinv[NG];
__device__ int   g_rowptr[NG + 1];
__device__ int   g_cursor[NG];
__device__ int   g_srcs[EE];

// ---------------- tf32 helpers ----------------
__device__ __forceinline__ float tf32r(float x) {
    uint32_t r;
    asm("cvt.rna.tf32.f32 %0, %1;" : "=r"(r) : "f"(x));
    return __uint_as_float(r);
}
__device__ __forceinline__ void mma_tf32(float* c, const uint32_t* a, const uint32_t* b) {
    asm volatile(
        "mma.sync.aligned.m16n8k8.row.col.f32.tf32.tf32.f32 "
        "{%0,%1,%2,%3}, {%4,%5,%6,%7}, {%8,%9}, {%0,%1,%2,%3};"
        : "+f"(c[0]), "+f"(c[1]), "+f"(c[2]), "+f"(c[3])
        : "r"(a[0]), "r"(a[1]), "r"(a[2]), "r"(a[3]), "r"(b[0]), "r"(b[1]));
}

// per-z slice descriptors
struct Sl {
    const float* A[4];
    float*       C[4];
    int          ldc[4];
};

// ---------------- generic N=64 GEMM (tf32 MMA), BM=128, 128 threads -----------
// abias:  A-load  a = relu(a + abias[k])
// bbias:  B-load  b = b + bbias[n]
// bscale: B-load  b = b * bscale[k]            (mass fusion for xs GEMM)
// bexp_*: B-load  b = b * exp(-ev[k] * max(t[n],eps))
// gridDim.y > 1 => split-K atomicAdd (caller zero-inits C).
__global__ __launch_bounds__(128) void gemm64(
    Sl sl, int lda,
    const float* __restrict__ B0, const float* __restrict__ B1, int ldb,
    int KB, int kchunk,
    const float* __restrict__ bias,
    const float* __restrict__ resid, int ldr, int act,
    const float* __restrict__ abias, const float* __restrict__ bbias,
    const float* __restrict__ bscale,
    const float* __restrict__ bexp_ev, const float* __restrict__ bexp_t)
{
    __shared__ float As[2][128][36];
    __shared__ float Bs[2][32][72];

    const int z = blockIdx.z;
    const float* A = sl.A[z];
    const float* B = (z & 1) ? B1 : B0;
    float* C = sl.C[z];
    const int ldc = sl.ldc[z];

    const int tid    = threadIdx.x;
    const int warp   = tid >> 5;
    const int lane   = tid & 31;
    const int g      = lane >> 2;
    const int tg     = lane & 3;
    const int m0     = blockIdx.x * 128;
    const int warp_m = warp * 32;
    const int kbeg   = blockIdx.y * kchunk;
    const int ntile  = kchunk >> 5;

    const int am = tid >> 3;
    const int ak = (tid & 7) * 4;
    const int bk = tid >> 4;
    const int bn = (tid & 15) * 4;

    float4 bb = make_float4(0.f, 0.f, 0.f, 0.f);
    if (bbias) bb = *(const float4*)(bbias + bn);
    float4 tc = make_float4(0.f, 0.f, 0.f, 0.f);
    if (bexp_t) {
        tc = *(const float4*)(bexp_t + bn);
        tc.x = fmaxf(tc.x, 1e-8f); tc.y = fmaxf(tc.y, 1e-8f);
        tc.z = fmaxf(tc.z, 1e-8f); tc.w = fmaxf(tc.w, 1e-8f);
    }

    float4 rA[8], rB[4];
    float c[2][8][4];
#pragma unroll
    for (int mi = 0; mi < 2; mi++)
#pragma unroll
        for (int ni = 0; ni < 8; ni++)
#pragma unroll
            for (int r = 0; r < 4; r++) c[mi][ni][r] = 0.0f;

    {   // prologue tile 0
        const float* ap = A + (size_t)(m0 + am) * lda + kbeg + ak;
        const float* bp = B + (size_t)(kbeg + bk) * ldb + bn;
#pragma unroll
        for (int i = 0; i < 8; i++) rA[i] = *(const float4*)(ap + (size_t)(i * 16) * lda);
#pragma unroll
        for (int i = 0; i < 4; i++) rB[i] = *(const float4*)(bp + (size_t)(i * 8) * ldb);
    }

    int buf = 0;
    for (int it = 0; it < ntile; it++) {
        const int kst = kbeg + it * 32;
#pragma unroll
        for (int i = 0; i < 8; i++) {
            float4 v = rA[i];
            if (abias) {
                float4 ab = *(const float4*)(abias + kst + ak);
                v.x = fmaxf(v.x + ab.x, 0.f); v.y = fmaxf(v.y + ab.y, 0.f);
                v.z = fmaxf(v.z + ab.z, 0.f); v.w = fmaxf(v.w + ab.w, 0.f);
            }
            v.x = tf32r(v.x); v.y = tf32r(v.y); v.z = tf32r(v.z); v.w = tf32r(v.w);
            *(float4*)&As[buf][am + i * 16][ak] = v;
        }
#pragma unroll
        for (int i = 0; i < 4; i++) {
            float4 v = rB[i];
            if (bscale) {
                float s = bscale[kst + bk + i * 8];
                v.x *= s; v.y *= s; v.z *= s; v.w *= s;
            }
            if (bexp_ev) {
                float ev = bexp_ev[kst + bk + i * 8];
                v.x *= __expf(-ev * tc.x); v.y *= __expf(-ev * tc.y);
                v.z *= __expf(-ev * tc.z); v.w *= __expf(-ev * tc.w);
            }
            v.x += bb.x; v.y += bb.y; v.z += bb.z; v.w += bb.w;
            v.x = tf32r(v.x); v.y = tf32r(v.y); v.z = tf32r(v.z); v.w = tf32r(v.w);
            *(float4*)&Bs[buf][bk + i * 8][bn] = v;
        }
        __syncthreads();

        if (it + 1 < ntile) {
            int kb = kbeg + (it + 1) * 32;
            const float* ap = A + (size_t)(m0 + am) * lda + kb + ak;
            const float* bp = B + (size_t)(kb + bk) * ldb + bn;
#pragma unroll
            for (int i = 0; i < 8; i++) rA[i] = *(const float4*)(ap + (size_t)(i * 16) * lda);
#pragma unroll
            for (int i = 0; i < 4; i++) rB[i] = *(const float4*)(bp + (size_t)(i * 8) * ldb);
        }

#pragma unroll
        for (int k8 = 0; k8 < 32; k8 += 8) {
            uint32_t a[2][4];
#pragma unroll
            for (int mi = 0; mi < 2; mi++) {
                int r0 = warp_m + mi * 16 + g;
                a[mi][0] = __float_as_uint(As[buf][r0][k8 + tg]);
                a[mi][1] = __float_as_uint(As[buf][r0 + 8][k8 + tg]);
                a[mi][2] = __float_as_uint(As[buf][r0][k8 + tg + 4]);
                a[mi][3] = __float_as_uint(As[buf][r0 + 8][k8 + tg + 4]);
            }
            uint32_t b[8][2];
#pragma unroll
            for (int ni = 0; ni < 8; ni++) {
                b[ni][0] = __float_as_uint(Bs[buf][k8 + tg][ni * 8 + g]);
                b[ni][1] = __float_as_uint(Bs[buf][k8 + tg + 4][ni * 8 + g]);
            }
#pragma unroll
            for (int mi = 0; mi < 2; mi++)
#pragma unroll
                for (int ni = 0; ni < 8; ni++)
                    mma_tf32(c[mi][ni], a[mi], b[ni]);
        }
        buf ^= 1;
    }

    const bool split = (gridDim.y > 1);
#pragma unroll
    for (int mi = 0; mi < 2; mi++) {
#pragma unroll
        for (int rr = 0; rr < 2; rr++) {
            int m = m0 + warp_m + mi * 16 + g + rr * 8;
#pragma unroll
            for (int ni = 0; ni < 8; ni++) {
                int n = ni * 8 + tg * 2;
                float v0 = c[mi][ni][rr * 2 + 0];
                float v1 = c[mi][ni][rr * 2 + 1];
                if (split) {
                    atomicAdd(&C[(size_t)m * ldc + n],     v0);
                    atomicAdd(&C[(size_t)m * ldc + n + 1], v1);
                } else {
                    if (bias)  { v0 += bias[n]; v1 += bias[n + 1]; }
                    if (resid) { v0 += resid[(size_t)m * ldr + n];
                                 v1 += resid[(size_t)m * ldr + n + 1]; }
                    if (act)   { v0 = fmaxf(v0, 0.0f); v1 = fmaxf(v1, 0.0f); }
                    *(float2*)&C[(size_t)m * ldc + n] = make_float2(v0, v1);
                }
            }
        }
    }
}

// ---------------- fused 3-layer MLP (one launch) -------------------------------
// A-loader: k<64 -> x (yA), k<128 -> x_diff, k>=128 -> gfeat from cat/b2.
__device__ __forceinline__ float4 load_f_ext(
    const float* __restrict__ x, const float* __restrict__ xd,
    const float* __restrict__ cat, const float* __restrict__ b2, int m, int k)
{
    if (k < 64)  return *(const float4*)(x  + (size_t)m * 64 + k);
    if (k < 128) return *(const float4*)(xd + (size_t)m * 64 + k - 64);
    int kk = k - 128;
    float4 gx = *(const float4*)(cat + (size_t)m * 128 + kk);
    float4 gy = *(const float4*)(cat + (size_t)m * 128 + 64 + kk);
    float4 br = *(const float4*)(b2 + (size_t)m * 64 + kk);
    float4 bi = *(const float4*)(b2 + (size_t)(NV * 64) + (size_t)m * 64 + kk);
    float4 r;
    r.x = tanhf(gx.x * br.x + gy.x * bi.x);
    r.y = tanhf(gx.y * br.y + gy.y * bi.y);
    r.z = tanhf(gx.z * br.z + gy.z * bi.z);
    r.w = tanhf(gx.w * br.w + gy.w * bi.w);
    return r;
}

__global__ __launch_bounds__(128) void mlp_kernel(
    const float* __restrict__ x, const float* __restrict__ xd,
    float* __restrict__ xout,
    const float* __restrict__ cat, const float* __restrict__ b2v,
    const float* __restrict__ w0, const float* __restrict__ b0,
    const float* __restrict__ w1, const float* __restrict__ b1,
    const float* __restrict__ w2, const float* __restrict__ b2)
{
    __shared__ float As[2][128][36];
    __shared__ float Bs[2][32][72];

    const int tid = threadIdx.x, warp = tid >> 5, lane = tid & 31;
    const int g = lane >> 2, tg = lane & 3;
    const int m0 = blockIdx.x * 128, warp_m = warp * 32;
    const int am = tid >> 3, ak = (tid & 7) * 4;
    const int bk = tid >> 4, bn = (tid & 15) * 4;

    float c[2][8][4];
#pragma unroll
    for (int mi = 0; mi < 2; mi++)
#pragma unroll
        for (int ni = 0; ni < 8; ni++)
#pragma unroll
            for (int r = 0; r < 4; r++) c[mi][ni][r] = 0.0f;

    // ---- phase 1: h1 = relu(fext @ w0 + b0), K=192 streamed (6 tiles) ----
    float4 rA[8], rB[4];
    {
#pragma unroll
        for (int i = 0; i < 8; i++)
            rA[i] = load_f_ext(x, xd, cat, b2v, m0 + am + i * 16, ak);
        const float* bp = w0 + (size_t)bk * 64 + bn;
#pragma unroll
        for (int i = 0; i < 4; i++) rB[i] = *(const float4*)(bp + (size_t)(i * 8) * 64);
    }
    int buf = 0;
    for (int it = 0; it < 6; it++) {
#pragma unroll
        for (int i = 0; i < 8; i++) {
            float4 v = rA[i];
            v.x = tf32r(v.x); v.y = tf32r(v.y); v.z = tf32r(v.z); v.w = tf32r(v.w);
            *(float4*)&As[buf][am + i * 16][ak] = v;
        }
#pragma unroll
        for (int i = 0; i < 4; i++) {
            float4 v = rB[i];
            v.x = tf32r(v.x); v.y = tf32r(v.y); v.z = tf32r(v.z); v.w = tf32r(v.w);
            *(float4*)&Bs[buf][bk + i * 8][bn] = v;
        }
        __syncthreads();
        if (it + 1 < 6) {
            int kb = (it + 1) * 32;
#pragma unroll
            for (int i = 0; i < 8; i++)
                rA[i] = load_f_ext(x, xd, cat, b2v, m0 + am + i * 16, kb + ak);
            const float* bp = w0 + (size_t)(kb + bk) * 64 + bn;
#pragma unroll
            for (int i = 0; i < 4; i++) rB[i] = *(const float4*)(bp + (size_t)(i * 8) * 64);
        }
#pragma unroll
        for (int k8 = 0; k8 < 32; k8 += 8) {
            uint32_t a[2][4];
#pragma unroll
            for (int mi = 0; mi < 2; mi++) {
                int r0 = warp_m + mi * 16 + g;
                a[mi][0] = __float_as_uint(As[buf][r0][k8 + tg]);
                a[mi][1] = __float_as_uint(As[buf][r0 + 8][k8 + tg]);
                a[mi][2] = __float_as_uint(As[buf][r0][k8 + tg + 4]);
                a[mi][3] = __float_as_uint(As[buf][r0 + 8][k8 + tg + 4]);
            }
            uint32_t b[8][2];
#pragma unroll
            for (int ni = 0; ni < 8; ni++) {
                b[ni][0] = __float_as_uint(Bs[buf][k8 + tg][ni * 8 + g]);
                b[ni][1] = __float_as_uint(Bs[buf][k8 + tg + 4][ni * 8 + g]);
            }
#pragma unroll
            for (int mi = 0; mi < 2; mi++)
#pragma unroll
                for (int ni = 0; ni < 8; ni++)
                    mma_tf32(c[mi][ni], a[mi], b[ni]);
        }
        buf ^= 1;
    }
    // h1 -> As (own-warp rows)
#pragma unroll
    for (int mi = 0; mi < 2; mi++)
#pragma unroll
        for (int rr = 0; rr < 2; rr++) {
            int ml = warp_m + mi * 16 + g + rr * 8;
#pragma unroll
            for (int ni = 0; ni < 8; ni++) {
                int n = ni * 8 + tg * 2;
                float v0 = fmaxf(c[mi][ni][rr * 2 + 0] + b0[n], 0.f);
                float v1 = fmaxf(c[mi][ni][rr * 2 + 1] + b0[n + 1], 0.f);
                *(float2*)&As[n >> 5][ml][n & 31] = make_float2(tf32r(v0), tf32r(v1));
            }
        }
    __syncthreads();

    // ---- phase 2: h2 = relu(h1 @ w1 + b1) ----
#pragma unroll
    for (int t = 0; t < 2; t++)
#pragma unroll
        for (int i = 0; i < 4; i++) {
            float4 v = *(const float4*)(w1 + (size_t)(t * 32 + bk + i * 8) * 64 + bn);
            v.x = tf32r(v.x); v.y = tf32r(v.y); v.z = tf32r(v.z); v.w = tf32r(v.w);
            *(float4*)&Bs[t][bk + i * 8][bn] = v;
        }
    __syncthreads();
#pragma unroll
    for (int mi = 0; mi < 2; mi++)
#pragma unroll
        for (int ni = 0; ni < 8; ni++)
#pragma unroll
            for (int r = 0; r < 4; r++) c[mi][ni][r] = 0.0f;
#pragma unroll
    for (int kt = 0; kt < 2; kt++)
#pragma unroll
        for (int k8 = 0; k8 < 32; k8 += 8) {
            uint32_t a[2][4];
#pragma unroll
            for (int mi = 0; mi < 2; mi++) {
                int r0 = warp_m + mi * 16 + g;
                a[mi][0] = __float_as_uint(As[kt][r0][k8 + tg]);
                a[mi][1] = __float_as_uint(As[kt][r0 + 8][k8 + tg]);
                a[mi][2] = __float_as_uint(As[kt][r0][k8 + tg + 4]);
                a[mi][3] = __float_as_uint(As[kt][r0 + 8][k8 + tg + 4]);
            }
            uint32_t b[8][2];
#pragma unroll
            for (int ni = 0; ni < 8; ni++) {
                b[ni][0] = __float_as_uint(Bs[kt][k8 + tg][ni * 8 + g]);
                b[ni][1] = __float_as_uint(Bs[kt][k8 + tg + 4][ni * 8 + g]);
            }
#pragma unroll
            for (int mi = 0; mi < 2; mi++)
#pragma unroll
                for (int ni = 0; ni < 8; ni++)
                    mma_tf32(c[mi][ni], a[mi], b[ni]);
        }
#pragma unroll
    for (int mi = 0; mi < 2; mi++)
#pragma unroll
        for (int rr = 0; rr < 2; rr++) {
            int ml = warp_m + mi * 16 + g + rr * 8;
#pragma unroll
            for (int ni = 0; ni < 8; ni++) {
                int n = ni * 8 + tg * 2;
                float v0 = fmaxf(c[mi][ni][rr * 2 + 0] + b1[n], 0.f);
                float v1 = fmaxf(c[mi][ni][rr * 2 + 1] + b1[n + 1], 0.f);
                *(float2*)&As[n >> 5][ml][n & 31] = make_float2(tf32r(v0), tf32r(v1));
            }
        }
    __syncthreads();

    // ---- phase 3: x' = h2 @ w2 + b2 + x -> xout ----
#pragma unroll
    for (int t = 0; t < 2; t++)
#pragma unroll
        for (int i = 0; i < 4; i++) {
            float4 v = *(const float4*)(w2 + (size_t)(t * 32 + bk + i * 8) * 64 + bn);
            v.x = tf32r(v.x); v.y = tf32r(v.y); v.z = tf32r(v.z); v.w = tf32r(v.w);
            *(float4*)&Bs[t][bk + i * 8][bn] = v;
        }
    __syncthreads();
#pragma unroll
    for (int mi = 0; mi < 2; mi++)
#pragma unroll
        for (int ni = 0; ni < 8; ni++)
#pragma unroll
            for (int r = 0; r < 4; r++) c[mi][ni][r] = 0.0f;
#pragma unroll
    for (int kt = 0; kt < 2; kt++)
#pragma unroll
        for (int k8 = 0; k8 < 32; k8 += 8) {
            uint32_t a[2][4];
#pragma unroll
            for (int mi = 0; mi < 2; mi++) {
                int r0 = warp_m + mi * 16 + g;
                a[mi][0] = __float_as_uint(As[kt][r0][k8 + tg]);
                a[mi][1] = __float_as_uint(As[kt][r0 + 8][k8 + tg]);
                a[mi][2] = __float_as_uint(As[kt][r0][k8 + tg + 4]);
                a[mi][3] = __float_as_uint(As[kt][r0 + 8][k8 + tg + 4]);
            }
            uint32_t b[8][2];
#pragma unroll
            for (int ni = 0; ni < 8; ni++) {
                b[ni][0] = __float_as_uint(Bs[kt][k8 + tg][ni * 8 + g]);
                b[ni][1] = __float_as_uint(Bs[kt][k8 + tg + 4][ni * 8 + g]);
            }
#pragma unroll
            for (int mi = 0; mi < 2; mi++)
#pragma unroll
                for (int ni = 0; ni < 8; ni++)
                    mma_tf32(c[mi][ni], a[mi], b[ni]);
        }
#pragma unroll
    for (int mi = 0; mi < 2; mi++)
#pragma unroll
        for (int rr = 0; rr < 2; rr++) {
            int m = m0 + warp_m + mi * 16 + g + rr * 8;
#pragma unroll
            for (int ni = 0; ni < 8; ni++) {
                int n = ni * 8 + tg * 2;
                float v0 = c[mi][ni][rr * 2 + 0] + b2[n]     + x[(size_t)m * 64 + n];
                float v1 = c[mi][ni][rr * 2 + 1] + b2[n + 1] + x[(size_t)m * 64 + n + 1];
                *(float2*)&xout[(size_t)m * 64 + n] = make_float2(v0, v1);
            }
        }
}

// ---------------- fused 2-layer GCN: t2 = (relu(t1@W1+b1))@W2 ----------------
__global__ __launch_bounds__(128) void gcn_kernel(
    const float* __restrict__ t1, float* __restrict__ t2,
    const float* __restrict__ W1, const float* __restrict__ bb1,
    const float* __restrict__ W2)
{
    __shared__ float As[2][128][36];
    __shared__ float Bs[2][32][72];
    float* Asf = &As[0][0][0];

    const int tid = threadIdx.x, warp = tid >> 5, lane = tid & 31;
    const int g = lane >> 2, tg = lane & 3;
    const int m0 = blockIdx.x * 128, warp_m = warp * 32;
    const int am = tid >> 3, ak = (tid & 7) * 4;
    const int bk = tid >> 4, bn = (tid & 15) * 4;

    // stage A = t1 (128x64), B = W1 (64x64)
#pragma unroll
    for (int b = 0; b < 2; b++)
#pragma unroll
        for (int i = 0; i < 8; i++) {
            float4 v = *(const float4*)(t1 + (size_t)(m0 + am + i * 16) * 64 + b * 32 + ak);
            v.x = tf32r(v.x); v.y = tf32r(v.y); v.z = tf32r(v.z); v.w = tf32r(v.w);
            *(float4*)&As[b][am + i * 16][ak] = v;
        }
#pragma unroll
    for (int i = 0; i < 8; i++) {
        int k = bk + i * 8;
        float4 v = *(const float4*)(W1 + (size_t)k * 64 + bn);
        v.x = tf32r(v.x); v.y = tf32r(v.y); v.z = tf32r(v.z); v.w = tf32r(v.w);
        *(float4*)&Bs[k >> 5][k & 31][bn] = v;
    }
    __syncthreads();

    float c[2][8][4];
#pragma unroll
    for (int mi = 0; mi < 2; mi++)
#pragma unroll
        for (int ni = 0; ni < 8; ni++)
#pragma unroll
            for (int r = 0; r < 4; r++) c[mi][ni][r] = 0.0f;
#pragma unroll
    for (int kt = 0; kt < 2; kt++)
#pragma unroll
        for (int k8 = 0; k8 < 32; k8 += 8) {
            uint32_t a[2][4];
#pragma unroll
            for (int mi = 0; mi < 2; mi++) {
                int r0 = warp_m + mi * 16 + g;
                a[mi][0] = __float_as_uint(As[kt][r0][k8 + tg]);
                a[mi][1] = __float_as_uint(As[kt][r0 + 8][k8 + tg]);
                a[mi][2] = __float_as_uint(As[kt][r0][k8 + tg + 4]);
                a[mi][3] = __float_as_uint(As[kt][r0 + 8][k8 + tg + 4]);
            }
            uint32_t b[8][2];
#pragma unroll
            for (int ni = 0; ni < 8; ni++) {
                b[ni][0] = __float_as_uint(Bs[kt][k8 + tg][ni * 8 + g]);
                b[ni][1] = __float_as_uint(Bs[kt][k8 + tg + 4][ni * 8 + g]);
            }
#pragma unroll
            for (int mi = 0; mi < 2; mi++)
#pragma unroll
                for (int ni = 0; ni < 8; ni++)
                    mma_tf32(c[mi][ni], a[mi], b[ni]);
        }
    // h = relu(c + b1) -> As (own-warp rows)
#pragma unroll
    for (int mi = 0; mi < 2; mi++)
#pragma unroll
        for (int rr = 0; rr < 2; rr++) {
            int ml = warp_m + mi * 16 + g + rr * 8;
#pragma unroll
            for (int ni = 0; ni < 8; ni++) {
                int n = ni * 8 + tg * 2;
                float v0 = fmaxf(c[mi][ni][rr * 2 + 0] + bb1[n], 0.f);
                float v1 = fmaxf(c[mi][ni][rr * 2 + 1] + bb1[n + 1], 0.f);
                int idx = (n >> 5) * 4608 + ml * 36 + (n & 31);
                Asf[idx]     = tf32r(v0);
                Asf[idx + 1] = tf32r(v1);
            }
        }
    __syncthreads();

    // stage B = W2
#pragma unroll
    for (int i = 0; i < 8; i++) {
        int k = bk + i * 8;
        float4 v = *(const float4*)(W2 + (size_t)k * 64 + bn);
        v.x = tf32r(v.x); v.y = tf32r(v.y); v.z = tf32r(v.z); v.w = tf32r(v.w);
        *(float4*)&Bs[k >> 5][k & 31][bn] = v;
    }
    __syncthreads();
#pragma unroll
    for (int mi = 0; mi < 2; mi++)
#pragma unroll
        for (int ni = 0; ni < 8; ni++)
#pragma unroll
            for (int r = 0; r < 4; r++) c[mi][ni][r] = 0.0f;
#pragma unroll
    for (int kt = 0; kt < 2; kt++)
#pragma unroll
        for (int k8 = 0; k8 < 32; k8 += 8) {
            uint32_t a[2][4];
#pragma unroll
            for (int mi = 0; mi < 2; mi++) {
                int r0 = warp_m + mi * 16 + g;
                a[mi][0] = __float_as_uint(As[kt][r0][k8 + tg]);
                a[mi][1] = __float_as_uint(As[kt][r0 + 8][k8 + tg]);
                a[mi][2] = __float_as_uint(As[kt][r0][k8 + tg + 4]);
                a[mi][3] = __float_as_uint(As[kt][r0 + 8][k8 + tg + 4]);
            }
            uint32_t b[8][2];
#pragma unroll
            for (int ni = 0; ni < 8; ni++) {
                b[ni][0] = __float_as_uint(Bs[kt][k8 + tg][ni * 8 + g]);
                b[ni][1] = __float_as_uint(Bs[kt][k8 + tg + 4][ni * 8 + g]);
            }
#pragma unroll
            for (int mi = 0; mi < 2; mi++)
#pragma unroll
                for (int ni = 0; ni < 8; ni++)
                    mma_tf32(c[mi][ni], a[mi], b[ni]);
        }
#pragma unroll
    for (int mi = 0; mi < 2; mi++)
#pragma unroll
        for (int rr = 0; rr < 2; rr++) {
            int m = m0 + warp_m + mi * 16 + g + rr * 8;
#pragma unroll
            for (int ni = 0; ni < 8; ni++) {
                int n = ni * 8 + tg * 2;
                *(float2*)&t2[(size_t)m * 64 + n] =
                    make_float2(c[mi][ni][rr * 2 + 0], c[mi][ni][rr * 2 + 1]);
            }
        }
}

// ---------------- rbf coupling + transpose (fast math) ----------------
__device__ __forceinline__ float exp_neg_04(float dist) {
    float t  = dist * -0.5770780163555852f;
    float fn = floorf(t);
    float fr = t - fn;
    float p  = 1.5403530e-4f;
    p = fmaf(p, fr, 1.33335581e-3f);
    p = fmaf(p, fr, 9.61812911e-3f);
    p = fmaf(p, fr, 5.55041087e-2f);
    p = fmaf(p, fr, 2.40226507e-1f);
    p = fmaf(p, fr, 6.93147181e-1f);
    p = fmaf(p, fr, 1.0f);
    int n = (int)fn;
    n = n < -126 ? -126 : n;
    return p * __int_as_float((n + 127) << 23);
}

__global__ void rbf_kernel(const float* __restrict__ vert, const float* __restrict__ gp,
                           float* __restrict__ rbf, float* __restrict__ rbfT)
{
    __shared__ float tile[32][33];
    int tx = threadIdx.x, ty = threadIdx.y;
    int g = blockIdx.x * 32 + tx;
    int v = blockIdx.y * 32 + ty;
    float vx = vert[v * 3], vy = vert[v * 3 + 1], vz = vert[v * 3 + 2];
    float gx = gp[g * 3],  gy = gp[g * 3 + 1],  gz = gp[g * 3 + 2];
    float dx = vx - gx, dy = vy - gy, dz = vz - gz;
    float d2 = fmaf(dx, dx, fmaf(dy, dy, dz * dz));
    d2 = fmaxf(d2, 1e-24f);
    float rs;
    asm("rsqrt.approx.f32 %0, %1;" : "=f"(rs) : "f"(d2));
    float r = exp_neg_04(d2 * rs);
    rbf[(size_t)v * NG + g] = r;
    tile[ty][tx] = r;
    __syncthreads();
    int g2 = blockIdx.x * 32 + ty;
    int v2 = blockIdx.y * 32 + tx;
    rbfT[(size_t)g2 * NV + v2] = tile[tx][ty];
}

__global__ void transpose_kernel(const float* __restrict__ in, float* __restrict__ out)
{
    __shared__ float t[32][33];
    int x = blockIdx.x * 32 + threadIdx.x;
    int y = blockIdx.y * 32 + threadIdx.y;
    t[threadIdx.y][threadIdx.x] = in[(size_t)y * 128 + x];
    __syncthreads();
    int ox = blockIdx.y * 32 + threadIdx.x;
    int oy = blockIdx.x * 32 + threadIdx.y;
    out[(size_t)oy * NV + ox] = t[threadIdx.x][threadIdx.y];
}

__global__ void wcat_kernel(const float* __restrict__ are, const float* __restrict__ aim,
                            float* __restrict__ W)
{
    int gid = blockIdx.x * 256 + threadIdx.x;   // NBLK*KK*64
    int blk = gid >> 13;
    int r = gid & 8191;
    int k = r >> 6, d = r & 63;
    const float* a_re = are + blk * 64 * 64;
    const float* a_im = aim + blk * 64 * 64;
    float wre, wim;
    if (k < 64) { wre = a_re[k * 64 + d];         wim = a_im[k * 64 + d]; }
    else        { wre = -a_im[(k - 64) * 64 + d]; wim = a_re[(k - 64) * 64 + d]; }
    float* Wb = W + blk * 2 * KK * 64;
    Wb[r]           = wre;
    Wb[KK * 64 + r] = wim;
}

// ---------------- GCN CSR build ----------------
__global__ void deg_kernel(const int* __restrict__ dst, float* __restrict__ deg)
{
    int e = blockIdx.x * 256 + threadIdx.x;
    atomicAdd(&deg[dst[e]], 1.0f);
}
__global__ void dinv_kernel(const float* __restrict__ deg, float* __restrict__ dinv)
{
    int i = blockIdx.x * 256 + threadIdx.x;
    dinv[i] = rsqrtf(deg[i] + 1.0f);
}
__global__ __launch_bounds__(1024) void scan_kernel(const float* __restrict__ deg,
                                                    int* __restrict__ rowptr,
                                                    int* __restrict__ cursor)
{
    __shared__ int p[1024];
    int t = threadIdx.x;
    int d0 = (int)deg[2 * t], d1 = (int)deg[2 * t + 1];
    p[t] = d0 + d1;
    __syncthreads();
    for (int off = 1; off < 1024; off <<= 1) {
        int v = p[t];
        if (t >= off) v += p[t - off];
        __syncthreads();
        p[t] = v;
        __syncthreads();
    }
    int excl = (t == 0) ? 0 : p[t - 1];
    rowptr[2 * t]     = excl;
    rowptr[2 * t + 1] = excl + d0;
    if (t == 1023) rowptr[2048] = p[1023];
    cursor[2 * t] = 0;
    cursor[2 * t + 1] = 0;
}
__global__ void scatter_kernel(const int* __restrict__ src, const int* __restrict__ dst,
                               const int* __restrict__ rowptr, int* __restrict__ cursor,
                               int* __restrict__ srcs)
{
    int e = blockIdx.x * 256 + threadIdx.x;
    int s = src[e], t = dst[e];
    int pos = rowptr[t] + atomicAdd(&cursor[t], 1);
    srcs[pos] = s;
}
__global__ void csr_agg_kernel(const float* __restrict__ hw, const float* __restrict__ dinv,
                               const int* __restrict__ rowptr, const int* __restrict__ srcs,
                               float* __restrict__ agg)
{
    int gid = blockIdx.x * 256 + threadIdx.x;   // NG*64
    int i = gid >> 6, d = gid & 63;
    float di = dinv[i];
    float acc = hw[i * 64 + d] * di;
    int r1 = rowptr[i + 1];
    for (int r = rowptr[i]; r < r1; r++) {
        int s = srcs[r];
        acc += hw[s * 64 + d] * dinv[s];
    }
    agg[gid] = acc * di;
}

// ---------------- head / tail ----------------
__global__ void lin1_kernel(const float* __restrict__ sx, const float* __restrict__ w,
                            const float* __restrict__ b, float* __restrict__ y)
{
    int gid = blockIdx.x * 256 + threadIdx.x;   // NV*64
    int v = gid >> 6, d = gid & 63;
    float acc = b[d];
#pragma unroll
    for (int j = 0; j < 5; j++) acc += sx[v * 5 + j] * w[j * 64 + d];
    y[gid] = acc;
}

__global__ void out_kernel(const float* __restrict__ y, const float* __restrict__ w,
                           const float* __restrict__ b, float* __restrict__ out)
{
    int gid = blockIdx.x * 256 + threadIdx.x;   // NV*8
    int v = gid >> 3, c = gid & 7;
    float acc = b[c];
#pragma unroll 8
    for (int d = 0; d < 64; d++) acc += y[v * 64 + d] * w[d * 8 + c];
    out[gid] = acc;
}

// ---------------- host ----------------
static inline Sl sl1(const float* A, float* C, int ldc) {
    Sl s; for (int i = 0; i < 4; i++) { s.A[i] = A; s.C[i] = C; s.ldc[i] = ldc; }
    return s;
}

extern "C" void kernel_launch(void* const* d_in, const int* in_sizes, int n_in,
                              void* d_out, int out_size)
{
    static bool inited = false;
    static float *p_rbf, *p_rbfT, *p_xd, *p_xout, *p_y, *p_cat, *p_b2,
                 *p_sg, *p_W, *p_GE, *p_eT, *p_hw, *p_agg, *p_agg2, *p_deg, *p_dinv;
    static int *p_rowptr, *p_cursor, *p_srcs;
    if (!inited) {
        cudaGetSymbolAddress((void**)&p_rbf,  g_rbf);
        cudaGetSymbolAddress((void**)&p_rbfT, g_rbfT);
        cudaGetSymbolAddress((void**)&p_xd,   g_xd);
        cudaGetSymbolAddress((void**)&p_xout, g_xout);
        cudaGetSymbolAddress((void**)&p_y,    g_y);
        cudaGetSymbolAddress((void**)&p_cat,  g_cat);
        cudaGetSymbolAddress((void**)&p_b2,   g_b2);
        cudaGetSymbolAddress((void**)&p_sg,   g_sg);
        cudaGetSymbolAddress((void**)&p_W,    g_W);
        cudaGetSymbolAddress((void**)&p_GE,   g_GE);
        cudaGetSymbolAddress((void**)&p_eT,   g_eT);
        cudaGetSymbolAddress((void**)&p_hw,   g_hw);
        cudaGetSymbolAddress((void**)&p_agg,  g_agg);
        cudaGetSymbolAddress((void**)&p_agg2, g_agg2);
        cudaGetSymbolAddress((void**)&p_deg,  g_deg);
        cudaGetSymbolAddress((void**)&p_dinv, g_dinv);
        cudaGetSymbolAddress((void**)&p_rowptr, g_rowptr);
        cudaGetSymbolAddress((void**)&p_cursor, g_cursor);
        cudaGetSymbolAddress((void**)&p_srcs,   g_srcs);
        inited = true;
    }
    float* p_xs = p_sg;
    float* p_gx = p_sg + KK * 64;

    const float* surf_x    = (const float*)d_in[0];
    const float* mass      = (const float*)d_in[1];
    const float* evals     = (const float*)d_in[2];
    const float* evecs     = (const float*)d_in[3];
    const float* gradX     = (const float*)d_in[4];
    const float* gradY     = (const float*)d_in[5];
    const float* vertices  = (const float*)d_in[6];
    const float* graph_pos = (const float*)d_in[8];
    const float* lin1_w    = (const float*)d_in[9];
    const float* lin1_b    = (const float*)d_in[10];
    const float* last_w    = (const float*)d_in[13];
    const float* last_b    = (const float*)d_in[14];
    const float* diff_time = (const float*)d_in[15];
    const float* A_re      = (const float*)d_in[16];
    const float* A_im      = (const float*)d_in[17];
    const float* mlp_w0    = (const float*)d_in[18];
    const float* mlp_b0    = (const float*)d_in[19];
    const float* mlp_w1    = (const float*)d_in[20];
    const float* mlp_b1    = (const float*)d_in[21];
    const float* mlp_w2    = (const float*)d_in[22];
    const float* mlp_b2    = (const float*)d_in[23];
    const float* gcn_w1    = (const float*)d_in[24];
    const float* gcn_b1    = (const float*)d_in[25];
    const float* gcn_w2    = (const float*)d_in[26];
    const float* gcn_b2    = (const float*)d_in[27];
    const int*   eidx      = (const int*)d_in[28];
    const int*   e_src     = eidx;
    const int*   e_dst     = eidx + EE;
    float* out = (float*)d_out;

    // ---- setup (serial) ----
    rbf_kernel<<<dim3(NG / 32, NV / 32), dim3(32, 32)>>>(vertices, graph_pos, p_rbf, p_rbfT);

    cudaMemsetAsync(p_deg, 0, NG * sizeof(float));
    deg_kernel<<<EE / 256, 256>>>(e_dst, p_deg);
    dinv_kernel<<<NG / 256, 256>>>(p_deg, p_dinv);
    scan_kernel<<<1, 1024>>>(p_deg, p_rowptr, p_cursor);
    scatter_kernel<<<EE / 256, 256>>>(e_src, e_dst, p_rowptr, p_cursor, p_srcs);

    transpose_kernel<<<dim3(KK / 32, NV / 32), dim3(32, 32)>>>(evecs, p_eT);
    lin1_kernel<<<NV * 64 / 256, 256>>>(surf_x, lin1_w, lin1_b, p_y);       // -> y[0]
    wcat_kernel<<<NBLK * KK * 64 / 256, 256>>>(A_re, A_im, p_W);            // all blocks

    // GE = [gradX@evecs(lo) ; gradX@evecs(hi) ; gradY@evecs(lo) ; gradY@evecs(hi)]
    {
        Sl s;
        s.A[0] = gradX; s.A[1] = gradX; s.A[2] = gradY; s.A[3] = gradY;
        s.C[0] = p_GE;            s.C[1] = p_GE + 64;
        s.C[2] = p_GE + NV * 128; s.C[3] = p_GE + NV * 128 + 64;
        s.ldc[0] = s.ldc[1] = s.ldc[2] = s.ldc[3] = 128;
        gemm64<<<dim3(NV / 128, 1, 4), 128>>>(
            s, NV, evecs, evecs + 64, 128, NV, NV,
            nullptr, nullptr, 0, 0, nullptr, nullptr, nullptr, nullptr, nullptr);
    }

    for (int blk = 0; blk < NBLK; blk++) {
        const float* t   = diff_time + blk * 64;
        const float* w0  = mlp_w0 + blk * 192 * 64;
        const float* b0  = mlp_b0 + blk * 64;
        const float* w1  = mlp_w1 + blk * 64 * 64;
        const float* b1  = mlp_b1 + blk * 64;
        const float* w2  = mlp_w2 + blk * 64 * 64;
        const float* b2m = mlp_b2 + blk * 64;
        const float* gw1 = gcn_w1 + blk * 64 * 64;
        const float* gb1 = gcn_b1 + blk * 64;
        const float* gw2 = gcn_w2 + blk * 64 * 64;
        const float* gb2 = gcn_b2 + blk * 64;
        const float* Wb  = p_W + blk * 2 * KK * 64;
        float* yA = p_y + (blk & 1) * NV * 64;
        float* yB = p_y + (1 - (blk & 1)) * NV * 64;

        // zero split-K targets
        cudaMemsetAsync(yB, 0, NV * 64 * sizeof(float));
        cudaMemsetAsync(p_sg, 0, (KK * 64 + NG * 64) * sizeof(float));

        // xs = evecsT @ (mass .* x)  (mass fused via bscale; split-K 16)
        gemm64<<<dim3(1, 16, 1), 128>>>(
            sl1(p_eT, p_xs, 64), NV, yA, yA, 64, NV, NV / 16,
            nullptr, nullptr, 0, 0, nullptr, nullptr, mass, nullptr, nullptr);

        // [x_diff ; gX ; gY] = [evecs ; GE_X ; GE_Y] @ (coef * xs)  (exp fused)
        {
            Sl s;
            s.A[0] = evecs;          s.C[0] = p_xd;       s.ldc[0] = 64;
            s.A[1] = p_GE;           s.C[1] = p_cat;      s.ldc[1] = 128;
            s.A[2] = p_GE + NV*128;  s.C[2] = p_cat + 64; s.ldc[2] = 128;
            s.A[3] = evecs;          s.C[3] = p_xd;       s.ldc[3] = 64;
            gemm64<<<dim3(NV / 128, 1, 3), 128>>>(
                s, 128, p_xs, p_xs, 64, KK, KK,
                nullptr, nullptr, 0, 0, nullptr, nullptr, nullptr, evals, t);
        }

        // b_re|b_im = cat @ [Wre|Wim]
        {
            Sl s;
            s.A[0] = p_cat; s.C[0] = p_b2;           s.ldc[0] = 64;
            s.A[1] = p_cat; s.C[1] = p_b2 + NV * 64; s.ldc[1] = 64;
            s.A[2] = p_cat; s.C[2] = p_b2;           s.ldc[2] = 64;
            s.A[3] = p_cat; s.C[3] = p_b2;           s.ldc[3] = 64;
            gemm64<<<dim3(NV / 128, 1, 2), 128>>>(
                s, 128, Wb, Wb + KK * 64, 64, KK, KK,
                nullptr, nullptr, 0, 0, nullptr, nullptr, nullptr, nullptr, nullptr);
        }

        // fused MLP (gfeat computed in-loader) + residual -> xout
        mlp_kernel<<<NV / 128, 128>>>(yA, p_xd, p_xout, p_cat, p_b2,
                                      w0, b0, w1, b1, w2, b2m);

        // gx = rbf^T @ x' (split-K 8)
        gemm64<<<dim3(NG / 128, 8, 1), 128>>>(
            sl1(p_rbfT, p_gx, 64), NV, p_xout, p_xout, 64, NV, NV / 8,
            nullptr, nullptr, 0, 0, nullptr, nullptr, nullptr, nullptr, nullptr);

        // GCN: t1 = A_hat*gx (wide csr_agg) ; hw = relu(t1@W1+b1)@W2 ; agg2 = A_hat*hw
        csr_agg_kernel<<<NG * 64 / 256, 256>>>(p_gx, p_dinv, p_rowptr, p_srcs, p_agg);
        gcn_kernel<<<NG / 128, 128>>>(p_agg, p_hw, gw1, gb1, gw2);
        csr_agg_kernel<<<NG * 64 / 256, 256>>>(p_hw, p_dinv, p_rowptr, p_srcs, p_agg2);

        // diff_x = rbf @ (agg2 + gb2)  (B-loader bias fused; split-K 4) -> yB
        gemm64<<<dim3(NV / 128, 4, 1), 128>>>(
            sl1(p_rbf, yB, 64), NG, p_agg2, p_agg2, 64, NG, NG / 4,
            nullptr, nullptr, 0, 0, nullptr, gb2, nullptr, nullptr, nullptr);
    }

    // final: out = y[0] @ last_w + last_b
    out_kernel<<<(NV * 8) / 256, 256>>>(p_y, last_w, last_b, out);
}

// round 15
// speedup vs baseline: 1.2745x; 1.0946x over previous
#include <cuda_runtime.h>
#include <math.h>
#include <stdint.h>

#define NV 4096
#define NG 2048
#define KK 128
#define NBLK 4
#define EE 32768

// ---------------- scratch ----------------
__device__ float g_rbf [NV * NG];
__device__ float g_rbfT[NG * NV];
__device__ float g_f   [NV * 128];       // [NV, 128] = [x | x_diff]
__device__ float g_y   [2 * NV * 64];    // double-buffered diff_x
__device__ float g_cat [NV * 128];       // [gX | gY]
__device__ float g_b2  [2 * NV * 64];    // [b_re ; b_im]
__device__ float g_mx  [NV * 64];        // mass * x
__device__ float g_xs  [KK * 64];
__device__ float g_W   [NBLK * 2 * KK * 64];  // per-block [Wre ; Wim]
__device__ float g_GE  [2 * NV * 128];   // [gradX@evecs ; gradY@evecs]
__device__ float g_eT  [KK * NV];        // evecs^T
__device__ float g_gx  [NG * 64];
__device__ float g_hw  [NG * 64];
__device__ float g_agg [NG * 64];
__device__ float g_agg2[NG * 64];
__device__ float g_deg [NG];
__device__ float g_dinv[NG];
__device__ int   g_rowptr[NG + 1];
__device__ int   g_cursor[NG];
__device__ int   g_srcs[EE];

// ---------------- tf32 helpers ----------------
__device__ __forceinline__ float tf32r(float x) {
    uint32_t r;
    asm("cvt.rna.tf32.f32 %0, %1;" : "=r"(r) : "f"(x));
    return __uint_as_float(r);
}
__device__ __forceinline__ void mma_tf32(float* c, const uint32_t* a, const uint32_t* b) {
    asm volatile(
        "mma.sync.aligned.m16n8k8.row.col.f32.tf32.tf32.f32 "
        "{%0,%1,%2,%3}, {%4,%5,%6,%7}, {%8,%9}, {%0,%1,%2,%3};"
        : "+f"(c[0]), "+f"(c[1]), "+f"(c[2]), "+f"(c[3])
        : "r"(a[0]), "r"(a[1]), "r"(a[2]), "r"(a[3]), "r"(b[0]), "r"(b[1]));
}

// per-z slice descriptors
struct Sl {
    const float* A[4];
    float*       C[4];
    int          ldc[4];
};

// ---------------- generic N=64 GEMM (tf32 MMA), BM=128, 128 threads -----------
__global__ __launch_bounds__(128) void gemm64(
    Sl sl, int lda,
    const float* __restrict__ B0, const float* __restrict__ B1, int ldb,
    int KB, int kchunk,
    const float* __restrict__ bias,
    const float* __restrict__ resid, int ldr, int act,
    const float* __restrict__ abias, const float* __restrict__ bbias,
    const float* __restrict__ bexp_ev, const float* __restrict__ bexp_t)
{
    __shared__ float As[2][128][36];
    __shared__ float Bs[2][32][72];

    const int z = blockIdx.z;
    const float* A = sl.A[z];
    const float* B = (z & 1) ? B1 : B0;
    float* C = sl.C[z];
    const int ldc = sl.ldc[z];

    const int tid    = threadIdx.x;
    const int warp   = tid >> 5;
    const int lane   = tid & 31;
    const int g      = lane >> 2;
    const int tg     = lane & 3;
    const int m0     = blockIdx.x * 128;
    const int warp_m = warp * 32;
    const int kbeg   = blockIdx.y * kchunk;
    const int ntile  = kchunk >> 5;

    const int am = tid >> 3;
    const int ak = (tid & 7) * 4;
    const int bk = tid >> 4;
    const int bn = (tid & 15) * 4;

    float4 bb = make_float4(0.f, 0.f, 0.f, 0.f);
    if (bbias) bb = *(const float4*)(bbias + bn);
    float4 tc = make_float4(0.f, 0.f, 0.f, 0.f);
    if (bexp_t) {
        tc = *(const float4*)(bexp_t + bn);
        tc.x = fmaxf(tc.x, 1e-8f); tc.y = fmaxf(tc.y, 1e-8f);
        tc.z = fmaxf(tc.z, 1e-8f); tc.w = fmaxf(tc.w, 1e-8f);
    }

    float4 rA[8], rB[4];
    float c[2][8][4];
#pragma unroll
    for (int mi = 0; mi < 2; mi++)
#pragma unroll
        for (int ni = 0; ni < 8; ni++)
#pragma unroll
            for (int r = 0; r < 4; r++) c[mi][ni][r] = 0.0f;

    {   // prologue tile 0
        const float* ap = A + (size_t)(m0 + am) * lda + kbeg + ak;
        const float* bp = B + (size_t)(kbeg + bk) * ldb + bn;
#pragma unroll
        for (int i = 0; i < 8; i++) rA[i] = *(const float4*)(ap + (size_t)(i * 16) * lda);
#pragma unroll
        for (int i = 0; i < 4; i++) rB[i] = *(const float4*)(bp + (size_t)(i * 8) * ldb);
    }

    int buf = 0;
    for (int it = 0; it < ntile; it++) {
        const int kst = kbeg + it * 32;
#pragma unroll
        for (int i = 0; i < 8; i++) {
            float4 v = rA[i];
            if (abias) {
                float4 ab = *(const float4*)(abias + kst + ak);
                v.x = fmaxf(v.x + ab.x, 0.f); v.y = fmaxf(v.y + ab.y, 0.f);
                v.z = fmaxf(v.z + ab.z, 0.f); v.w = fmaxf(v.w + ab.w, 0.f);
            }
            v.x = tf32r(v.x); v.y = tf32r(v.y); v.z = tf32r(v.z); v.w = tf32r(v.w);
            *(float4*)&As[buf][am + i * 16][ak] = v;
        }
#pragma unroll
        for (int i = 0; i < 4; i++) {
            float4 v = rB[i];
            if (bexp_ev) {
                float ev = bexp_ev[kst + bk + i * 8];
                v.x *= __expf(-ev * tc.x); v.y *= __expf(-ev * tc.y);
                v.z *= __expf(-ev * tc.z); v.w *= __expf(-ev * tc.w);
            }
            v.x += bb.x; v.y += bb.y; v.z += bb.z; v.w += bb.w;
            v.x = tf32r(v.x); v.y = tf32r(v.y); v.z = tf32r(v.z); v.w = tf32r(v.w);
            *(float4*)&Bs[buf][bk + i * 8][bn] = v;
        }
        __syncthreads();

        if (it + 1 < ntile) {
            int kb = kbeg + (it + 1) * 32;
            const float* ap = A + (size_t)(m0 + am) * lda + kb + ak;
            const float* bp = B + (size_t)(kb + bk) * ldb + bn;
#pragma unroll
            for (int i = 0; i < 8; i++) rA[i] = *(const float4*)(ap + (size_t)(i * 16) * lda);
#pragma unroll
            for (int i = 0; i < 4; i++) rB[i] = *(const float4*)(bp + (size_t)(i * 8) * ldb);
        }

#pragma unroll
        for (int k8 = 0; k8 < 32; k8 += 8) {
            uint32_t a[2][4];
#pragma unroll
            for (int mi = 0; mi < 2; mi++) {
                int r0 = warp_m + mi * 16 + g;
                a[mi][0] = __float_as_uint(As[buf][r0][k8 + tg]);
                a[mi][1] = __float_as_uint(As[buf][r0 + 8][k8 + tg]);
                a[mi][2] = __float_as_uint(As[buf][r0][k8 + tg + 4]);
                a[mi][3] = __float_as_uint(As[buf][r0 + 8][k8 + tg + 4]);
            }
            uint32_t b[8][2];
#pragma unroll
            for (int ni = 0; ni < 8; ni++) {
                b[ni][0] = __float_as_uint(Bs[buf][k8 + tg][ni * 8 + g]);
                b[ni][1] = __float_as_uint(Bs[buf][k8 + tg + 4][ni * 8 + g]);
            }
#pragma unroll
            for (int mi = 0; mi < 2; mi++)
#pragma unroll
                for (int ni = 0; ni < 8; ni++)
                    mma_tf32(c[mi][ni], a[mi], b[ni]);
        }
        buf ^= 1;
    }

    const bool split = (gridDim.y > 1);
#pragma unroll
    for (int mi = 0; mi < 2; mi++) {
#pragma unroll
        for (int rr = 0; rr < 2; rr++) {
            int m = m0 + warp_m + mi * 16 + g + rr * 8;
#pragma unroll
            for (int ni = 0; ni < 8; ni++) {
                int n = ni * 8 + tg * 2;
                float v0 = c[mi][ni][rr * 2 + 0];
                float v1 = c[mi][ni][rr * 2 + 1];
                if (split) {
                    atomicAdd(&C[(size_t)m * ldc + n],     v0);
                    atomicAdd(&C[(size_t)m * ldc + n + 1], v1);
                } else {
                    if (bias)  { v0 += bias[n]; v1 += bias[n + 1]; }
                    if (resid) { v0 += resid[(size_t)m * ldr + n];
                                 v1 += resid[(size_t)m * ldr + n + 1]; }
                    if (act)   { v0 = fmaxf(v0, 0.0f); v1 = fmaxf(v1, 0.0f); }
                    *(float2*)&C[(size_t)m * ldc + n] = make_float2(v0, v1);
                }
            }
        }
    }
}

// ---------------- fused 3-layer MLP (one launch) -------------------------------
__device__ __forceinline__ float4 load_f_ext(
    const float* __restrict__ f, const float* __restrict__ cat,
    const float* __restrict__ b2, int m, int k)
{
    if (k < 128) return *(const float4*)(f + (size_t)m * 128 + k);
    int kk = k - 128;
    float4 gx = *(const float4*)(cat + (size_t)m * 128 + kk);
    float4 gy = *(const float4*)(cat + (size_t)m * 128 + 64 + kk);
    float4 br = *(const float4*)(b2 + (size_t)m * 64 + kk);
    float4 bi = *(const float4*)(b2 + (size_t)(NV * 64) + (size_t)m * 64 + kk);
    float4 r;
    r.x = tanhf(gx.x * br.x + gy.x * bi.x);
    r.y = tanhf(gx.y * br.y + gy.y * bi.y);
    r.z = tanhf(gx.z * br.z + gy.z * bi.z);
    r.w = tanhf(gx.w * br.w + gy.w * bi.w);
    return r;
}

__global__ __launch_bounds__(128) void mlp_kernel(
    float* __restrict__ f,                         // [NV,128]; writes cols 0:64
    const float* __restrict__ cat, const float* __restrict__ b2v,
    const float* __restrict__ w0, const float* __restrict__ b0,
    const float* __restrict__ w1, const float* __restrict__ b1,
    const float* __restrict__ w2, const float* __restrict__ b2)
{
    __shared__ float As[2][128][36];
    __shared__ float Bs[2][32][72];

    const int tid = threadIdx.x, warp = tid >> 5, lane = tid & 31;
    const int g = lane >> 2, tg = lane & 3;
    const int m0 = blockIdx.x * 128, warp_m = warp * 32;
    const int am = tid >> 3, ak = (tid & 7) * 4;
    const int bk = tid >> 4, bn = (tid & 15) * 4;

    float c[2][8][4];
#pragma unroll
    for (int mi = 0; mi < 2; mi++)
#pragma unroll
        for (int ni = 0; ni < 8; ni++)
#pragma unroll
            for (int r = 0; r < 4; r++) c[mi][ni][r] = 0.0f;

    // ---- phase 1: h1 = relu(fext @ w0 + b0), K=192 streamed (6 tiles) ----
    float4 rA[8], rB[4];
    {
#pragma unroll
        for (int i = 0; i < 8; i++)
            rA[i] = load_f_ext(f, cat, b2v, m0 + am + i * 16, ak);
        const float* bp = w0 + (size_t)bk * 64 + bn;
#pragma unroll
        for (int i = 0; i < 4; i++) rB[i] = *(const float4*)(bp + (size_t)(i * 8) * 64);
    }
    int buf = 0;
    for (int it = 0; it < 6; it++) {
#pragma unroll
        for (int i = 0; i < 8; i++) {
            float4 v = rA[i];
            v.x = tf32r(v.x); v.y = tf32r(v.y); v.z = tf32r(v.z); v.w = tf32r(v.w);
            *(float4*)&As[buf][am + i * 16][ak] = v;
        }
#pragma unroll
        for (int i = 0; i < 4; i++) {
            float4 v = rB[i];
            v.x = tf32r(v.x); v.y = tf32r(v.y); v.z = tf32r(v.z); v.w = tf32r(v.w);
            *(float4*)&Bs[buf][bk + i * 8][bn] = v;
        }
        __syncthreads();
        if (it + 1 < 6) {
            int kb = (it + 1) * 32;
#pragma unroll
            for (int i = 0; i < 8; i++)
                rA[i] = load_f_ext(f, cat, b2v, m0 + am + i * 16, kb + ak);
            const float* bp = w0 + (size_t)(kb + bk) * 64 + bn;
#pragma unroll
            for (int i = 0; i < 4; i++) rB[i] = *(const float4*)(bp + (size_t)(i * 8) * 64);
        }
#pragma unroll
        for (int k8 = 0; k8 < 32; k8 += 8) {
            uint32_t a[2][4];
#pragma unroll
            for (int mi = 0; mi < 2; mi++) {
                int r0 = warp_m + mi * 16 + g;
                a[mi][0] = __float_as_uint(As[buf][r0][k8 + tg]);
                a[mi][1] = __float_as_uint(As[buf][r0 + 8][k8 + tg]);
                a[mi][2] = __float_as_uint(As[buf][r0][k8 + tg + 4]);
                a[mi][3] = __float_as_uint(As[buf][r0 + 8][k8 + tg + 4]);
            }
            uint32_t b[8][2];
#pragma unroll
            for (int ni = 0; ni < 8; ni++) {
                b[ni][0] = __float_as_uint(Bs[buf][k8 + tg][ni * 8 + g]);
                b[ni][1] = __float_as_uint(Bs[buf][k8 + tg + 4][ni * 8 + g]);
            }
#pragma unroll
            for (int mi = 0; mi < 2; mi++)
#pragma unroll
                for (int ni = 0; ni < 8; ni++)
                    mma_tf32(c[mi][ni], a[mi], b[ni]);
        }
        buf ^= 1;
    }
    // h1 -> As (own-warp rows)
#pragma unroll
    for (int mi = 0; mi < 2; mi++)
#pragma unroll
        for (int rr = 0; rr < 2; rr++) {
            int ml = warp_m + mi * 16 + g + rr * 8;
#pragma unroll
            for (int ni = 0; ni < 8; ni++) {
                int n = ni * 8 + tg * 2;
                float v0 = fmaxf(c[mi][ni][rr * 2 + 0] + b0[n], 0.f);
                float v1 = fmaxf(c[mi][ni][rr * 2 + 1] + b0[n + 1], 0.f);
                *(float2*)&As[n >> 5][ml][n & 31] = make_float2(tf32r(v0), tf32r(v1));
            }
        }
    __syncthreads();

    // ---- phase 2: h2 = relu(h1 @ w1 + b1) ----
#pragma unroll
    for (int t = 0; t < 2; t++)
#pragma unroll
        for (int i = 0; i < 4; i++) {
            float4 v = *(const float4*)(w1 + (size_t)(t * 32 + bk + i * 8) * 64 + bn);
            v.x = tf32r(v.x); v.y = tf32r(v.y); v.z = tf32r(v.z); v.w = tf32r(v.w);
            *(float4*)&Bs[t][bk + i * 8][bn] = v;
        }
    __syncthreads();
#pragma unroll
    for (int mi = 0; mi < 2; mi++)
#pragma unroll
        for (int ni = 0; ni < 8; ni++)
#pragma unroll
            for (int r = 0; r < 4; r++) c[mi][ni][r] = 0.0f;
#pragma unroll
    for (int kt = 0; kt < 2; kt++)
#pragma unroll
        for (int k8 = 0; k8 < 32; k8 += 8) {
            uint32_t a[2][4];
#pragma unroll
            for (int mi = 0; mi < 2; mi++) {
                int r0 = warp_m + mi * 16 + g;
                a[mi][0] = __float_as_uint(As[kt][r0][k8 + tg]);
                a[mi][1] = __float_as_uint(As[kt][r0 + 8][k8 + tg]);
                a[mi][2] = __float_as_uint(As[kt][r0][k8 + tg + 4]);
                a[mi][3] = __float_as_uint(As[kt][r0 + 8][k8 + tg + 4]);
            }
            uint32_t b[8][2];
#pragma unroll
            for (int ni = 0; ni < 8; ni++) {
                b[ni][0] = __float_as_uint(Bs[kt][k8 + tg][ni * 8 + g]);
                b[ni][1] = __float_as_uint(Bs[kt][k8 + tg + 4][ni * 8 + g]);
            }
#pragma unroll
            for (int mi = 0; mi < 2; mi++)
#pragma unroll
                for (int ni = 0; ni < 8; ni++)
                    mma_tf32(c[mi][ni], a[mi], b[ni]);
        }
#pragma unroll
    for (int mi = 0; mi < 2; mi++)
#pragma unroll
        for (int rr = 0; rr < 2; rr++) {
            int ml = warp_m + mi * 16 + g + rr * 8;
#pragma unroll
            for (int ni = 0; ni < 8; ni++) {
                int n = ni * 8 + tg * 2;
                float v0 = fmaxf(c[mi][ni][rr * 2 + 0] + b1[n], 0.f);
                float v1 = fmaxf(c[mi][ni][rr * 2 + 1] + b1[n + 1], 0.f);
                *(float2*)&As[n >> 5][ml][n & 31] = make_float2(tf32r(v0), tf32r(v1));
            }
        }
    __syncthreads();

    // ---- phase 3: x' = h2 @ w2 + b2 + x ----
#pragma unroll
    for (int t = 0; t < 2; t++)
#pragma unroll
        for (int i = 0; i < 4; i++) {
            float4 v = *(const float4*)(w2 + (size_t)(t * 32 + bk + i * 8) * 64 + bn);
            v.x = tf32r(v.x); v.y = tf32r(v.y); v.z = tf32r(v.z); v.w = tf32r(v.w);
            *(float4*)&Bs[t][bk + i * 8][bn] = v;
        }
    __syncthreads();
#pragma unroll
    for (int mi = 0; mi < 2; mi++)
#pragma unroll
        for (int ni = 0; ni < 8; ni++)
#pragma unroll
            for (int r = 0; r < 4; r++) c[mi][ni][r] = 0.0f;
#pragma unroll
    for (int kt = 0; kt < 2; kt++)
#pragma unroll
        for (int k8 = 0; k8 < 32; k8 += 8) {
            uint32_t a[2][4];
#pragma unroll
            for (int mi = 0; mi < 2; mi++) {
                int r0 = warp_m + mi * 16 + g;
                a[mi][0] = __float_as_uint(As[kt][r0][k8 + tg]);
                a[mi][1] = __float_as_uint(As[kt][r0 + 8][k8 + tg]);
                a[mi][2] = __float_as_uint(As[kt][r0][k8 + tg + 4]);
                a[mi][3] = __float_as_uint(As[kt][r0 + 8][k8 + tg + 4]);
            }
            uint32_t b[8][2];
#pragma unroll
            for (int ni = 0; ni < 8; ni++) {
                b[ni][0] = __float_as_uint(Bs[kt][k8 + tg][ni * 8 + g]);
                b[ni][1] = __float_as_uint(Bs[kt][k8 + tg + 4][ni * 8 + g]);
            }
#pragma unroll
            for (int mi = 0; mi < 2; mi++)
#pragma unroll
                for (int ni = 0; ni < 8; ni++)
                    mma_tf32(c[mi][ni], a[mi], b[ni]);
        }
#pragma unroll
    for (int mi = 0; mi < 2; mi++)
#pragma unroll
        for (int rr = 0; rr < 2; rr++) {
            int m = m0 + warp_m + mi * 16 + g + rr * 8;
#pragma unroll
            for (int ni = 0; ni < 8; ni++) {
                int n = ni * 8 + tg * 2;
                float v0 = c[mi][ni][rr * 2 + 0] + b2[n]     + f[(size_t)m * 128 + n];
                float v1 = c[mi][ni][rr * 2 + 1] + b2[n + 1] + f[(size_t)m * 128 + n + 1];
                *(float2*)&f[(size_t)m * 128 + n] = make_float2(v0, v1);
            }
        }
}

// ---------------- fused 2-layer GCN: t2 = (relu(t1@W1+b1))@W2 ----------------
__global__ __launch_bounds__(128) void gcn_kernel(
    const float* __restrict__ t1, float* __restrict__ t2,
    const float* __restrict__ W1, const float* __restrict__ bb1,
    const float* __restrict__ W2)
{
    __shared__ float As[2][128][36];
    __shared__ float Bs[2][32][72];
    float* Asf = &As[0][0][0];

    const int tid = threadIdx.x, warp = tid >> 5, lane = tid & 31;
    const int g = lane >> 2, tg = lane & 3;
    const int m0 = blockIdx.x * 128, warp_m = warp * 32;
    const int am = tid >> 3, ak = (tid & 7) * 4;
    const int bk = tid >> 4, bn = (tid & 15) * 4;

    // stage A = t1 (128x64), B = W1 (64x64)
#pragma unroll
    for (int b = 0; b < 2; b++)
#pragma unroll
        for (int i = 0; i < 8; i++) {
            float4 v = *(const float4*)(t1 + (size_t)(m0 + am + i * 16) * 64 + b * 32 + ak);
            v.x = tf32r(v.x); v.y = tf32r(v.y); v.z = tf32r(v.z); v.w = tf32r(v.w);
            *(float4*)&As[b][am + i * 16][ak] = v;
        }
#pragma unroll
    for (int i = 0; i < 8; i++) {
        int k = bk + i * 8;
        float4 v = *(const float4*)(W1 + (size_t)k * 64 + bn);
        v.x = tf32r(v.x); v.y = tf32r(v.y); v.z = tf32r(v.z); v.w = tf32r(v.w);
        *(float4*)&Bs[k >> 5][k & 31][bn] = v;
    }
    __syncthreads();

    float c[2][8][4];
#pragma unroll
    for (int mi = 0; mi < 2; mi++)
#pragma unroll
        for (int ni = 0; ni < 8; ni++)
#pragma unroll
            for (int r = 0; r < 4; r++) c[mi][ni][r] = 0.0f;
#pragma unroll
    for (int kt = 0; kt < 2; kt++)
#pragma unroll
        for (int k8 = 0; k8 < 32; k8 += 8) {
            uint32_t a[2][4];
#pragma unroll
            for (int mi = 0; mi < 2; mi++) {
                int r0 = warp_m + mi * 16 + g;
                a[mi][0] = __float_as_uint(As[kt][r0][k8 + tg]);
                a[mi][1] = __float_as_uint(As[kt][r0 + 8][k8 + tg]);
                a[mi][2] = __float_as_uint(As[kt][r0][k8 + tg + 4]);
                a[mi][3] = __float_as_uint(As[kt][r0 + 8][k8 + tg + 4]);
            }
            uint32_t b[8][2];
#pragma unroll
            for (int ni = 0; ni < 8; ni++) {
                b[ni][0] = __float_as_uint(Bs[kt][k8 + tg][ni * 8 + g]);
                b[ni][1] = __float_as_uint(Bs[kt][k8 + tg + 4][ni * 8 + g]);
            }
#pragma unroll
            for (int mi = 0; mi < 2; mi++)
#pragma unroll
                for (int ni = 0; ni < 8; ni++)
                    mma_tf32(c[mi][ni], a[mi], b[ni]);
        }
    // h = relu(c + b1) -> As (own-warp rows)
#pragma unroll
    for (int mi = 0; mi < 2; mi++)
#pragma unroll
        for (int rr = 0; rr < 2; rr++) {
            int ml = warp_m + mi * 16 + g + rr * 8;
#pragma unroll
            for (int ni = 0; ni < 8; ni++) {
                int n = ni * 8 + tg * 2;
                float v0 = fmaxf(c[mi][ni][rr * 2 + 0] + bb1[n], 0.f);
                float v1 = fmaxf(c[mi][ni][rr * 2 + 1] + bb1[n + 1], 0.f);
                int idx = (n >> 5) * 4608 + ml * 36 + (n & 31);
                Asf[idx]     = tf32r(v0);
                Asf[idx + 1] = tf32r(v1);
            }
        }
    __syncthreads();

    // stage B = W2
#pragma unroll
    for (int i = 0; i < 8; i++) {
        int k = bk + i * 8;
        float4 v = *(const float4*)(W2 + (size_t)k * 64 + bn);
        v.x = tf32r(v.x); v.y = tf32r(v.y); v.z = tf32r(v.z); v.w = tf32r(v.w);
        *(float4*)&Bs[k >> 5][k & 31][bn] = v;
    }
    __syncthreads();
#pragma unroll
    for (int mi = 0; mi < 2; mi++)
#pragma unroll
        for (int ni = 0; ni < 8; ni++)
#pragma unroll
            for (int r = 0; r < 4; r++) c[mi][ni][r] = 0.0f;
#pragma unroll
    for (int kt = 0; kt < 2; kt++)
#pragma unroll
        for (int k8 = 0; k8 < 32; k8 += 8) {
            uint32_t a[2][4];
#pragma unroll
            for (int mi = 0; mi < 2; mi++) {
                int r0 = warp_m + mi * 16 + g;
                a[mi][0] = __float_as_uint(As[kt][r0][k8 + tg]);
                a[mi][1] = __float_as_uint(As[kt][r0 + 8][k8 + tg]);
                a[mi][2] = __float_as_uint(As[kt][r0][k8 + tg + 4]);
                a[mi][3] = __float_as_uint(As[kt][r0 + 8][k8 + tg + 4]);
            }
            uint32_t b[8][2];
#pragma unroll
            for (int ni = 0; ni < 8; ni++) {
                b[ni][0] = __float_as_uint(Bs[kt][k8 + tg][ni * 8 + g]);
                b[ni][1] = __float_as_uint(Bs[kt][k8 + tg + 4][ni * 8 + g]);
            }
#pragma unroll
            for (int mi = 0; mi < 2; mi++)
#pragma unroll
                for (int ni = 0; ni < 8; ni++)
                    mma_tf32(c[mi][ni], a[mi], b[ni]);
        }
#pragma unroll
    for (int mi = 0; mi < 2; mi++)
#pragma unroll
        for (int rr = 0; rr < 2; rr++) {
            int m = m0 + warp_m + mi * 16 + g + rr * 8;
#pragma unroll
            for (int ni = 0; ni < 8; ni++) {
                int n = ni * 8 + tg * 2;
                *(float2*)&t2[(size_t)m * 64 + n] =
                    make_float2(c[mi][ni][rr * 2 + 0], c[mi][ni][rr * 2 + 1]);
            }
        }
}

// ---------------- rbf coupling + transpose (fast math) ----------------
__device__ __forceinline__ float exp_neg_04(float dist) {
    float t  = dist * -0.5770780163555852f;
    float fn = floorf(t);
    float fr = t - fn;
    float p  = 1.5403530e-4f;
    p = fmaf(p, fr, 1.33335581e-3f);
    p = fmaf(p, fr, 9.61812911e-3f);
    p = fmaf(p, fr, 5.55041087e-2f);
    p = fmaf(p, fr, 2.40226507e-1f);
    p = fmaf(p, fr, 6.93147181e-1f);
    p = fmaf(p, fr, 1.0f);
    int n = (int)fn;
    n = n < -126 ? -126 : n;
    return p * __int_as_float((n + 127) << 23);
}

__global__ void rbf_kernel(const float* __restrict__ vert, const float* __restrict__ gp,
                           float* __restrict__ rbf, float* __restrict__ rbfT)
{
    __shared__ float tile[32][33];
    int tx = threadIdx.x, ty = threadIdx.y;
    int g = blockIdx.x * 32 + tx;
    int v = blockIdx.y * 32 + ty;
    float vx = vert[v * 3], vy = vert[v * 3 + 1], vz = vert[v * 3 + 2];
    float gx = gp[g * 3],  gy = gp[g * 3 + 1],  gz = gp[g * 3 + 2];
    float dx = vx - gx, dy = vy - gy, dz = vz - gz;
    float d2 = fmaf(dx, dx, fmaf(dy, dy, dz * dz));
    d2 = fmaxf(d2, 1e-24f);
    float rs;
    asm("rsqrt.approx.f32 %0, %1;" : "=f"(rs) : "f"(d2));
    float r = exp_neg_04(d2 * rs);
    rbf[(size_t)v * NG + g] = r;
    tile[ty][tx] = r;
    __syncthreads();
    int g2 = blockIdx.x * 32 + ty;
    int v2 = blockIdx.y * 32 + tx;
    rbfT[(size_t)g2 * NV + v2] = tile[tx][ty];
}

__global__ void transpose_kernel(const float* __restrict__ in, float* __restrict__ out)
{
    __shared__ float t[32][33];
    int x = blockIdx.x * 32 + threadIdx.x;
    int y = blockIdx.y * 32 + threadIdx.y;
    t[threadIdx.y][threadIdx.x] = in[(size_t)y * 128 + x];
    __syncthreads();
    int ox = blockIdx.y * 32 + threadIdx.x;
    int oy = blockIdx.x * 32 + threadIdx.y;
    out[(size_t)oy * NV + ox] = t[threadIdx.x][threadIdx.y];
}

// ---------------- elementwise (with fused zeroing) ----------------
__global__ void massx_kernel(const float* __restrict__ y, const float* __restrict__ mass,
                             float* __restrict__ f, float* __restrict__ mx,
                             float* __restrict__ yB, float* __restrict__ xs,
                             float* __restrict__ gx)
{
    int gid = blockIdx.x * 256 + threadIdx.x;   // NV*64
    int v = gid >> 6, d = gid & 63;
    float x = y[gid];
    f[v * 128 + d] = x;
    mx[gid] = mass[v] * x;
    yB[gid] = 0.0f;
    if (gid < KK * 64) xs[gid] = 0.0f;
    if (gid < NG * 64) gx[gid] = 0.0f;
}

// fused lin1 + wcat (independent elementwise setup work, one launch)
__global__ void setup_misc_kernel(const float* __restrict__ sx, const float* __restrict__ w,
                                  const float* __restrict__ b, float* __restrict__ y,
                                  const float* __restrict__ are, const float* __restrict__ aim,
                                  float* __restrict__ W)
{
    int gid = blockIdx.x * 256 + threadIdx.x;
    if (gid < NV * 64) {
        int v = gid >> 6, d = gid & 63;
        float acc = b[d];
#pragma unroll
        for (int j = 0; j < 5; j++) acc += sx[v * 5 + j] * w[j * 64 + d];
        y[gid] = acc;
    } else {
        int q = gid - NV * 64;                 // NBLK*KK*64
        int blk = q >> 13;
        int r = q & 8191;
        int k = r >> 6, d = r & 63;
        const float* a_re = are + blk * 64 * 64;
        const float* a_im = aim + blk * 64 * 64;
        float wre, wim;
        if (k < 64) { wre = a_re[k * 64 + d];         wim = a_im[k * 64 + d]; }
        else        { wre = -a_im[(k - 64) * 64 + d]; wim = a_re[(k - 64) * 64 + d]; }
        float* Wb = W + blk * 2 * KK * 64;
        Wb[r]           = wre;
        Wb[KK * 64 + r] = wim;
    }
}

// ---------------- GCN CSR build ----------------
__global__ void deg_kernel(const int* __restrict__ dst, float* __restrict__ deg)
{
    int e = blockIdx.x * 256 + threadIdx.x;
    atomicAdd(&deg[dst[e]], 1.0f);
}
// scan + dinv + cursor-zero in one launch
__global__ __launch_bounds__(1024) void scan_kernel(const float* __restrict__ deg,
                                                    int* __restrict__ rowptr,
                                                    int* __restrict__ cursor,
                                                    float* __restrict__ dinv)
{
    __shared__ int p[1024];
    int t = threadIdx.x;
    int d0 = (int)deg[2 * t], d1 = (int)deg[2 * t + 1];
    dinv[2 * t]     = rsqrtf((float)d0 + 1.0f);
    dinv[2 * t + 1] = rsqrtf((float)d1 + 1.0f);
    p[t] = d0 + d1;
    __syncthreads();
    for (int off = 1; off < 1024; off <<= 1) {
        int v = p[t];
        if (t >= off) v += p[t - off];
        __syncthreads();
        p[t] = v;
        __syncthreads();
    }
    int excl = (t == 0) ? 0 : p[t - 1];
    rowptr[2 * t]     = excl;
    rowptr[2 * t + 1] = excl + d0;
    if (t == 1023) rowptr[2048] = p[1023];
    cursor[2 * t] = 0;
    cursor[2 * t + 1] = 0;
}
__global__ void scatter_kernel(const int* __restrict__ src, const int* __restrict__ dst,
                               const int* __restrict__ rowptr, int* __restrict__ cursor,
                               int* __restrict__ srcs)
{
    int e = blockIdx.x * 256 + threadIdx.x;
    int s = src[e], t = dst[e];
    int pos = rowptr[t] + atomicAdd(&cursor[t], 1);
    srcs[pos] = s;
}
__global__ void csr_agg_kernel(const float* __restrict__ hw, const float* __restrict__ dinv,
                               const int* __restrict__ rowptr, const int* __restrict__ srcs,
                               float* __restrict__ agg)
{
    int gid = blockIdx.x * 256 + threadIdx.x;   // NG*64
    int i = gid >> 6, d = gid & 63;
    float di = dinv[i];
    float acc = hw[i * 64 + d] * di;
    int r1 = rowptr[i + 1];
    for (int r = rowptr[i]; r < r1; r++) {
        int s = srcs[r];
        acc += hw[s * 64 + d] * dinv[s];
    }
    agg[gid] = acc * di;
}

// ---------------- tail ----------------
__global__ void out_kernel(const float* __restrict__ y, const float* __restrict__ w,
                           const float* __restrict__ b, float* __restrict__ out)
{
    int gid = blockIdx.x * 256 + threadIdx.x;   // NV*8
    int v = gid >> 3, c = gid & 7;
    float acc = b[c];
#pragma unroll 8
    for (int d = 0; d < 64; d++) acc += y[v * 64 + d] * w[d * 8 + c];
    out[gid] = acc;
}

// ---------------- host ----------------
static inline Sl sl1(const float* A, float* C, int ldc) {
    Sl s; for (int i = 0; i < 4; i++) { s.A[i] = A; s.C[i] = C; s.ldc[i] = ldc; }
    return s;
}

extern "C" void kernel_launch(void* const* d_in, const int* in_sizes, int n_in,
                              void* d_out, int out_size)
{
    static bool inited = false;
    static float *p_rbf, *p_rbfT, *p_f, *p_y, *p_cat, *p_b2, *p_mx,
                 *p_xs, *p_W, *p_GE, *p_eT, *p_gx, *p_hw, *p_agg, *p_agg2,
                 *p_deg, *p_dinv;
    static int *p_rowptr, *p_cursor, *p_srcs;
    if (!inited) {
        cudaGetSymbolAddress((void**)&p_rbf,  g_rbf);
        cudaGetSymbolAddress((void**)&p_rbfT, g_rbfT);
        cudaGetSymbolAddress((void**)&p_f,    g_f);
        cudaGetSymbolAddress((void**)&p_y,    g_y);
        cudaGetSymbolAddress((void**)&p_cat,  g_cat);
        cudaGetSymbolAddress((void**)&p_b2,   g_b2);
        cudaGetSymbolAddress((void**)&p_mx,   g_mx);
        cudaGetSymbolAddress((void**)&p_xs,   g_xs);
        cudaGetSymbolAddress((void**)&p_W,    g_W);
        cudaGetSymbolAddress((void**)&p_GE,   g_GE);
        cudaGetSymbolAddress((void**)&p_eT,   g_eT);
        cudaGetSymbolAddress((void**)&p_gx,   g_gx);
        cudaGetSymbolAddress((void**)&p_hw,   g_hw);
        cudaGetSymbolAddress((void**)&p_agg,  g_agg);
        cudaGetSymbolAddress((void**)&p_agg2, g_agg2);
        cudaGetSymbolAddress((void**)&p_deg,  g_deg);
        cudaGetSymbolAddress((void**)&p_dinv, g_dinv);
        cudaGetSymbolAddress((void**)&p_rowptr, g_rowptr);
        cudaGetSymbolAddress((void**)&p_cursor, g_cursor);
        cudaGetSymbolAddress((void**)&p_srcs,   g_srcs);
        inited = true;
    }

    const float* surf_x    = (const float*)d_in[0];
    const float* mass      = (const float*)d_in[1];
    const float* evals     = (const float*)d_in[2];
    const float* evecs     = (const float*)d_in[3];
    const float* gradX     = (const float*)d_in[4];
    const float* gradY     = (const float*)d_in[5];
    const float* vertices  = (const float*)d_in[6];
    const float* graph_pos = (const float*)d_in[8];
    const float* lin1_w    = (const float*)d_in[9];
    const float* lin1_b    = (const float*)d_in[10];
    const float* last_w    = (const float*)d_in[13];
    const float* last_b    = (const float*)d_in[14];
    const float* diff_time = (const float*)d_in[15];
    const float* A_re      = (const float*)d_in[16];
    const float* A_im      = (const float*)d_in[17];
    const float* mlp_w0    = (const float*)d_in[18];
    const float* mlp_b0    = (const float*)d_in[19];
    const float* mlp_w1    = (const float*)d_in[20];
    const float* mlp_b1    = (const float*)d_in[21];
    const float* mlp_w2    = (const float*)d_in[22];
    const float* mlp_b2    = (const float*)d_in[23];
    const float* gcn_w1    = (const float*)d_in[24];
    const float* gcn_b1    = (const float*)d_in[25];
    const float* gcn_w2    = (const float*)d_in[26];
    const float* gcn_b2    = (const float*)d_in[27];
    const int*   eidx      = (const int*)d_in[28];
    const int*   e_src     = eidx;
    const int*   e_dst     = eidx + EE;
    float* out = (float*)d_out;

    // ---- setup (serial) ----
    rbf_kernel<<<dim3(NG / 32, NV / 32), dim3(32, 32)>>>(vertices, graph_pos, p_rbf, p_rbfT);

    cudaMemsetAsync(p_deg, 0, NG * sizeof(float));
    deg_kernel<<<EE / 256, 256>>>(e_dst, p_deg);
    scan_kernel<<<1, 1024>>>(p_deg, p_rowptr, p_cursor, p_dinv);
    scatter_kernel<<<EE / 256, 256>>>(e_src, e_dst, p_rowptr, p_cursor, p_srcs);

    transpose_kernel<<<dim3(KK / 32, NV / 32), dim3(32, 32)>>>(evecs, p_eT);
    setup_misc_kernel<<<(NV * 64 + NBLK * KK * 64) / 256, 256>>>(
        surf_x, lin1_w, lin1_b, p_y, A_re, A_im, p_W);

    // GE = [gradX@evecs(lo) ; gradX@evecs(hi) ; gradY@evecs(lo) ; gradY@evecs(hi)]
    {
        Sl s;
        s.A[0] = gradX; s.A[1] = gradX; s.A[2] = gradY; s.A[3] = gradY;
        s.C[0] = p_GE;            s.C[1] = p_GE + 64;
        s.C[2] = p_GE + NV * 128; s.C[3] = p_GE + NV * 128 + 64;
        s.ldc[0] = s.ldc[1] = s.ldc[2] = s.ldc[3] = 128;
        gemm64<<<dim3(NV / 128, 1, 4), 128>>>(
            s, NV, evecs, evecs + 64, 128, NV, NV,
            nullptr, nullptr, 0, 0, nullptr, nullptr, nullptr, nullptr);
    }

    for (int blk = 0; blk < NBLK; blk++) {
        const float* t   = diff_time + blk * 64;
        const float* w0  = mlp_w0 + blk * 192 * 64;
        const float* b0  = mlp_b0 + blk * 64;
        const float* w1  = mlp_w1 + blk * 64 * 64;
        const float* b1  = mlp_b1 + blk * 64;
        const float* w2  = mlp_w2 + blk * 64 * 64;
        const float* b2m = mlp_b2 + blk * 64;
        const float* gw1 = gcn_w1 + blk * 64 * 64;
        const float* gb1 = gcn_b1 + blk * 64;
        const float* gw2 = gcn_w2 + blk * 64 * 64;
        const float* gb2 = gcn_b2 + blk * 64;
        const float* Wb  = p_W + blk * 2 * KK * 64;
        float* yA = p_y + (blk & 1) * NV * 64;
        float* yB = p_y + (1 - (blk & 1)) * NV * 64;

        // x -> f[:,0:64], mx = mass*x ; zero yB + xs + gx
        massx_kernel<<<NV * 64 / 256, 256>>>(yA, mass, p_f, p_mx, yB, p_xs, p_gx);

        // xs = evecsT @ mx  (split-K 16)
        gemm64<<<dim3(1, 16, 1), 128>>>(
            sl1(p_eT, p_xs, 64), NV, p_mx, p_mx, 64, NV, NV / 16,
            nullptr, nullptr, 0, 0, nullptr, nullptr, nullptr, nullptr);

        // [x_diff ; gX ; gY] = [evecs ; GE_X ; GE_Y] @ (coef * xs)  (exp fused)
        {
            Sl s;
            s.A[0] = evecs;          s.C[0] = p_f + 64;   s.ldc[0] = 128;
            s.A[1] = p_GE;           s.C[1] = p_cat;      s.ldc[1] = 128;
            s.A[2] = p_GE + NV*128;  s.C[2] = p_cat + 64; s.ldc[2] = 128;
            s.A[3] = evecs;          s.C[3] = p_f + 64;   s.ldc[3] = 128;
            gemm64<<<dim3(NV / 128, 1, 3), 128>>>(
                s, 128, p_xs, p_xs, 64, KK, KK,
                nullptr, nullptr, 0, 0, nullptr, nullptr, evals, t);
        }

        // b_re|b_im = cat @ [Wre|Wim]
        {
            Sl s;
            s.A[0] = p_cat; s.C[0] = p_b2;           s.ldc[0] = 64;
            s.A[1] = p_cat; s.C[1] = p_b2 + NV * 64; s.ldc[1] = 64;
            s.A[2] = p_cat; s.C[2] = p_b2;           s.ldc[2] = 64;
            s.A[3] = p_cat; s.C[3] = p_b2;           s.ldc[3] = 64;
            gemm64<<<dim3(NV / 128, 1, 2), 128>>>(
                s, 128, Wb, Wb + KK * 64, 64, KK, KK,
                nullptr, nullptr, 0, 0, nullptr, nullptr, nullptr, nullptr);
        }

        // fused MLP (gfeat computed in-loader) + residual -> f[:,0:64]
        mlp_kernel<<<NV / 128, 128>>>(p_f, p_cat, p_b2, w0, b0, w1, b1, w2, b2m);

        // gx = rbf^T @ diff_x (split-K 8)
        gemm64<<<dim3(NG / 128, 8, 1), 128>>>(
            sl1(p_rbfT, p_gx, 64), NV, p_f, p_f, 128, NV, NV / 8,
            nullptr, nullptr, 0, 0, nullptr, nullptr, nullptr, nullptr);

        // GCN: t1 = A_hat*gx ; hw = relu(t1@W1+b1)@W2 ; agg2 = A_hat*hw
        csr_agg_kernel<<<NG * 64 / 256, 256>>>(p_gx, p_dinv, p_rowptr, p_srcs, p_agg);
        gcn_kernel<<<NG / 128, 128>>>(p_agg, p_hw, gw1, gb1, gw2);
        csr_agg_kernel<<<NG * 64 / 256, 256>>>(p_hw, p_dinv, p_rowptr, p_srcs, p_agg2);

        // diff_x = rbf @ (agg2 + gb2)  (B-loader bias fused; split-K 4) -> yB
        gemm64<<<dim3(NV / 128, 4, 1), 128>>>(
            sl1(p_rbf, yB, 64), NG, p_agg2, p_agg2, 64, NG, NG / 4,
            nullptr, nullptr, 0, 0, nullptr, gb2, nullptr, nullptr);
    }

    // final: out = y[0] @ last_w + last_b
    out_kernel<<<(NV * 8) / 256, 256>>>(p_y, last_w, last_b, out);
}

// round 16
// speedup vs baseline: 1.2805x; 1.0047x over previous
#include <cuda_runtime.h>
#include <math.h>
#include <stdint.h>

#define NV 4096
#define NG 2048
#define KK 128
#define NBLK 4
#define EE 32768

// ---------------- scratch ----------------
__device__ float g_rbf [NV * NG];
__device__ float g_rbfT[NG * NV];
__device__ float g_f   [NV * 128];       // [NV, 128] = [x | x_diff]
__device__ float g_y   [2 * NV * 64];    // double-buffered diff_x
__device__ float g_cat [NV * 128];       // [gX | gY]
__device__ float g_b2  [2 * NV * 64];    // [b_re ; b_im]
__device__ float g_mx  [NV * 64];        // mass * x
__device__ float g_xs  [KK * 64];
__device__ float g_W   [NBLK * 2 * KK * 64];  // per-block [Wre ; Wim]
__device__ float g_GE  [2 * NV * 128];   // [gradX@evecs ; gradY@evecs]
__device__ float g_eT  [KK * NV];        // evecs^T
__device__ float g_gx  [NG * 64];
__device__ float g_hw  [NG * 64];
__device__ float g_agg [NG * 64];
__device__ float g_agg2[NG * 64];
__device__ float g_deg [NG];
__device__ float g_dinv[NG];
__device__ int   g_rowptr[NG + 1];
__device__ int   g_cursor[NG];
__device__ int   g_srcs[EE];

// ---------------- tf32 helpers ----------------
__device__ __forceinline__ float tf32r(float x) {
    uint32_t r;
    asm("cvt.rna.tf32.f32 %0, %1;" : "=r"(r) : "f"(x));
    return __uint_as_float(r);
}
__device__ __forceinline__ void mma_tf32(float* c, const uint32_t* a, const uint32_t* b) {
    asm volatile(
        "mma.sync.aligned.m16n8k8.row.col.f32.tf32.tf32.f32 "
        "{%0,%1,%2,%3}, {%4,%5,%6,%7}, {%8,%9}, {%0,%1,%2,%3};"
        : "+f"(c[0]), "+f"(c[1]), "+f"(c[2]), "+f"(c[3])
        : "r"(a[0]), "r"(a[1]), "r"(a[2]), "r"(a[3]), "r"(b[0]), "r"(b[1]));
}

// per-z slice descriptors
struct Sl {
    const float* A[4];
    float*       C[4];
    int          ldc[4];
};

// ---------------- generic N=64 GEMM (tf32 MMA), BM=128, 128 threads -----------
__global__ __launch_bounds__(128) void gemm64(
    Sl sl, int lda,
    const float* __restrict__ B0, const float* __restrict__ B1, int ldb,
    int KB, int kchunk,
    const float* __restrict__ bias,
    const float* __restrict__ resid, int ldr, int act,
    const float* __restrict__ abias, const float* __restrict__ bbias,
    const float* __restrict__ bexp_ev, const float* __restrict__ bexp_t)
{
    __shared__ float As[2][128][36];
    __shared__ float Bs[2][32][72];

    const int z = blockIdx.z;
    const float* A = sl.A[z];
    const float* B = (z & 1) ? B1 : B0;
    float* C = sl.C[z];
    const int ldc = sl.ldc[z];

    const int tid    = threadIdx.x;
    const int warp   = tid >> 5;
    const int lane   = tid & 31;
    const int g      = lane >> 2;
    const int tg     = lane & 3;
    const int m0     = blockIdx.x * 128;
    const int warp_m = warp * 32;
    const int kbeg   = blockIdx.y * kchunk;
    const int ntile  = kchunk >> 5;

    const int am = tid >> 3;
    const int ak = (tid & 7) * 4;
    const int bk = tid >> 4;
    const int bn = (tid & 15) * 4;

    float4 bb = make_float4(0.f, 0.f, 0.f, 0.f);
    if (bbias) bb = *(const float4*)(bbias + bn);
    float4 tc = make_float4(0.f, 0.f, 0.f, 0.f);
    if (bexp_t) {
        tc = *(const float4*)(bexp_t + bn);
        tc.x = fmaxf(tc.x, 1e-8f); tc.y = fmaxf(tc.y, 1e-8f);
        tc.z = fmaxf(tc.z, 1e-8f); tc.w = fmaxf(tc.w, 1e-8f);
    }

    float4 rA[8], rB[4];
    float c[2][8][4];
#pragma unroll
    for (int mi = 0; mi < 2; mi++)
#pragma unroll
        for (int ni = 0; ni < 8; ni++)
#pragma unroll
            for (int r = 0; r < 4; r++) c[mi][ni][r] = 0.0f;

    {   // prologue tile 0
        const float* ap = A + (size_t)(m0 + am) * lda + kbeg + ak;
        const float* bp = B + (size_t)(kbeg + bk) * ldb + bn;
#pragma unroll
        for (int i = 0; i < 8; i++) rA[i] = *(const float4*)(ap + (size_t)(i * 16) * lda);
#pragma unroll
        for (int i = 0; i < 4; i++) rB[i] = *(const float4*)(bp + (size_t)(i * 8) * ldb);
    }

    int buf = 0;
    for (int it = 0; it < ntile; it++) {
        const int kst = kbeg + it * 32;
#pragma unroll
        for (int i = 0; i < 8; i++) {
            float4 v = rA[i];
            if (abias) {
                float4 ab = *(const float4*)(abias + kst + ak);
                v.x = fmaxf(v.x + ab.x, 0.f); v.y = fmaxf(v.y + ab.y, 0.f);
                v.z = fmaxf(v.z + ab.z, 0.f); v.w = fmaxf(v.w + ab.w, 0.f);
            }
            v.x = tf32r(v.x); v.y = tf32r(v.y); v.z = tf32r(v.z); v.w = tf32r(v.w);
            *(float4*)&As[buf][am + i * 16][ak] = v;
        }
#pragma unroll
        for (int i = 0; i < 4; i++) {
            float4 v = rB[i];
            if (bexp_ev) {
                float ev = bexp_ev[kst + bk + i * 8];
                v.x *= __expf(-ev * tc.x); v.y *= __expf(-ev * tc.y);
                v.z *= __expf(-ev * tc.z); v.w *= __expf(-ev * tc.w);
            }
            v.x += bb.x; v.y += bb.y; v.z += bb.z; v.w += bb.w;
            v.x = tf32r(v.x); v.y = tf32r(v.y); v.z = tf32r(v.z); v.w = tf32r(v.w);
            *(float4*)&Bs[buf][bk + i * 8][bn] = v;
        }
        __syncthreads();

        if (it + 1 < ntile) {
            int kb = kbeg + (it + 1) * 32;
            const float* ap = A + (size_t)(m0 + am) * lda + kb + ak;
            const float* bp = B + (size_t)(kb + bk) * ldb + bn;
#pragma unroll
            for (int i = 0; i < 8; i++) rA[i] = *(const float4*)(ap + (size_t)(i * 16) * lda);
#pragma unroll
            for (int i = 0; i < 4; i++) rB[i] = *(const float4*)(bp + (size_t)(i * 8) * ldb);
        }

#pragma unroll
        for (int k8 = 0; k8 < 32; k8 += 8) {
            uint32_t a[2][4];
#pragma unroll
            for (int mi = 0; mi < 2; mi++) {
                int r0 = warp_m + mi * 16 + g;
                a[mi][0] = __float_as_uint(As[buf][r0][k8 + tg]);
                a[mi][1] = __float_as_uint(As[buf][r0 + 8][k8 + tg]);
                a[mi][2] = __float_as_uint(As[buf][r0][k8 + tg + 4]);
                a[mi][3] = __float_as_uint(As[buf][r0 + 8][k8 + tg + 4]);
            }
            uint32_t b[8][2];
#pragma unroll
            for (int ni = 0; ni < 8; ni++) {
                b[ni][0] = __float_as_uint(Bs[buf][k8 + tg][ni * 8 + g]);
                b[ni][1] = __float_as_uint(Bs[buf][k8 + tg + 4][ni * 8 + g]);
            }
#pragma unroll
            for (int mi = 0; mi < 2; mi++)
#pragma unroll
                for (int ni = 0; ni < 8; ni++)
                    mma_tf32(c[mi][ni], a[mi], b[ni]);
        }
        buf ^= 1;
    }

    const bool split = (gridDim.y > 1);
#pragma unroll
    for (int mi = 0; mi < 2; mi++) {
#pragma unroll
        for (int rr = 0; rr < 2; rr++) {
            int m = m0 + warp_m + mi * 16 + g + rr * 8;
#pragma unroll
            for (int ni = 0; ni < 8; ni++) {
                int n = ni * 8 + tg * 2;
                float v0 = c[mi][ni][rr * 2 + 0];
                float v1 = c[mi][ni][rr * 2 + 1];
                if (split) {
                    atomicAdd(&C[(size_t)m * ldc + n],     v0);
                    atomicAdd(&C[(size_t)m * ldc + n + 1], v1);
                } else {
                    if (bias)  { v0 += bias[n]; v1 += bias[n + 1]; }
                    if (resid) { v0 += resid[(size_t)m * ldr + n];
                                 v1 += resid[(size_t)m * ldr + n + 1]; }
                    if (act)   { v0 = fmaxf(v0, 0.0f); v1 = fmaxf(v1, 0.0f); }
                    *(float2*)&C[(size_t)m * ldc + n] = make_float2(v0, v1);
                }
            }
        }
    }
}

// ---------------- fused 3-layer MLP (one launch) -------------------------------
__device__ __forceinline__ float4 load_f_ext(
    const float* __restrict__ f, const float* __restrict__ cat,
    const float* __restrict__ b2, int m, int k)
{
    if (k < 128) return *(const float4*)(f + (size_t)m * 128 + k);
    int kk = k - 128;
    float4 gx = *(const float4*)(cat + (size_t)m * 128 + kk);
    float4 gy = *(const float4*)(cat + (size_t)m * 128 + 64 + kk);
    float4 br = *(const float4*)(b2 + (size_t)m * 64 + kk);
    float4 bi = *(const float4*)(b2 + (size_t)(NV * 64) + (size_t)m * 64 + kk);
    float4 r;
    r.x = tanhf(gx.x * br.x + gy.x * bi.x);
    r.y = tanhf(gx.y * br.y + gy.y * bi.y);
    r.z = tanhf(gx.z * br.z + gy.z * bi.z);
    r.w = tanhf(gx.w * br.w + gy.w * bi.w);
    return r;
}

__global__ __launch_bounds__(128) void mlp_kernel(
    float* __restrict__ f,                         // [NV,128]; writes cols 0:64
    const float* __restrict__ cat, const float* __restrict__ b2v,
    const float* __restrict__ w0, const float* __restrict__ b0,
    const float* __restrict__ w1, const float* __restrict__ b1,
    const float* __restrict__ w2, const float* __restrict__ b2)
{
    __shared__ float As[2][128][36];
    __shared__ float Bs[2][32][72];

    const int tid = threadIdx.x, warp = tid >> 5, lane = tid & 31;
    const int g = lane >> 2, tg = lane & 3;
    const int m0 = blockIdx.x * 128, warp_m = warp * 32;
    const int am = tid >> 3, ak = (tid & 7) * 4;
    const int bk = tid >> 4, bn = (tid & 15) * 4;

    float c[2][8][4];
#pragma unroll
    for (int mi = 0; mi < 2; mi++)
#pragma unroll
        for (int ni = 0; ni < 8; ni++)
#pragma unroll
            for (int r = 0; r < 4; r++) c[mi][ni][r] = 0.0f;

    // ---- phase 1: h1 = relu(fext @ w0 + b0), K=192 streamed (6 tiles) ----
    float4 rA[8], rB[4];
    {
#pragma unroll
        for (int i = 0; i < 8; i++)
            rA[i] = load_f_ext(f, cat, b2v, m0 + am + i * 16, ak);
        const float* bp = w0 + (size_t)bk * 64 + bn;
#pragma unroll
        for (int i = 0; i < 4; i++) rB[i] = *(const float4*)(bp + (size_t)(i * 8) * 64);
    }
    int buf = 0;
    for (int it = 0; it < 6; it++) {
#pragma unroll
        for (int i = 0; i < 8; i++) {
            float4 v = rA[i];
            v.x = tf32r(v.x); v.y = tf32r(v.y); v.z = tf32r(v.z); v.w = tf32r(v.w);
            *(float4*)&As[buf][am + i * 16][ak] = v;
        }
#pragma unroll
        for (int i = 0; i < 4; i++) {
            float4 v = rB[i];
            v.x = tf32r(v.x); v.y = tf32r(v.y); v.z = tf32r(v.z); v.w = tf32r(v.w);
            *(float4*)&Bs[buf][bk + i * 8][bn] = v;
        }
        __syncthreads();
        if (it + 1 < 6) {
            int kb = (it + 1) * 32;
#pragma unroll
            for (int i = 0; i < 8; i++)
                rA[i] = load_f_ext(f, cat, b2v, m0 + am + i * 16, kb + ak);
            const float* bp = w0 + (size_t)(kb + bk) * 64 + bn;
#pragma unroll
            for (int i = 0; i < 4; i++) rB[i] = *(const float4*)(bp + (size_t)(i * 8) * 64);
        }
#pragma unroll
        for (int k8 = 0; k8 < 32; k8 += 8) {
            uint32_t a[2][4];
#pragma unroll
            for (int mi = 0; mi < 2; mi++) {
                int r0 = warp_m + mi * 16 + g;
                a[mi][0] = __float_as_uint(As[buf][r0][k8 + tg]);
                a[mi][1] = __float_as_uint(As[buf][r0 + 8][k8 + tg]);
                a[mi][2] = __float_as_uint(As[buf][r0][k8 + tg + 4]);
                a[mi][3] = __float_as_uint(As[buf][r0 + 8][k8 + tg + 4]);
            }
            uint32_t b[8][2];
#pragma unroll
            for (int ni = 0; ni < 8; ni++) {
                b[ni][0] = __float_as_uint(Bs[buf][k8 + tg][ni * 8 + g]);
                b[ni][1] = __float_as_uint(Bs[buf][k8 + tg + 4][ni * 8 + g]);
            }
#pragma unroll
            for (int mi = 0; mi < 2; mi++)
#pragma unroll
                for (int ni = 0; ni < 8; ni++)
                    mma_tf32(c[mi][ni], a[mi], b[ni]);
        }
        buf ^= 1;
    }
    // h1 -> As (own-warp rows)
#pragma unroll
    for (int mi = 0; mi < 2; mi++)
#pragma unroll
        for (int rr = 0; rr < 2; rr++) {
            int ml = warp_m + mi * 16 + g + rr * 8;
#pragma unroll
            for (int ni = 0; ni < 8; ni++) {
                int n = ni * 8 + tg * 2;
                float v0 = fmaxf(c[mi][ni][rr * 2 + 0] + b0[n], 0.f);
                float v1 = fmaxf(c[mi][ni][rr * 2 + 1] + b0[n + 1], 0.f);
                *(float2*)&As[n >> 5][ml][n & 31] = make_float2(tf32r(v0), tf32r(v1));
            }
        }
    __syncthreads();

    // ---- phase 2: h2 = relu(h1 @ w1 + b1) ----
#pragma unroll
    for (int t = 0; t < 2; t++)
#pragma unroll
        for (int i = 0; i < 4; i++) {
            float4 v = *(const float4*)(w1 + (size_t)(t * 32 + bk + i * 8) * 64 + bn);
            v.x = tf32r(v.x); v.y = tf32r(v.y); v.z = tf32r(v.z); v.w = tf32r(v.w);
            *(float4*)&Bs[t][bk + i * 8][bn] = v;
        }
    __syncthreads();
#pragma unroll
    for (int mi = 0; mi < 2; mi++)
#pragma unroll
        for (int ni = 0; ni < 8; ni++)
#pragma unroll
            for (int r = 0; r < 4; r++) c[mi][ni][r] = 0.0f;
#pragma unroll
    for (int kt = 0; kt < 2; kt++)
#pragma unroll
        for (int k8 = 0; k8 < 32; k8 += 8) {
            uint32_t a[2][4];
#pragma unroll
            for (int mi = 0; mi < 2; mi++) {
                int r0 = warp_m + mi * 16 + g;
                a[mi][0] = __float_as_uint(As[kt][r0][k8 + tg]);
                a[mi][1] = __float_as_uint(As[kt][r0 + 8][k8 + tg]);
                a[mi][2] = __float_as_uint(As[kt][r0][k8 + tg + 4]);
                a[mi][3] = __float_as_uint(As[kt][r0 + 8][k8 + tg + 4]);
            }
            uint32_t b[8][2];
#pragma unroll
            for (int ni = 0; ni < 8; ni++) {
                b[ni][0] = __float_as_uint(Bs[kt][k8 + tg][ni * 8 + g]);
                b[ni][1] = __float_as_uint(Bs[kt][k8 + tg + 4][ni * 8 + g]);
            }
#pragma unroll
            for (int mi = 0; mi < 2; mi++)
#pragma unroll
                for (int ni = 0; ni < 8; ni++)
                    mma_tf32(c[mi][ni], a[mi], b[ni]);
        }
#pragma unroll
    for (int mi = 0; mi < 2; mi++)
#pragma unroll
        for (int rr = 0; rr < 2; rr++) {
            int ml = warp_m + mi * 16 + g + rr * 8;
#pragma unroll
            for (int ni = 0; ni < 8; ni++) {
                int n = ni * 8 + tg * 2;
                float v0 = fmaxf(c[mi][ni][rr * 2 + 0] + b1[n], 0.f);
                float v1 = fmaxf(c[mi][ni][rr * 2 + 1] + b1[n + 1], 0.f);
                *(float2*)&As[n >> 5][ml][n & 31] = make_float2(tf32r(v0), tf32r(v1));
            }
        }
    __syncthreads();

    // ---- phase 3: x' = h2 @ w2 + b2 + x ----
#pragma unroll
    for (int t = 0; t < 2; t++)
#pragma unroll
        for (int i = 0; i < 4; i++) {
            float4 v = *(const float4*)(w2 + (size_t)(t * 32 + bk + i * 8) * 64 + bn);
            v.x = tf32r(v.x); v.y = tf32r(v.y); v.z = tf32r(v.z); v.w = tf32r(v.w);
            *(float4*)&Bs[t][bk + i * 8][bn] = v;
        }
    __syncthreads();
#pragma unroll
    for (int mi = 0; mi < 2; mi++)
#pragma unroll
        for (int ni = 0; ni < 8; ni++)
#pragma unroll
            for (int r = 0; r < 4; r++) c[mi][ni][r] = 0.0f;
#pragma unroll
    for (int kt = 0; kt < 2; kt++)
#pragma unroll
        for (int k8 = 0; k8 < 32; k8 += 8) {
            uint32_t a[2][4];
#pragma unroll
            for (int mi = 0; mi < 2; mi++) {
                int r0 = warp_m + mi * 16 + g;
                a[mi][0] = __float_as_uint(As[kt][r0][k8 + tg]);
                a[mi][1] = __float_as_uint(As[kt][r0 + 8][k8 + tg]);
                a[mi][2] = __float_as_uint(As[kt][r0][k8 + tg + 4]);
                a[mi][3] = __float_as_uint(As[kt][r0 + 8][k8 + tg + 4]);
            }
            uint32_t b[8][2];
#pragma unroll
            for (int ni = 0; ni < 8; ni++) {
                b[ni][0] = __float_as_uint(Bs[kt][k8 + tg][ni * 8 + g]);
                b[ni][1] = __float_as_uint(Bs[kt][k8 + tg + 4][ni * 8 + g]);
            }
#pragma unroll
            for (int mi = 0; mi < 2; mi++)
#pragma unroll
                for (int ni = 0; ni < 8; ni++)
                    mma_tf32(c[mi][ni], a[mi], b[ni]);
        }
#pragma unroll
    for (int mi = 0; mi < 2; mi++)
#pragma unroll
        for (int rr = 0; rr < 2; rr++) {
            int m = m0 + warp_m + mi * 16 + g + rr * 8;
#pragma unroll
            for (int ni = 0; ni < 8; ni++) {
                int n = ni * 8 + tg * 2;
                float v0 = c[mi][ni][rr * 2 + 0] + b2[n]     + f[(size_t)m * 128 + n];
                float v1 = c[mi][ni][rr * 2 + 1] + b2[n + 1] + f[(size_t)m * 128 + n + 1];
                *(float2*)&f[(size_t)m * 128 + n] = make_float2(v0, v1);
            }
        }
}

// ---------------- fused 2-layer GCN: t2 = (relu(t1@W1+b1))@W2 ----------------
__global__ __launch_bounds__(128) void gcn_kernel(
    const float* __restrict__ t1, float* __restrict__ t2,
    const float* __restrict__ W1, const float* __restrict__ bb1,
    const float* __restrict__ W2)
{
    __shared__ float As[2][128][36];
    __shared__ float Bs[2][32][72];
    float* Asf = &As[0][0][0];

    const int tid = threadIdx.x, warp = tid >> 5, lane = tid & 31;
    const int g = lane >> 2, tg = lane & 3;
    const int m0 = blockIdx.x * 128, warp_m = warp * 32;
    const int am = tid >> 3, ak = (tid & 7) * 4;
    const int bk = tid >> 4, bn = (tid & 15) * 4;

    // stage A = t1 (128x64), B = W1 (64x64)
#pragma unroll
    for (int b = 0; b < 2; b++)
#pragma unroll
        for (int i = 0; i < 8; i++) {
            float4 v = *(const float4*)(t1 + (size_t)(m0 + am + i * 16) * 64 + b * 32 + ak);
            v.x = tf32r(v.x); v.y = tf32r(v.y); v.z = tf32r(v.z); v.w = tf32r(v.w);
            *(float4*)&As[b][am + i * 16][ak] = v;
        }
#pragma unroll
    for (int i = 0; i < 8; i++) {
        int k = bk + i * 8;
        float4 v = *(const float4*)(W1 + (size_t)k * 64 + bn);
        v.x = tf32r(v.x); v.y = tf32r(v.y); v.z = tf32r(v.z); v.w = tf32r(v.w);
        *(float4*)&Bs[k >> 5][k & 31][bn] = v;
    }
    __syncthreads();

    float c[2][8][4];
#pragma unroll
    for (int mi = 0; mi < 2; mi++)
#pragma unroll
        for (int ni = 0; ni < 8; ni++)
#pragma unroll
            for (int r = 0; r < 4; r++) c[mi][ni][r] = 0.0f;
#pragma unroll
    for (int kt = 0; kt < 2; kt++)
#pragma unroll
        for (int k8 = 0; k8 < 32; k8 += 8) {
            uint32_t a[2][4];
#pragma unroll
            for (int mi = 0; mi < 2; mi++) {
                int r0 = warp_m + mi * 16 + g;
                a[mi][0] = __float_as_uint(As[kt][r0][k8 + tg]);
                a[mi][1] = __float_as_uint(As[kt][r0 + 8][k8 + tg]);
                a[mi][2] = __float_as_uint(As[kt][r0][k8 + tg + 4]);
                a[mi][3] = __float_as_uint(As[kt][r0 + 8][k8 + tg + 4]);
            }
            uint32_t b[8][2];
#pragma unroll
            for (int ni = 0; ni < 8; ni++) {
                b[ni][0] = __float_as_uint(Bs[kt][k8 + tg][ni * 8 + g]);
                b[ni][1] = __float_as_uint(Bs[kt][k8 + tg + 4][ni * 8 + g]);
            }
#pragma unroll
            for (int mi = 0; mi < 2; mi++)
#pragma unroll
                for (int ni = 0; ni < 8; ni++)
                    mma_tf32(c[mi][ni], a[mi], b[ni]);
        }
    // h = relu(c + b1) -> As (own-warp rows)
#pragma unroll
    for (int mi = 0; mi < 2; mi++)
#pragma unroll
        for (int rr = 0; rr < 2; rr++) {
            int ml = warp_m + mi * 16 + g + rr * 8;
#pragma unroll
            for (int ni = 0; ni < 8; ni++) {
                int n = ni * 8 + tg * 2;
                float v0 = fmaxf(c[mi][ni][rr * 2 + 0] + bb1[n], 0.f);
                float v1 = fmaxf(c[mi][ni][rr * 2 + 1] + bb1[n + 1], 0.f);
                int idx = (n >> 5) * 4608 + ml * 36 + (n & 31);
                Asf[idx]     = tf32r(v0);
                Asf[idx + 1] = tf32r(v1);
            }
        }
    __syncthreads();

    // stage B = W2
#pragma unroll
    for (int i = 0; i < 8; i++) {
        int k = bk + i * 8;
        float4 v = *(const float4*)(W2 + (size_t)k * 64 + bn);
        v.x = tf32r(v.x); v.y = tf32r(v.y); v.z = tf32r(v.z); v.w = tf32r(v.w);
        *(float4*)&Bs[k >> 5][k & 31][bn] = v;
    }
    __syncthreads();
#pragma unroll
    for (int mi = 0; mi < 2; mi++)
#pragma unroll
        for (int ni = 0; ni < 8; ni++)
#pragma unroll
            for (int r = 0; r < 4; r++) c[mi][ni][r] = 0.0f;
#pragma unroll
    for (int kt = 0; kt < 2; kt++)
#pragma unroll
        for (int k8 = 0; k8 < 32; k8 += 8) {
            uint32_t a[2][4];
#pragma unroll
            for (int mi = 0; mi < 2; mi++) {
                int r0 = warp_m + mi * 16 + g;
                a[mi][0] = __float_as_uint(As[kt][r0][k8 + tg]);
                a[mi][1] = __float_as_uint(As[kt][r0 + 8][k8 + tg]);
                a[mi][2] = __float_as_uint(As[kt][r0][k8 + tg + 4]);
                a[mi][3] = __float_as_uint(As[kt][r0 + 8][k8 + tg + 4]);
            }
            uint32_t b[8][2];
#pragma unroll
            for (int ni = 0; ni < 8; ni++) {
                b[ni][0] = __float_as_uint(Bs[kt][k8 + tg][ni * 8 + g]);
                b[ni][1] = __float_as_uint(Bs[kt][k8 + tg + 4][ni * 8 + g]);
            }
#pragma unroll
            for (int mi = 0; mi < 2; mi++)
#pragma unroll
                for (int ni = 0; ni < 8; ni++)
                    mma_tf32(c[mi][ni], a[mi], b[ni]);
        }
#pragma unroll
    for (int mi = 0; mi < 2; mi++)
#pragma unroll
        for (int rr = 0; rr < 2; rr++) {
            int m = m0 + warp_m + mi * 16 + g + rr * 8;
#pragma unroll
            for (int ni = 0; ni < 8; ni++) {
                int n = ni * 8 + tg * 2;
                *(float2*)&t2[(size_t)m * 64 + n] =
                    make_float2(c[mi][ni][rr * 2 + 0], c[mi][ni][rr * 2 + 1]);
            }
        }
}

// ---------------- rbf coupling + transpose (fast math) ----------------
__device__ __forceinline__ float exp_neg_04(float dist) {
    float t  = dist * -0.5770780163555852f;
    float fn = floorf(t);
    float fr = t - fn;
    float p  = 1.5403530e-4f;
    p = fmaf(p, fr, 1.33335581e-3f);
    p = fmaf(p, fr, 9.61812911e-3f);
    p = fmaf(p, fr, 5.55041087e-2f);
    p = fmaf(p, fr, 2.40226507e-1f);
    p = fmaf(p, fr, 6.93147181e-1f);
    p = fmaf(p, fr, 1.0f);
    int n = (int)fn;
    n = n < -126 ? -126 : n;
    return p * __int_as_float((n + 127) << 23);
}

__global__ void rbf_kernel(const float* __restrict__ vert, const float* __restrict__ gp,
                           float* __restrict__ rbf, float* __restrict__ rbfT)
{
    __shared__ float tile[32][33];
    int tx = threadIdx.x, ty = threadIdx.y;
    int g = blockIdx.x * 32 + tx;
    int v = blockIdx.y * 32 + ty;
    float vx = vert[v * 3], vy = vert[v * 3 + 1], vz = vert[v * 3 + 2];
    float gx = gp[g * 3],  gy = gp[g * 3 + 1],  gz = gp[g * 3 + 2];
    float dx = vx - gx, dy = vy - gy, dz = vz - gz;
    float d2 = fmaf(dx, dx, fmaf(dy, dy, dz * dz));
    d2 = fmaxf(d2, 1e-24f);
    float rs;
    asm("rsqrt.approx.f32 %0, %1;" : "=f"(rs) : "f"(d2));
    float r = exp_neg_04(d2 * rs);
    rbf[(size_t)v * NG + g] = r;
    tile[ty][tx] = r;
    __syncthreads();
    int g2 = blockIdx.x * 32 + ty;
    int v2 = blockIdx.y * 32 + tx;
    rbfT[(size_t)g2 * NV + v2] = tile[tx][ty];
}

__global__ void transpose_kernel(const float* __restrict__ in, float* __restrict__ out)
{
    __shared__ float t[32][33];
    int x = blockIdx.x * 32 + threadIdx.x;
    int y = blockIdx.y * 32 + threadIdx.y;
    t[threadIdx.y][threadIdx.x] = in[(size_t)y * 128 + x];
    __syncthreads();
    int ox = blockIdx.y * 32 + threadIdx.x;
    int oy = blockIdx.x * 32 + threadIdx.y;
    out[(size_t)oy * NV + ox] = t[threadIdx.x][threadIdx.y];
}

// ---------------- elementwise (with fused zeroing) ----------------
__global__ void massx_kernel(const float* __restrict__ y, const float* __restrict__ mass,
                             float* __restrict__ f, float* __restrict__ mx,
                             float* __restrict__ yB, float* __restrict__ xs,
                             float* __restrict__ gx)
{
    int gid = blockIdx.x * 256 + threadIdx.x;   // NV*64
    int v = gid >> 6, d = gid & 63;
    float x = y[gid];
    f[v * 128 + d] = x;
    mx[gid] = mass[v] * x;
    yB[gid] = 0.0f;
    if (gid < KK * 64) xs[gid] = 0.0f;
    if (gid < NG * 64) gx[gid] = 0.0f;
}

// fused lin1 + wcat
__global__ void setup_misc_kernel(const float* __restrict__ sx, const float* __restrict__ w,
                                  const float* __restrict__ b, float* __restrict__ y,
                                  const float* __restrict__ are, const float* __restrict__ aim,
                                  float* __restrict__ W)
{
    int gid = blockIdx.x * 256 + threadIdx.x;
    if (gid < NV * 64) {
        int v = gid >> 6, d = gid & 63;
        float acc = b[d];
#pragma unroll
        for (int j = 0; j < 5; j++) acc += sx[v * 5 + j] * w[j * 64 + d];
        y[gid] = acc;
    } else {
        int q = gid - NV * 64;                 // NBLK*KK*64
        int blk = q >> 13;
        int r = q & 8191;
        int k = r >> 6, d = r & 63;
        const float* a_re = are + blk * 64 * 64;
        const float* a_im = aim + blk * 64 * 64;
        float wre, wim;
        if (k < 64) { wre = a_re[k * 64 + d];         wim = a_im[k * 64 + d]; }
        else        { wre = -a_im[(k - 64) * 64 + d]; wim = a_re[(k - 64) * 64 + d]; }
        float* Wb = W + blk * 2 * KK * 64;
        Wb[r]           = wre;
        Wb[KK * 64 + r] = wim;
    }
}

// ---------------- GCN CSR build ----------------
__global__ void deg_kernel(const int* __restrict__ dst, float* __restrict__ deg)
{
    int e = blockIdx.x * 256 + threadIdx.x;
    atomicAdd(&deg[dst[e]], 1.0f);
}
// scan + dinv + cursor-zero in one launch
__global__ __launch_bounds__(1024) void scan_kernel(const float* __restrict__ deg,
                                                    int* __restrict__ rowptr,
                                                    int* __restrict__ cursor,
                                                    float* __restrict__ dinv)
{
    __shared__ int p[1024];
    int t = threadIdx.x;
    int d0 = (int)deg[2 * t], d1 = (int)deg[2 * t + 1];
    dinv[2 * t]     = rsqrtf((float)d0 + 1.0f);
    dinv[2 * t + 1] = rsqrtf((float)d1 + 1.0f);
    p[t] = d0 + d1;
    __syncthreads();
    for (int off = 1; off < 1024; off <<= 1) {
        int v = p[t];
        if (t >= off) v += p[t - off];
        __syncthreads();
        p[t] = v;
        __syncthreads();
    }
    int excl = (t == 0) ? 0 : p[t - 1];
    rowptr[2 * t]     = excl;
    rowptr[2 * t + 1] = excl + d0;
    if (t == 1023) rowptr[2048] = p[1023];
    cursor[2 * t] = 0;
    cursor[2 * t + 1] = 0;
}
__global__ void scatter_kernel(const int* __restrict__ src, const int* __restrict__ dst,
                               const int* __restrict__ rowptr, int* __restrict__ cursor,
                               int* __restrict__ srcs)
{
    int e = blockIdx.x * 256 + threadIdx.x;
    int s = src[e], t = dst[e];
    int pos = rowptr[t] + atomicAdd(&cursor[t], 1);
    srcs[pos] = s;
}
__global__ void csr_agg_kernel(const float* __restrict__ hw, const float* __restrict__ dinv,
                               const int* __restrict__ rowptr, const int* __restrict__ srcs,
                               float* __restrict__ agg)
{
    int gid = blockIdx.x * 256 + threadIdx.x;   // NG*64
    int i = gid >> 6, d = gid & 63;
    float di = dinv[i];
    float acc = hw[i * 64 + d] * di;
    int r1 = rowptr[i + 1];
    for (int r = rowptr[i]; r < r1; r++) {
        int s = srcs[r];
        acc += hw[s * 64 + d] * dinv[s];
    }
    agg[gid] = acc * di;
}

// ---------------- tail ----------------
__global__ void out_kernel(const float* __restrict__ y, const float* __restrict__ w,
                           const float* __restrict__ b, float* __restrict__ out)
{
    int gid = blockIdx.x * 256 + threadIdx.x;   // NV*8
    int v = gid >> 3, c = gid & 7;
    float acc = b[c];
#pragma unroll 8
    for (int d = 0; d < 64; d++) acc += y[v * 64 + d] * w[d * 8 + c];
    out[gid] = acc;
}

// ---------------- host ----------------
static inline Sl sl1(const float* A, float* C, int ldc) {
    Sl s; for (int i = 0; i < 4; i++) { s.A[i] = A; s.C[i] = C; s.ldc[i] = ldc; }
    return s;
}

extern "C" void kernel_launch(void* const* d_in, const int* in_sizes, int n_in,
                              void* d_out, int out_size)
{
    static bool inited = false;
    static float *p_rbf, *p_rbfT, *p_f, *p_y, *p_cat, *p_b2, *p_mx,
                 *p_xs, *p_W, *p_GE, *p_eT, *p_gx, *p_hw, *p_agg, *p_agg2,
                 *p_deg, *p_dinv;
    static int *p_rowptr, *p_cursor, *p_srcs;
    static cudaStream_t s2;
    static cudaEvent_t evF2, evJ2;
    if (!inited) {
        cudaGetSymbolAddress((void**)&p_rbf,  g_rbf);
        cudaGetSymbolAddress((void**)&p_rbfT, g_rbfT);
        cudaGetSymbolAddress((void**)&p_f,    g_f);
        cudaGetSymbolAddress((void**)&p_y,    g_y);
        cudaGetSymbolAddress((void**)&p_cat,  g_cat);
        cudaGetSymbolAddress((void**)&p_b2,   g_b2);
        cudaGetSymbolAddress((void**)&p_mx,   g_mx);
        cudaGetSymbolAddress((void**)&p_xs,   g_xs);
        cudaGetSymbolAddress((void**)&p_W,    g_W);
        cudaGetSymbolAddress((void**)&p_GE,   g_GE);
        cudaGetSymbolAddress((void**)&p_eT,   g_eT);
        cudaGetSymbolAddress((void**)&p_gx,   g_gx);
        cudaGetSymbolAddress((void**)&p_hw,   g_hw);
        cudaGetSymbolAddress((void**)&p_agg,  g_agg);
        cudaGetSymbolAddress((void**)&p_agg2, g_agg2);
        cudaGetSymbolAddress((void**)&p_deg,  g_deg);
        cudaGetSymbolAddress((void**)&p_dinv, g_dinv);
        cudaGetSymbolAddress((void**)&p_rowptr, g_rowptr);
        cudaGetSymbolAddress((void**)&p_cursor, g_cursor);
        cudaGetSymbolAddress((void**)&p_srcs,   g_srcs);
        cudaStreamCreateWithFlags(&s2, cudaStreamNonBlocking);
        cudaEventCreateWithFlags(&evF2, cudaEventDisableTiming);
        cudaEventCreateWithFlags(&evJ2, cudaEventDisableTiming);
        inited = true;
    }

    const float* surf_x    = (const float*)d_in[0];
    const float* mass      = (const float*)d_in[1];
    const float* evals     = (const float*)d_in[2];
    const float* evecs     = (const float*)d_in[3];
    const float* gradX     = (const float*)d_in[4];
    const float* gradY     = (const float*)d_in[5];
    const float* vertices  = (const float*)d_in[6];
    const float* graph_pos = (const float*)d_in[8];
    const float* lin1_w    = (const float*)d_in[9];
    const float* lin1_b    = (const float*)d_in[10];
    const float* last_w    = (const float*)d_in[13];
    const float* last_b    = (const float*)d_in[14];
    const float* diff_time = (const float*)d_in[15];
    const float* A_re      = (const float*)d_in[16];
    const float* A_im      = (const float*)d_in[17];
    const float* mlp_w0    = (const float*)d_in[18];
    const float* mlp_b0    = (const float*)d_in[19];
    const float* mlp_w1    = (const float*)d_in[20];
    const float* mlp_b1    = (const float*)d_in[21];
    const float* mlp_w2    = (const float*)d_in[22];
    const float* mlp_b2    = (const float*)d_in[23];
    const float* gcn_w1    = (const float*)d_in[24];
    const float* gcn_b1    = (const float*)d_in[25];
    const float* gcn_w2    = (const float*)d_in[26];
    const float* gcn_b2    = (const float*)d_in[27];
    const int*   eidx      = (const int*)d_in[28];
    const int*   e_src     = eidx;
    const int*   e_dst     = eidx + EE;
    float* out = (float*)d_out;

    // ---- fork s2: CSR build only (tiny kernels, zero main-chain deps) ----
    cudaEventRecord(evF2, 0);
    cudaStreamWaitEvent(s2, evF2, 0);
    cudaMemsetAsync(p_deg, 0, NG * sizeof(float), s2);
    deg_kernel<<<EE / 256, 256, 0, s2>>>(e_dst, p_deg);
    scan_kernel<<<1, 1024, 0, s2>>>(p_deg, p_rowptr, p_cursor, p_dinv);
    scatter_kernel<<<EE / 256, 256, 0, s2>>>(e_src, e_dst, p_rowptr, p_cursor, p_srcs);
    cudaEventRecord(evJ2, s2);

    // ---- main-stream setup ----
    rbf_kernel<<<dim3(NG / 32, NV / 32), dim3(32, 32)>>>(vertices, graph_pos, p_rbf, p_rbfT);
    transpose_kernel<<<dim3(KK / 32, NV / 32), dim3(32, 32)>>>(evecs, p_eT);
    setup_misc_kernel<<<(NV * 64 + NBLK * KK * 64) / 256, 256>>>(
        surf_x, lin1_w, lin1_b, p_y, A_re, A_im, p_W);

    // GE = [gradX@evecs(lo) ; gradX@evecs(hi) ; gradY@evecs(lo) ; gradY@evecs(hi)]
    {
        Sl s;
        s.A[0] = gradX; s.A[1] = gradX; s.A[2] = gradY; s.A[3] = gradY;
        s.C[0] = p_GE;            s.C[1] = p_GE + 64;
        s.C[2] = p_GE + NV * 128; s.C[3] = p_GE + NV * 128 + 64;
        s.ldc[0] = s.ldc[1] = s.ldc[2] = s.ldc[3] = 128;
        gemm64<<<dim3(NV / 128, 1, 4), 128>>>(
            s, NV, evecs, evecs + 64, 128, NV, NV,
            nullptr, nullptr, 0, 0, nullptr, nullptr, nullptr, nullptr);
    }

    for (int blk = 0; blk < NBLK; blk++) {
        const float* t   = diff_time + blk * 64;
        const float* w0  = mlp_w0 + blk * 192 * 64;
        const float* b0  = mlp_b0 + blk * 64;
        const float* w1  = mlp_w1 + blk * 64 * 64;
        const float* b1  = mlp_b1 + blk * 64;
        const float* w2  = mlp_w2 + blk * 64 * 64;
        const float* b2m = mlp_b2 + blk * 64;
        const float* gw1 = gcn_w1 + blk * 64 * 64;
        const float* gb1 = gcn_b1 + blk * 64;
        const float* gw2 = gcn_w2 + blk * 64 * 64;
        const float* gb2 = gcn_b2 + blk * 64;
        const float* Wb  = p_W + blk * 2 * KK * 64;
        float* yA = p_y + (blk & 1) * NV * 64;
        float* yB = p_y + (1 - (blk & 1)) * NV * 64;

        // x -> f[:,0:64], mx = mass*x ; zero yB + xs + gx
        massx_kernel<<<NV * 64 / 256, 256>>>(yA, mass, p_f, p_mx, yB, p_xs, p_gx);

        // xs = evecsT @ mx  (split-K 16)
        gemm64<<<dim3(1, 16, 1), 128>>>(
            sl1(p_eT, p_xs, 64), NV, p_mx, p_mx, 64, NV, NV / 16,
            nullptr, nullptr, 0, 0, nullptr, nullptr, nullptr, nullptr);

        // [x_diff ; gX ; gY] = [evecs ; GE_X ; GE_Y] @ (coef * xs)  (exp fused)
        {
            Sl s;
            s.A[0] = evecs;          s.C[0] = p_f + 64;   s.ldc[0] = 128;
            s.A[1] = p_GE;           s.C[1] = p_cat;      s.ldc[1] = 128;
            s.A[2] = p_GE + NV*128;  s.C[2] = p_cat + 64; s.ldc[2] = 128;
            s.A[3] = evecs;          s.C[3] = p_f + 64;   s.ldc[3] = 128;
            gemm64<<<dim3(NV / 128, 1, 3), 128>>>(
                s, 128, p_xs, p_xs, 64, KK, KK,
                nullptr, nullptr, 0, 0, nullptr, nullptr, evals, t);
        }

        // b_re|b_im = cat @ [Wre|Wim]
        {
            Sl s;
            s.A[0] = p_cat; s.C[0] = p_b2;           s.ldc[0] = 64;
            s.A[1] = p_cat; s.C[1] = p_b2 + NV * 64; s.ldc[1] = 64;
            s.A[2] = p_cat; s.C[2] = p_b2;           s.ldc[2] = 64;
            s.A[3] = p_cat; s.C[3] = p_b2;           s.ldc[3] = 64;
            gemm64<<<dim3(NV / 128, 1, 2), 128>>>(
                s, 128, Wb, Wb + KK * 64, 64, KK, KK,
                nullptr, nullptr, 0, 0, nullptr, nullptr, nullptr, nullptr);
        }

        // fused MLP (gfeat computed in-loader) + residual -> f[:,0:64]
        mlp_kernel<<<NV / 128, 128>>>(p_f, p_cat, p_b2, w0, b0, w1, b1, w2, b2m);

        // gx = rbf^T @ diff_x (split-K 8)
        gemm64<<<dim3(NG / 128, 8, 1), 128>>>(
            sl1(p_rbfT, p_gx, 64), NV, p_f, p_f, 128, NV, NV / 8,
            nullptr, nullptr, 0, 0, nullptr, nullptr, nullptr, nullptr);

        if (blk == 0) cudaStreamWaitEvent(0, evJ2, 0);   // CSR build ready

        // GCN: t1 = A_hat*gx ; hw = relu(t1@W1+b1)@W2 ; agg2 = A_hat*hw
        csr_agg_kernel<<<NG * 64 / 256, 256>>>(p_gx, p_dinv, p_rowptr, p_srcs, p_agg);
        gcn_kernel<<<NG / 128, 128>>>(p_agg, p_hw, gw1, gb1, gw2);
        csr_agg_kernel<<<NG * 64 / 256, 256>>>(p_hw, p_dinv, p_rowptr, p_srcs, p_agg2);

        // diff_x = rbf @ (agg2 + gb2)  (B-loader bias fused; split-K 4) -> yB
        gemm64<<<dim3(NV / 128, 4, 1), 128>>>(
            sl1(p_rbf, yB, 64), NG, p_agg2, p_agg2, 64, NG, NG / 4,
            nullptr, nullptr, 0, 0, nullptr, gb2, nullptr, nullptr);
    }

    // final: out = y[0] @ last_w + last_b
    out_kernel<<<(NV * 8) / 256, 256>>>(p_y, last_w, last_b, out);
}

// round 17
// speedup vs baseline: 1.3082x; 1.0216x over previous
#include <cuda_runtime.h>
#include <math.h>
#include <stdint.h>

#define NV 4096
#define NG 2048
#define KK 128
#define NBLK 4
#define EE 32768

// ---------------- scratch ----------------
__device__ float g_rbf [NV * NG];
__device__ float g_rbfT[NG * NV];
__device__ float g_f   [NV * 128];       // [NV, 128] = [x | x_diff]
__device__ float g_y   [2 * NV * 64];    // double-buffered diff_x
__device__ float g_cat [NV * 128];       // [gX | gY]
__device__ float g_b2  [2 * NV * 64];    // [b_re ; b_im]
__device__ float g_mx  [NV * 64];        // mass * x
__device__ float g_xs  [KK * 64];
__device__ float g_W   [NBLK * 2 * KK * 64];  // per-block [Wre ; Wim]
__device__ float g_GE  [2 * NV * 128];   // [gradX@evecs ; gradY@evecs]
__device__ float g_eT  [KK * NV];        // evecs^T
__device__ float g_gx  [NG * 64];
__device__ float g_hw  [NG * 64];
__device__ float g_agg [NG * 64];
__device__ float g_agg2[NG * 64];
__device__ float g_deg [NG];
__device__ float g_dinv[NG];
__device__ int   g_rowptr[NG + 1];
__device__ int   g_cursor[NG];
__device__ int   g_srcs[EE];

// ---------------- tf32 helpers ----------------
__device__ __forceinline__ float tf32r(float x) {
    uint32_t r;
    asm("cvt.rna.tf32.f32 %0, %1;" : "=r"(r) : "f"(x));
    return __uint_as_float(r);
}
__device__ __forceinline__ void mma_tf32(float* c, const uint32_t* a, const uint32_t* b) {
    asm volatile(
        "mma.sync.aligned.m16n8k8.row.col.f32.tf32.tf32.f32 "
        "{%0,%1,%2,%3}, {%4,%5,%6,%7}, {%8,%9}, {%0,%1,%2,%3};"
        : "+f"(c[0]), "+f"(c[1]), "+f"(c[2]), "+f"(c[3])
        : "r"(a[0]), "r"(a[1]), "r"(a[2]), "r"(a[3]), "r"(b[0]), "r"(b[1]));
}

// per-z slice descriptors
struct Sl {
    const float* A[4];
    float*       C[4];
    int          ldc[4];
};

// ---------------- generic N=64 GEMM (tf32 MMA), BM=128, 128 threads -----------
__global__ __launch_bounds__(128) void gemm64(
    Sl sl, int lda,
    const float* __restrict__ B0, const float* __restrict__ B1, int ldb,
    int KB, int kchunk,
    const float* __restrict__ bias,
    const float* __restrict__ resid, int ldr, int act,
    const float* __restrict__ abias, const float* __restrict__ bbias,
    const float* __restrict__ bexp_ev, const float* __restrict__ bexp_t)
{
    __shared__ float As[2][128][36];
    __shared__ float Bs[2][32][72];

    const int z = blockIdx.z;
    const float* A = sl.A[z];
    const float* B = (z & 1) ? B1 : B0;
    float* C = sl.C[z];
    const int ldc = sl.ldc[z];

    const int tid    = threadIdx.x;
    const int warp   = tid >> 5;
    const int lane   = tid & 31;
    const int g      = lane >> 2;
    const int tg     = lane & 3;
    const int m0     = blockIdx.x * 128;
    const int warp_m = warp * 32;
    const int kbeg   = blockIdx.y * kchunk;
    const int ntile  = kchunk >> 5;

    const int am = tid >> 3;
    const int ak = (tid & 7) * 4;
    const int bk = tid >> 4;
    const int bn = (tid & 15) * 4;

    float4 bb = make_float4(0.f, 0.f, 0.f, 0.f);
    if (bbias) bb = *(const float4*)(bbias + bn);
    float4 tc = make_float4(0.f, 0.f, 0.f, 0.f);
    if (bexp_t) {
        tc = *(const float4*)(bexp_t + bn);
        tc.x = fmaxf(tc.x, 1e-8f); tc.y = fmaxf(tc.y, 1e-8f);
        tc.z = fmaxf(tc.z, 1e-8f); tc.w = fmaxf(tc.w, 1e-8f);
    }

    float4 rA[8], rB[4];
    float c[2][8][4];
#pragma unroll
    for (int mi = 0; mi < 2; mi++)
#pragma unroll
        for (int ni = 0; ni < 8; ni++)
#pragma unroll
            for (int r = 0; r < 4; r++) c[mi][ni][r] = 0.0f;

    {   // prologue tile 0
        const float* ap = A + (size_t)(m0 + am) * lda + kbeg + ak;
        const float* bp = B + (size_t)(kbeg + bk) * ldb + bn;
#pragma unroll
        for (int i = 0; i < 8; i++) rA[i] = *(const float4*)(ap + (size_t)(i * 16) * lda);
#pragma unroll
        for (int i = 0; i < 4; i++) rB[i] = *(const float4*)(bp + (size_t)(i * 8) * ldb);
    }

    int buf = 0;
    for (int it = 0; it < ntile; it++) {
        const int kst = kbeg + it * 32;
#pragma unroll
        for (int i = 0; i < 8; i++) {
            float4 v = rA[i];
            if (abias) {
                float4 ab = *(const float4*)(abias + kst + ak);
                v.x = fmaxf(v.x + ab.x, 0.f); v.y = fmaxf(v.y + ab.y, 0.f);
                v.z = fmaxf(v.z + ab.z, 0.f); v.w = fmaxf(v.w + ab.w, 0.f);
            }
            v.x = tf32r(v.x); v.y = tf32r(v.y); v.z = tf32r(v.z); v.w = tf32r(v.w);
            *(float4*)&As[buf][am + i * 16][ak] = v;
        }
#pragma unroll
        for (int i = 0; i < 4; i++) {
            float4 v = rB[i];
            if (bexp_ev) {
                float ev = bexp_ev[kst + bk + i * 8];
                v.x *= __expf(-ev * tc.x); v.y *= __expf(-ev * tc.y);
                v.z *= __expf(-ev * tc.z); v.w *= __expf(-ev * tc.w);
            }
            v.x += bb.x; v.y += bb.y; v.z += bb.z; v.w += bb.w;
            v.x = tf32r(v.x); v.y = tf32r(v.y); v.z = tf32r(v.z); v.w = tf32r(v.w);
            *(float4*)&Bs[buf][bk + i * 8][bn] = v;
        }
        __syncthreads();

        if (it + 1 < ntile) {
            int kb = kbeg + (it + 1) * 32;
            const float* ap = A + (size_t)(m0 + am) * lda + kb + ak;
            const float* bp = B + (size_t)(kb + bk) * ldb + bn;
#pragma unroll
            for (int i = 0; i < 8; i++) rA[i] = *(const float4*)(ap + (size_t)(i * 16) * lda);
#pragma unroll
            for (int i = 0; i < 4; i++) rB[i] = *(const float4*)(bp + (size_t)(i * 8) * ldb);
        }

#pragma unroll
        for (int k8 = 0; k8 < 32; k8 += 8) {
            uint32_t a[2][4];
#pragma unroll
            for (int mi = 0; mi < 2; mi++) {
                int r0 = warp_m + mi * 16 + g;
                a[mi][0] = __float_as_uint(As[buf][r0][k8 + tg]);
                a[mi][1] = __float_as_uint(As[buf][r0 + 8][k8 + tg]);
                a[mi][2] = __float_as_uint(As[buf][r0][k8 + tg + 4]);
                a[mi][3] = __float_as_uint(As[buf][r0 + 8][k8 + tg + 4]);
            }
            uint32_t b[8][2];
#pragma unroll
            for (int ni = 0; ni < 8; ni++) {
                b[ni][0] = __float_as_uint(Bs[buf][k8 + tg][ni * 8 + g]);
                b[ni][1] = __float_as_uint(Bs[buf][k8 + tg + 4][ni * 8 + g]);
            }
#pragma unroll
            for (int mi = 0; mi < 2; mi++)
#pragma unroll
                for (int ni = 0; ni < 8; ni++)
                    mma_tf32(c[mi][ni], a[mi], b[ni]);
        }
        buf ^= 1;
    }

    const bool split = (gridDim.y > 1);
#pragma unroll
    for (int mi = 0; mi < 2; mi++) {
#pragma unroll
        for (int rr = 0; rr < 2; rr++) {
            int m = m0 + warp_m + mi * 16 + g + rr * 8;
#pragma unroll
            for (int ni = 0; ni < 8; ni++) {
                int n = ni * 8 + tg * 2;
                float v0 = c[mi][ni][rr * 2 + 0];
                float v1 = c[mi][ni][rr * 2 + 1];
                if (split) {
                    atomicAdd(&C[(size_t)m * ldc + n],     v0);
                    atomicAdd(&C[(size_t)m * ldc + n + 1], v1);
                } else {
                    if (bias)  { v0 += bias[n]; v1 += bias[n + 1]; }
                    if (resid) { v0 += resid[(size_t)m * ldr + n];
                                 v1 += resid[(size_t)m * ldr + n + 1]; }
                    if (act)   { v0 = fmaxf(v0, 0.0f); v1 = fmaxf(v1, 0.0f); }
                    *(float2*)&C[(size_t)m * ldc + n] = make_float2(v0, v1);
                }
            }
        }
    }
}

// ---------------- fused 3-layer MLP (one launch) -------------------------------
__device__ __forceinline__ float4 load_f_ext(
    const float* __restrict__ f, const float* __restrict__ cat,
    const float* __restrict__ b2, int m, int k)
{
    if (k < 128) return *(const float4*)(f + (size_t)m * 128 + k);
    int kk = k - 128;
    float4 gx = *(const float4*)(cat + (size_t)m * 128 + kk);
    float4 gy = *(const float4*)(cat + (size_t)m * 128 + 64 + kk);
    float4 br = *(const float4*)(b2 + (size_t)m * 64 + kk);
    float4 bi = *(const float4*)(b2 + (size_t)(NV * 64) + (size_t)m * 64 + kk);
    float4 r;
    r.x = tanhf(gx.x * br.x + gy.x * bi.x);
    r.y = tanhf(gx.y * br.y + gy.y * bi.y);
    r.z = tanhf(gx.z * br.z + gy.z * bi.z);
    r.w = tanhf(gx.w * br.w + gy.w * bi.w);
    return r;
}

__global__ __launch_bounds__(128) void mlp_kernel(
    float* __restrict__ f,                         // [NV,128]; writes cols 0:64
    const float* __restrict__ cat, const float* __restrict__ b2v,
    const float* __restrict__ w0, const float* __restrict__ b0,
    const float* __restrict__ w1, const float* __restrict__ b1,
    const float* __restrict__ w2, const float* __restrict__ b2)
{
    __shared__ float As[2][128][36];
    __shared__ float Bs[2][32][72];

    const int tid = threadIdx.x, warp = tid >> 5, lane = tid & 31;
    const int g = lane >> 2, tg = lane & 3;
    const int m0 = blockIdx.x * 128, warp_m = warp * 32;
    const int am = tid >> 3, ak = (tid & 7) * 4;
    const int bk = tid >> 4, bn = (tid & 15) * 4;

    float c[2][8][4];
#pragma unroll
    for (int mi = 0; mi < 2; mi++)
#pragma unroll
        for (int ni = 0; ni < 8; ni++)
#pragma unroll
            for (int r = 0; r < 4; r++) c[mi][ni][r] = 0.0f;

    // ---- phase 1: h1 = relu(fext @ w0 + b0), K=192 streamed (6 tiles) ----
    float4 rA[8], rB[4];
    {
#pragma unroll
        for (int i = 0; i < 8; i++)
            rA[i] = load_f_ext(f, cat, b2v, m0 + am + i * 16, ak);
        const float* bp = w0 + (size_t)bk * 64 + bn;
#pragma unroll
        for (int i = 0; i < 4; i++) rB[i] = *(const float4*)(bp + (size_t)(i * 8) * 64);
    }
    int buf = 0;
    for (int it = 0; it < 6; it++) {
#pragma unroll
        for (int i = 0; i < 8; i++) {
            float4 v = rA[i];
            v.x = tf32r(v.x); v.y = tf32r(v.y); v.z = tf32r(v.z); v.w = tf32r(v.w);
            *(float4*)&As[buf][am + i * 16][ak] = v;
        }
#pragma unroll
        for (int i = 0; i < 4; i++) {
            float4 v = rB[i];
            v.x = tf32r(v.x); v.y = tf32r(v.y); v.z = tf32r(v.z); v.w = tf32r(v.w);
            *(float4*)&Bs[buf][bk + i * 8][bn] = v;
        }
        __syncthreads();
        if (it + 1 < 6) {
            int kb = (it + 1) * 32;
#pragma unroll
            for (int i = 0; i < 8; i++)
                rA[i] = load_f_ext(f, cat, b2v, m0 + am + i * 16, kb + ak);
            const float* bp = w0 + (size_t)(kb + bk) * 64 + bn;
#pragma unroll
            for (int i = 0; i < 4; i++) rB[i] = *(const float4*)(bp + (size_t)(i * 8) * 64);
        }
#pragma unroll
        for (int k8 = 0; k8 < 32; k8 += 8) {
            uint32_t a[2][4];
#pragma unroll
            for (int mi = 0; mi < 2; mi++) {
                int r0 = warp_m + mi * 16 + g;
                a[mi][0] = __float_as_uint(As[buf][r0][k8 + tg]);
                a[mi][1] = __float_as_uint(As[buf][r0 + 8][k8 + tg]);
                a[mi][2] = __float_as_uint(As[buf][r0][k8 + tg + 4]);
                a[mi][3] = __float_as_uint(As[buf][r0 + 8][k8 + tg + 4]);
            }
            uint32_t b[8][2];
#pragma unroll
            for (int ni = 0; ni < 8; ni++) {
                b[ni][0] = __float_as_uint(Bs[buf][k8 + tg][ni * 8 + g]);
                b[ni][1] = __float_as_uint(Bs[buf][k8 + tg + 4][ni * 8 + g]);
            }
#pragma unroll
            for (int mi = 0; mi < 2; mi++)
#pragma unroll
                for (int ni = 0; ni < 8; ni++)
                    mma_tf32(c[mi][ni], a[mi], b[ni]);
        }
        buf ^= 1;
    }
    // h1 -> As (own-warp rows)
#pragma unroll
    for (int mi = 0; mi < 2; mi++)
#pragma unroll
        for (int rr = 0; rr < 2; rr++) {
            int ml = warp_m + mi * 16 + g + rr * 8;
#pragma unroll
            for (int ni = 0; ni < 8; ni++) {
                int n = ni * 8 + tg * 2;
                float v0 = fmaxf(c[mi][ni][rr * 2 + 0] + b0[n], 0.f);
                float v1 = fmaxf(c[mi][ni][rr * 2 + 1] + b0[n + 1], 0.f);
                *(float2*)&As[n >> 5][ml][n & 31] = make_float2(tf32r(v0), tf32r(v1));
            }
        }
    __syncthreads();

    // ---- phase 2: h2 = relu(h1 @ w1 + b1) ----
#pragma unroll
    for (int t = 0; t < 2; t++)
#pragma unroll
        for (int i = 0; i < 4; i++) {
            float4 v = *(const float4*)(w1 + (size_t)(t * 32 + bk + i * 8) * 64 + bn);
            v.x = tf32r(v.x); v.y = tf32r(v.y); v.z = tf32r(v.z); v.w = tf32r(v.w);
            *(float4*)&Bs[t][bk + i * 8][bn] = v;
        }
    __syncthreads();
#pragma unroll
    for (int mi = 0; mi < 2; mi++)
#pragma unroll
        for (int ni = 0; ni < 8; ni++)
#pragma unroll
            for (int r = 0; r < 4; r++) c[mi][ni][r] = 0.0f;
#pragma unroll
    for (int kt = 0; kt < 2; kt++)
#pragma unroll
        for (int k8 = 0; k8 < 32; k8 += 8) {
            uint32_t a[2][4];
#pragma unroll
            for (int mi = 0; mi < 2; mi++) {
                int r0 = warp_m + mi * 16 + g;
                a[mi][0] = __float_as_uint(As[kt][r0][k8 + tg]);
                a[mi][1] = __float_as_uint(As[kt][r0 + 8][k8 + tg]);
                a[mi][2] = __float_as_uint(As[kt][r0][k8 + tg + 4]);
                a[mi][3] = __float_as_uint(As[kt][r0 + 8][k8 + tg + 4]);
            }
            uint32_t b[8][2];
#pragma unroll
            for (int ni = 0; ni < 8; ni++) {
                b[ni][0] = __float_as_uint(Bs[kt][k8 + tg][ni * 8 + g]);
                b[ni][1] = __float_as_uint(Bs[kt][k8 + tg + 4][ni * 8 + g]);
            }
#pragma unroll
            for (int mi = 0; mi < 2; mi++)
#pragma unroll
                for (int ni = 0; ni < 8; ni++)
                    mma_tf32(c[mi][ni], a[mi], b[ni]);
        }
#pragma unroll
    for (int mi = 0; mi < 2; mi++)
#pragma unroll
        for (int rr = 0; rr < 2; rr++) {
            int ml = warp_m + mi * 16 + g + rr * 8;
#pragma unroll
            for (int ni = 0; ni < 8; ni++) {
                int n = ni * 8 + tg * 2;
                float v0 = fmaxf(c[mi][ni][rr * 2 + 0] + b1[n], 0.f);
                float v1 = fmaxf(c[mi][ni][rr * 2 + 1] + b1[n + 1], 0.f);
                *(float2*)&As[n >> 5][ml][n & 31] = make_float2(tf32r(v0), tf32r(v1));
            }
        }
    __syncthreads();

    // ---- phase 3: x' = h2 @ w2 + b2 + x ----
#pragma unroll
    for (int t = 0; t < 2; t++)
#pragma unroll
        for (int i = 0; i < 4; i++) {
            float4 v = *(const float4*)(w2 + (size_t)(t * 32 + bk + i * 8) * 64 + bn);
            v.x = tf32r(v.x); v.y = tf32r(v.y); v.z = tf32r(v.z); v.w = tf32r(v.w);
            *(float4*)&Bs[t][bk + i * 8][bn] = v;
        }
    __syncthreads();
#pragma unroll
    for (int mi = 0; mi < 2; mi++)
#pragma unroll
        for (int ni = 0; ni < 8; ni++)
#pragma unroll
            for (int r = 0; r < 4; r++) c[mi][ni][r] = 0.0f;
#pragma unroll
    for (int kt = 0; kt < 2; kt++)
#pragma unroll
        for (int k8 = 0; k8 < 32; k8 += 8) {
            uint32_t a[2][4];
#pragma unroll
            for (int mi = 0; mi < 2; mi++) {
                int r0 = warp_m + mi * 16 + g;
                a[mi][0] = __float_as_uint(As[kt][r0][k8 + tg]);
                a[mi][1] = __float_as_uint(As[kt][r0 + 8][k8 + tg]);
                a[mi][2] = __float_as_uint(As[kt][r0][k8 + tg + 4]);
                a[mi][3] = __float_as_uint(As[kt][r0 + 8][k8 + tg + 4]);
            }
            uint32_t b[8][2];
#pragma unroll
            for (int ni = 0; ni < 8; ni++) {
                b[ni][0] = __float_as_uint(Bs[kt][k8 + tg][ni * 8 + g]);
                b[ni][1] = __float_as_uint(Bs[kt][k8 + tg + 4][ni * 8 + g]);
            }
#pragma unroll
            for (int mi = 0; mi < 2; mi++)
#pragma unroll
                for (int ni = 0; ni < 8; ni++)
                    mma_tf32(c[mi][ni], a[mi], b[ni]);
        }
#pragma unroll
    for (int mi = 0; mi < 2; mi++)
#pragma unroll
        for (int rr = 0; rr < 2; rr++) {
            int m = m0 + warp_m + mi * 16 + g + rr * 8;
#pragma unroll
            for (int ni = 0; ni < 8; ni++) {
                int n = ni * 8 + tg * 2;
                float v0 = c[mi][ni][rr * 2 + 0] + b2[n]     + f[(size_t)m * 128 + n];
                float v1 = c[mi][ni][rr * 2 + 1] + b2[n + 1] + f[(size_t)m * 128 + n + 1];
                *(float2*)&f[(size_t)m * 128 + n] = make_float2(v0, v1);
            }
        }
}

// ---------------- fused 2-layer GCN: t2 = (relu(t1@W1+b1))@W2 ----------------
__global__ __launch_bounds__(128) void gcn_kernel(
    const float* __restrict__ t1, float* __restrict__ t2,
    const float* __restrict__ W1, const float* __restrict__ bb1,
    const float* __restrict__ W2)
{
    __shared__ float As[2][128][36];
    __shared__ float Bs[2][32][72];
    float* Asf = &As[0][0][0];

    const int tid = threadIdx.x, warp = tid >> 5, lane = tid & 31;
    const int g = lane >> 2, tg = lane & 3;
    const int m0 = blockIdx.x * 128, warp_m = warp * 32;
    const int am = tid >> 3, ak = (tid & 7) * 4;
    const int bk = tid >> 4, bn = (tid & 15) * 4;

    // stage A = t1 (128x64), B = W1 (64x64)
#pragma unroll
    for (int b = 0; b < 2; b++)
#pragma unroll
        for (int i = 0; i < 8; i++) {
            float4 v = *(const float4*)(t1 + (size_t)(m0 + am + i * 16) * 64 + b * 32 + ak);
            v.x = tf32r(v.x); v.y = tf32r(v.y); v.z = tf32r(v.z); v.w = tf32r(v.w);
            *(float4*)&As[b][am + i * 16][ak] = v;
        }
#pragma unroll
    for (int i = 0; i < 8; i++) {
        int k = bk + i * 8;
        float4 v = *(const float4*)(W1 + (size_t)k * 64 + bn);
        v.x = tf32r(v.x); v.y = tf32r(v.y); v.z = tf32r(v.z); v.w = tf32r(v.w);
        *(float4*)&Bs[k >> 5][k & 31][bn] = v;
    }
    __syncthreads();

    float c[2][8][4];
#pragma unroll
    for (int mi = 0; mi < 2; mi++)
#pragma unroll
        for (int ni = 0; ni < 8; ni++)
#pragma unroll
            for (int r = 0; r < 4; r++) c[mi][ni][r] = 0.0f;
#pragma unroll
    for (int kt = 0; kt < 2; kt++)
#pragma unroll
        for (int k8 = 0; k8 < 32; k8 += 8) {
            uint32_t a[2][4];
#pragma unroll
            for (int mi = 0; mi < 2; mi++) {
                int r0 = warp_m + mi * 16 + g;
                a[mi][0] = __float_as_uint(As[kt][r0][k8 + tg]);
                a[mi][1] = __float_as_uint(As[kt][r0 + 8][k8 + tg]);
                a[mi][2] = __float_as_uint(As[kt][r0][k8 + tg + 4]);
                a[mi][3] = __float_as_uint(As[kt][r0 + 8][k8 + tg + 4]);
            }
            uint32_t b[8][2];
#pragma unroll
            for (int ni = 0; ni < 8; ni++) {
                b[ni][0] = __float_as_uint(Bs[kt][k8 + tg][ni * 8 + g]);
                b[ni][1] = __float_as_uint(Bs[kt][k8 + tg + 4][ni * 8 + g]);
            }
#pragma unroll
            for (int mi = 0; mi < 2; mi++)
#pragma unroll
                for (int ni = 0; ni < 8; ni++)
                    mma_tf32(c[mi][ni], a[mi], b[ni]);
        }
    // h = relu(c + b1) -> As (own-warp rows)
#pragma unroll
    for (int mi = 0; mi < 2; mi++)
#pragma unroll
        for (int rr = 0; rr < 2; rr++) {
            int ml = warp_m + mi * 16 + g + rr * 8;
#pragma unroll
            for (int ni = 0; ni < 8; ni++) {
                int n = ni * 8 + tg * 2;
                float v0 = fmaxf(c[mi][ni][rr * 2 + 0] + bb1[n], 0.f);
                float v1 = fmaxf(c[mi][ni][rr * 2 + 1] + bb1[n + 1], 0.f);
                int idx = (n >> 5) * 4608 + ml * 36 + (n & 31);
                Asf[idx]     = tf32r(v0);
                Asf[idx + 1] = tf32r(v1);
            }
        }
    __syncthreads();

    // stage B = W2
#pragma unroll
    for (int i = 0; i < 8; i++) {
        int k = bk + i * 8;
        float4 v = *(const float4*)(W2 + (size_t)k * 64 + bn);
        v.x = tf32r(v.x); v.y = tf32r(v.y); v.z = tf32r(v.z); v.w = tf32r(v.w);
        *(float4*)&Bs[k >> 5][k & 31][bn] = v;
    }
    __syncthreads();
#pragma unroll
    for (int mi = 0; mi < 2; mi++)
#pragma unroll
        for (int ni = 0; ni < 8; ni++)
#pragma unroll
            for (int r = 0; r < 4; r++) c[mi][ni][r] = 0.0f;
#pragma unroll
    for (int kt = 0; kt < 2; kt++)
#pragma unroll
        for (int k8 = 0; k8 < 32; k8 += 8) {
            uint32_t a[2][4];
#pragma unroll
            for (int mi = 0; mi < 2; mi++) {
                int r0 = warp_m + mi * 16 + g;
                a[mi][0] = __float_as_uint(As[kt][r0][k8 + tg]);
                a[mi][1] = __float_as_uint(As[kt][r0 + 8][k8 + tg]);
                a[mi][2] = __float_as_uint(As[kt][r0][k8 + tg + 4]);
                a[mi][3] = __float_as_uint(As[kt][r0 + 8][k8 + tg + 4]);
            }
            uint32_t b[8][2];
#pragma unroll
            for (int ni = 0; ni < 8; ni++) {
                b[ni][0] = __float_as_uint(Bs[kt][k8 + tg][ni * 8 + g]);
                b[ni][1] = __float_as_uint(Bs[kt][k8 + tg + 4][ni * 8 + g]);
            }
#pragma unroll
            for (int mi = 0; mi < 2; mi++)
#pragma unroll
                for (int ni = 0; ni < 8; ni++)
                    mma_tf32(c[mi][ni], a[mi], b[ni]);
        }
#pragma unroll
    for (int mi = 0; mi < 2; mi++)
#pragma unroll
        for (int rr = 0; rr < 2; rr++) {
            int m = m0 + warp_m + mi * 16 + g + rr * 8;
#pragma unroll
            for (int ni = 0; ni < 8; ni++) {
                int n = ni * 8 + tg * 2;
                *(float2*)&t2[(size_t)m * 64 + n] =
                    make_float2(c[mi][ni][rr * 2 + 0], c[mi][ni][rr * 2 + 1]);
            }
        }
}

// ---------------- rbf coupling + transpose (fast math, 4x vectorized) ---------
__device__ __forceinline__ float exp_neg_04(float dist) {
    float t  = dist * -0.5770780163555852f;
    float fn = floorf(t);
    float fr = t - fn;
    float p  = 1.5403530e-4f;
    p = fmaf(p, fr, 1.33335581e-3f);
    p = fmaf(p, fr, 9.61812911e-3f);
    p = fmaf(p, fr, 5.55041087e-2f);
    p = fmaf(p, fr, 2.40226507e-1f);
    p = fmaf(p, fr, 6.93147181e-1f);
    p = fmaf(p, fr, 1.0f);
    int n = (int)fn;
    n = n < -126 ? -126 : n;
    return p * __int_as_float((n + 127) << 23);
}

__device__ __forceinline__ float rbf1(float vx, float vy, float vz,
                                      float gx, float gy, float gz) {
    float dx = vx - gx, dy = vy - gy, dz = vz - gz;
    float d2 = fmaf(dx, dx, fmaf(dy, dy, dz * dz));
    d2 = fmaxf(d2, 1e-24f);
    float rs;
    asm("rsqrt.approx.f32 %0, %1;" : "=f"(rs) : "f"(d2));
    return exp_neg_04(d2 * rs);
}

// block: 32x32 threads, tile 32 v-rows x 128 g-cols; each thread does 4 g.
__global__ void rbf_kernel(const float* __restrict__ vert, const float* __restrict__ gp,
                           float* __restrict__ rbf, float* __restrict__ rbfT)
{
    __shared__ float tile[32][133];   // stride 133 (≡5 mod 32) -> conflict-free T reads
    int tx = threadIdx.x, ty = threadIdx.y;
    int g4 = blockIdx.x * 128 + tx * 4;
    int v  = blockIdx.y * 32 + ty;
    float vx = vert[v * 3], vy = vert[v * 3 + 1], vz = vert[v * 3 + 2];
    const float4* gp4 = (const float4*)(gp + (size_t)g4 * 3);
    float4 p0 = gp4[0], p1 = gp4[1], p2 = gp4[2];
    float r0 = rbf1(vx, vy, vz, p0.x, p0.y, p0.z);
    float r1 = rbf1(vx, vy, vz, p0.w, p1.x, p1.y);
    float r2 = rbf1(vx, vy, vz, p1.z, p1.w, p2.x);
    float r3 = rbf1(vx, vy, vz, p2.y, p2.z, p2.w);
    *(float4*)&rbf[(size_t)v * NG + g4] = make_float4(r0, r1, r2, r3);
    tile[ty][tx * 4 + 0] = r0;
    tile[ty][tx * 4 + 1] = r1;
    tile[ty][tx * 4 + 2] = r2;
    tile[ty][tx * 4 + 3] = r3;
    __syncthreads();
    int v2 = blockIdx.y * 32 + tx;
#pragma unroll
    for (int i = 0; i < 4; i++) {
        int g2 = blockIdx.x * 128 + i * 32 + ty;
        rbfT[(size_t)g2 * NV + v2] = tile[tx][i * 32 + ty];
    }
}

__global__ void transpose_kernel(const float* __restrict__ in, float* __restrict__ out)
{
    __shared__ float t[32][33];
    int x = blockIdx.x * 32 + threadIdx.x;
    int y = blockIdx.y * 32 + threadIdx.y;
    t[threadIdx.y][threadIdx.x] = in[(size_t)y * 128 + x];
    __syncthreads();
    int ox = blockIdx.y * 32 + threadIdx.x;
    int oy = blockIdx.x * 32 + threadIdx.y;
    out[(size_t)oy * NV + ox] = t[threadIdx.x][threadIdx.y];
}

// ---------------- elementwise (with fused zeroing) ----------------
__global__ void massx_kernel(const float* __restrict__ y, const float* __restrict__ mass,
                             float* __restrict__ f, float* __restrict__ mx,
                             float* __restrict__ yB, float* __restrict__ xs,
                             float* __restrict__ gx)
{
    int gid = blockIdx.x * 256 + threadIdx.x;   // NV*64
    int v = gid >> 6, d = gid & 63;
    float x = y[gid];
    f[v * 128 + d] = x;
    mx[gid] = mass[v] * x;
    yB[gid] = 0.0f;
    if (gid < KK * 64) xs[gid] = 0.0f;
    if (gid < NG * 64) gx[gid] = 0.0f;
}

// fused lin1 + wcat
__global__ void setup_misc_kernel(const float* __restrict__ sx, const float* __restrict__ w,
                                  const float* __restrict__ b, float* __restrict__ y,
                                  const float* __restrict__ are, const float* __restrict__ aim,
                                  float* __restrict__ W)
{
    int gid = blockIdx.x * 256 + threadIdx.x;
    if (gid < NV * 64) {
        int v = gid >> 6, d = gid & 63;
        float acc = b[d];
#pragma unroll
        for (int j = 0; j < 5; j++) acc += sx[v * 5 + j] * w[j * 64 + d];
        y[gid] = acc;
    } else {
        int q = gid - NV * 64;                 // NBLK*KK*64
        int blk = q >> 13;
        int r = q & 8191;
        int k = r >> 6, d = r & 63;
        const float* a_re = are + blk * 64 * 64;
        const float* a_im = aim + blk * 64 * 64;
        float wre, wim;
        if (k < 64) { wre = a_re[k * 64 + d];         wim = a_im[k * 64 + d]; }
        else        { wre = -a_im[(k - 64) * 64 + d]; wim = a_re[(k - 64) * 64 + d]; }
        float* Wb = W + blk * 2 * KK * 64;
        Wb[r]           = wre;
        Wb[KK * 64 + r] = wim;
    }
}

// ---------------- GCN CSR build ----------------
__global__ void deg_kernel(const int* __restrict__ dst, float* __restrict__ deg)
{
    int e = blockIdx.x * 256 + threadIdx.x;
    atomicAdd(&deg[dst[e]], 1.0f);
}
// scan + dinv + cursor-zero in one launch
__global__ __launch_bounds__(1024) void scan_kernel(const float* __restrict__ deg,
                                                    int* __restrict__ rowptr,
                                                    int* __restrict__ cursor,
                                                    float* __restrict__ dinv)
{
    __shared__ int p[1024];
    int t = threadIdx.x;
    int d0 = (int)deg[2 * t], d1 = (int)deg[2 * t + 1];
    dinv[2 * t]     = rsqrtf((float)d0 + 1.0f);
    dinv[2 * t + 1] = rsqrtf((float)d1 + 1.0f);
    p[t] = d0 + d1;
    __syncthreads();
    for (int off = 1; off < 1024; off <<= 1) {
        int v = p[t];
        if (t >= off) v += p[t - off];
        __syncthreads();
        p[t] = v;
        __syncthreads();
    }
    int excl = (t == 0) ? 0 : p[t - 1];
    rowptr[2 * t]     = excl;
    rowptr[2 * t + 1] = excl + d0;
    if (t == 1023) rowptr[2048] = p[1023];
    cursor[2 * t] = 0;
    cursor[2 * t + 1] = 0;
}
__global__ void scatter_kernel(const int* __restrict__ src, const int* __restrict__ dst,
                               const int* __restrict__ rowptr, int* __restrict__ cursor,
                               int* __restrict__ srcs)
{
    int e = blockIdx.x * 256 + threadIdx.x;
    int s = src[e], t = dst[e];
    int pos = rowptr[t] + atomicAdd(&cursor[t], 1);
    srcs[pos] = s;
}
__global__ void csr_agg_kernel(const float* __restrict__ hw, const float* __restrict__ dinv,
                               const int* __restrict__ rowptr, const int* __restrict__ srcs,
                               float* __restrict__ agg)
{
    int gid = blockIdx.x * 256 + threadIdx.x;   // NG*64
    int i = gid >> 6, d = gid & 63;
    float di = dinv[i];
    float acc = hw[i * 64 + d] * di;
    int r1 = rowptr[i + 1];
    for (int r = rowptr[i]; r < r1; r++) {
        int s = srcs[r];
        acc += hw[s * 64 + d] * dinv[s];
    }
    agg[gid] = acc * di;
}

// ---------------- tail ----------------
__global__ void out_kernel(const float* __restrict__ y, const float* __restrict__ w,
                           const float* __restrict__ b, float* __restrict__ out)
{
    int gid = blockIdx.x * 256 + threadIdx.x;   // NV*8
    int v = gid >> 3, c = gid & 7;
    float acc = b[c];
#pragma unroll 8
    for (int d = 0; d < 64; d++) acc += y[v * 64 + d] * w[d * 8 + c];
    out[gid] = acc;
}

// ---------------- host ----------------
static inline Sl sl1(const float* A, float* C, int ldc) {
    Sl s; for (int i = 0; i < 4; i++) { s.A[i] = A; s.C[i] = C; s.ldc[i] = ldc; }
    return s;
}

extern "C" void kernel_launch(void* const* d_in, const int* in_sizes, int n_in,
                              void* d_out, int out_size)
{
    static bool inited = false;
    static float *p_rbf, *p_rbfT, *p_f, *p_y, *p_cat, *p_b2, *p_mx,
                 *p_xs, *p_W, *p_GE, *p_eT, *p_gx, *p_hw, *p_agg, *p_agg2,
                 *p_deg, *p_dinv;
    static int *p_rowptr, *p_cursor, *p_srcs;
    static cudaStream_t s2;
    static cudaEvent_t evF2, evJ2;
    if (!inited) {
        cudaGetSymbolAddress((void**)&p_rbf,  g_rbf);
        cudaGetSymbolAddress((void**)&p_rbfT, g_rbfT);
        cudaGetSymbolAddress((void**)&p_f,    g_f);
        cudaGetSymbolAddress((void**)&p_y,    g_y);
        cudaGetSymbolAddress((void**)&p_cat,  g_cat);
        cudaGetSymbolAddress((void**)&p_b2,   g_b2);
        cudaGetSymbolAddress((void**)&p_mx,   g_mx);
        cudaGetSymbolAddress((void**)&p_xs,   g_xs);
        cudaGetSymbolAddress((void**)&p_W,    g_W);
        cudaGetSymbolAddress((void**)&p_GE,   g_GE);
        cudaGetSymbolAddress((void**)&p_eT,   g_eT);
        cudaGetSymbolAddress((void**)&p_gx,   g_gx);
        cudaGetSymbolAddress((void**)&p_hw,   g_hw);
        cudaGetSymbolAddress((void**)&p_agg,  g_agg);
        cudaGetSymbolAddress((void**)&p_agg2, g_agg2);
        cudaGetSymbolAddress((void**)&p_deg,  g_deg);
        cudaGetSymbolAddress((void**)&p_dinv, g_dinv);
        cudaGetSymbolAddress((void**)&p_rowptr, g_rowptr);
        cudaGetSymbolAddress((void**)&p_cursor, g_cursor);
        cudaGetSymbolAddress((void**)&p_srcs,   g_srcs);
        cudaStreamCreateWithFlags(&s2, cudaStreamNonBlocking);
        cudaEventCreateWithFlags(&evF2, cudaEventDisableTiming);
        cudaEventCreateWithFlags(&evJ2, cudaEventDisableTiming);
        inited = true;
    }

    const float* surf_x    = (const float*)d_in[0];
    const float* mass      = (const float*)d_in[1];
    const float* evals     = (const float*)d_in[2];
    const float* evecs     = (const float*)d_in[3];
    const float* gradX     = (const float*)d_in[4];
    const float* gradY     = (const float*)d_in[5];
    const float* vertices  = (const float*)d_in[6];
    const float* graph_pos = (const float*)d_in[8];
    const float* lin1_w    = (const float*)d_in[9];
    const float* lin1_b    = (const float*)d_in[10];
    const float* last_w    = (const float*)d_in[13];
    const float* last_b    = (const float*)d_in[14];
    const float* diff_time = (const float*)d_in[15];
    const float* A_re      = (const float*)d_in[16];
    const float* A_im      = (const float*)d_in[17];
    const float* mlp_w0    = (const float*)d_in[18];
    const float* mlp_b0    = (const float*)d_in[19];
    const float* mlp_w1    = (const float*)d_in[20];
    const float* mlp_b1    = (const float*)d_in[21];
    const float* mlp_w2    = (const float*)d_in[22];
    const float* mlp_b2    = (const float*)d_in[23];
    const float* gcn_w1    = (const float*)d_in[24];
    const float* gcn_b1    = (const float*)d_in[25];
    const float* gcn_w2    = (const float*)d_in[26];
    const float* gcn_b2    = (const float*)d_in[27];
    const int*   eidx      = (const int*)d_in[28];
    const int*   e_src     = eidx;
    const int*   e_dst     = eidx + EE;
    float* out = (float*)d_out;

    // ---- fork s2: CSR build only (tiny kernels, zero main-chain deps) ----
    cudaEventRecord(evF2, 0);
    cudaStreamWaitEvent(s2, evF2, 0);
    cudaMemsetAsync(p_deg, 0, NG * sizeof(float), s2);
    deg_kernel<<<EE / 256, 256, 0, s2>>>(e_dst, p_deg);
    scan_kernel<<<1, 1024, 0, s2>>>(p_deg, p_rowptr, p_cursor, p_dinv);
    scatter_kernel<<<EE / 256, 256, 0, s2>>>(e_src, e_dst, p_rowptr, p_cursor, p_srcs);
    cudaEventRecord(evJ2, s2);

    // ---- main-stream setup ----
    rbf_kernel<<<dim3(NG / 128, NV / 32), dim3(32, 32)>>>(vertices, graph_pos, p_rbf, p_rbfT);
    transpose_kernel<<<dim3(KK / 32, NV / 32), dim3(32, 32)>>>(evecs, p_eT);
    setup_misc_kernel<<<(NV * 64 + NBLK * KK * 64) / 256, 256>>>(
        surf_x, lin1_w, lin1_b, p_y, A_re, A_im, p_W);

    // GE = [gradX@evecs(lo) ; gradX@evecs(hi) ; gradY@evecs(lo) ; gradY@evecs(hi)]
    {
        Sl s;
        s.A[0] = gradX; s.A[1] = gradX; s.A[2] = gradY; s.A[3] = gradY;
        s.C[0] = p_GE;            s.C[1] = p_GE + 64;
        s.C[2] = p_GE + NV * 128; s.C[3] = p_GE + NV * 128 + 64;
        s.ldc[0] = s.ldc[1] = s.ldc[2] = s.ldc[3] = 128;
        gemm64<<<dim3(NV / 128, 1, 4), 128>>>(
            s, NV, evecs, evecs + 64, 128, NV, NV,
            nullptr, nullptr, 0, 0, nullptr, nullptr, nullptr, nullptr);
    }

    for (int blk = 0; blk < NBLK; blk++) {
        const float* t   = diff_time + blk * 64;
        const float* w0  = mlp_w0 + blk * 192 * 64;
        const float* b0  = mlp_b0 + blk * 64;
        const float* w1  = mlp_w1 + blk * 64 * 64;
        const float* b1  = mlp_b1 + blk * 64;
        const float* w2  = mlp_w2 + blk * 64 * 64;
        const float* b2m = mlp_b2 + blk * 64;
        const float* gw1 = gcn_w1 + blk * 64 * 64;
        const float* gb1 = gcn_b1 + blk * 64;
        const float* gw2 = gcn_w2 + blk * 64 * 64;
        const float* gb2 = gcn_b2 + blk * 64;
        const float* Wb  = p_W + blk * 2 * KK * 64;
        float* yA = p_y + (blk & 1) * NV * 64;
        float* yB = p_y + (1 - (blk & 1)) * NV * 64;

        // x -> f[:,0:64], mx = mass*x ; zero yB + xs + gx
        massx_kernel<<<NV * 64 / 256, 256>>>(yA, mass, p_f, p_mx, yB, p_xs, p_gx);

        // xs = evecsT @ mx  (split-K 16)
        gemm64<<<dim3(1, 16, 1), 128>>>(
            sl1(p_eT, p_xs, 64), NV, p_mx, p_mx, 64, NV, NV / 16,
            nullptr, nullptr, 0, 0, nullptr, nullptr, nullptr, nullptr);

        // [x_diff ; gX ; gY] = [evecs ; GE_X ; GE_Y] @ (coef * xs)  (exp fused)
        {
            Sl s;
            s.A[0] = evecs;          s.C[0] = p_f + 64;   s.ldc[0] = 128;
            s.A[1] = p_GE;           s.C[1] = p_cat;      s.ldc[1] = 128;
            s.A[2] = p_GE + NV*128;  s.C[2] = p_cat + 64; s.ldc[2] = 128;
            s.A[3] = evecs;          s.C[3] = p_f + 64;   s.ldc[3] = 128;
            gemm64<<<dim3(NV / 128, 1, 3), 128>>>(
                s, 128, p_xs, p_xs, 64, KK, KK,
                nullptr, nullptr, 0, 0, nullptr, nullptr, evals, t);
        }

        // b_re|b_im = cat @ [Wre|Wim]
        {
            Sl s;
            s.A[0] = p_cat; s.C[0] = p_b2;           s.ldc[0] = 64;
            s.A[1] = p_cat; s.C[1] = p_b2 + NV * 64; s.ldc[1] = 64;
            s.A[2] = p_cat; s.C[2] = p_b2;           s.ldc[2] = 64;
            s.A[3] = p_cat; s.C[3] = p_b2;           s.ldc[3] = 64;
            gemm64<<<dim3(NV / 128, 1, 2), 128>>>(
                s, 128, Wb, Wb + KK * 64, 64, KK, KK,
                nullptr, nullptr, 0, 0, nullptr, nullptr, nullptr, nullptr);
        }

        // fused MLP (gfeat computed in-loader) + residual -> f[:,0:64]
        mlp_kernel<<<NV / 128, 128>>>(p_f, p_cat, p_b2, w0, b0, w1, b1, w2, b2m);

        // gx = rbf^T @ diff_x (split-K 8)
        gemm64<<<dim3(NG / 128, 8, 1), 128>>>(
            sl1(p_rbfT, p_gx, 64), NV, p_f, p_f, 128, NV, NV / 8,
            nullptr, nullptr, 0, 0, nullptr, nullptr, nullptr, nullptr);

        if (blk == 0) cudaStreamWaitEvent(0, evJ2, 0);   // CSR build ready

        // GCN: t1 = A_hat*gx ; hw = relu(t1@W1+b1)@W2 ; agg2 = A_hat*hw
        csr_agg_kernel<<<NG * 64 / 256, 256>>>(p_gx, p_dinv, p_rowptr, p_srcs, p_agg);
        gcn_kernel<<<NG / 128, 128>>>(p_agg, p_hw, gw1, gb1, gw2);
        csr_agg_kernel<<<NG * 64 / 256, 256>>>(p_hw, p_dinv, p_rowptr, p_srcs, p_agg2);

        // diff_x = rbf @ (agg2 + gb2)  (B-loader bias fused; split-K 4) -> yB
        gemm64<<<dim3(NV / 128, 4, 1), 128>>>(
            sl1(p_rbf, yB, 64), NG, p_agg2, p_agg2, 64, NG, NG / 4,
            nullptr, nullptr, 0, 0, nullptr, gb2, nullptr, nullptr);
    }

    // final: out = y[0] @ last_w + last_b
    out_kernel<<<(NV * 8) / 256, 256>>>(p_y, last_w, last_b, out);
}